// round 8
// baseline (speedup 1.0000x reference)
#include <cuda_runtime.h>
#include <cuda_bf16.h>
#include <math.h>
#include <cstdint>

#define D      1024
#define D3     3072
#define D4     4096
#define TSEQ   2048
#define NBATCH 2
#define NTOK   4096
#define NH     16
#define HD     64
#define EPS    1.1920929e-07f

// ---------------------------------------------------------------------------
// Scratch (device globals; no allocations allowed)
// ---------------------------------------------------------------------------
__device__ __nv_bfloat16 g_ah[NTOK * D];
__device__ __nv_bfloat16 g_al[NTOK * D];
__device__ __nv_bfloat16 g_bh[NTOK * D4];
__device__ __nv_bfloat16 g_bl[NTOK * D4];
__device__ __nv_bfloat16 g_wth[D * D4];
__device__ __nv_bfloat16 g_wtl[D * D4];
__device__ __nv_bfloat16 g_qh[NTOK * D];
__device__ __nv_bfloat16 g_ql[NTOK * D];
__device__ __nv_bfloat16 g_kh[NTOK * D];
__device__ __nv_bfloat16 g_kl[NTOK * D];
__device__ __nv_bfloat16 g_vh[NTOK * D];
__device__ __nv_bfloat16 g_vl[NTOK * D];

// ---------------------------------------------------------------------------
// Helpers
// ---------------------------------------------------------------------------
__device__ __forceinline__ uint32_t smem_to_u32(const void* p) {
    uint32_t a;
    asm("{ .reg .u64 t; cvta.to.shared.u64 t, %1; cvt.u32.u64 %0, t; }" : "=r"(a) : "l"(p));
    return a;
}

// 128B-row swizzle (16B chunk ^= row&7)
#define SWZ(off) ((uint32_t)(off) ^ ((((uint32_t)(off) >> 7) & 7) << 4))
// 64B-row swizzle (16B chunk ^= (row>>1)&3) — conflict-free for 64B rows
#define SWZ32(off) ((uint32_t)(off) ^ ((((uint32_t)(off) >> 7) & 3) << 4))

__device__ __forceinline__ void ldsm_x4(uint32_t* r, uint32_t addr) {
    asm volatile("ldmatrix.sync.aligned.m8n8.x4.shared.b16 {%0,%1,%2,%3}, [%4];"
                 : "=r"(r[0]), "=r"(r[1]), "=r"(r[2]), "=r"(r[3]) : "r"(addr));
}
__device__ __forceinline__ void ldsm_x2(uint32_t* r, uint32_t addr) {
    asm volatile("ldmatrix.sync.aligned.m8n8.x2.shared.b16 {%0,%1}, [%2];"
                 : "=r"(r[0]), "=r"(r[1]) : "r"(addr));
}
__device__ __forceinline__ void ldsm_x2_trans(uint32_t* r, uint32_t addr) {
    asm volatile("ldmatrix.sync.aligned.m8n8.x2.trans.shared.b16 {%0,%1}, [%2];"
                 : "=r"(r[0]), "=r"(r[1]) : "r"(addr));
}
__device__ __forceinline__ void mma_bf16_g(float* d, const uint32_t* a, const uint32_t* b) {
    asm volatile(
        "mma.sync.aligned.m16n8k16.row.col.f32.bf16.bf16.f32 "
        "{%0,%1,%2,%3}, {%4,%5,%6,%7}, {%8,%9}, {%0,%1,%2,%3};"
        : "+f"(d[0]), "+f"(d[1]), "+f"(d[2]), "+f"(d[3])
        : "r"(a[0]), "r"(a[1]), "r"(a[2]), "r"(a[3]), "r"(b[0]), "r"(b[1]));
}

__device__ __forceinline__ void split2(float v, __nv_bfloat16& h, __nv_bfloat16& l) {
    h = __float2bfloat16(v);
    l = __float2bfloat16(v - __bfloat162float(h));
}
__device__ __forceinline__ uint32_t pack_bf16x2(float a, float b) {
    uint32_t r;
    asm("cvt.rn.bf16x2.f32 %0, %1, %2;" : "=r"(r) : "f"(b), "f"(a));
    return r;
}
__device__ __forceinline__ uint32_t pack_hi16(float a, float b) {
    uint32_t r;
    asm("prmt.b32 %0, %1, %2, 0x7632;" : "=r"(r) : "r"(__float_as_uint(a)), "r"(__float_as_uint(b)));
    return r;
}
__device__ __forceinline__ float trunc_bf16f(float v) {
    return __uint_as_float(__float_as_uint(v) & 0xFFFF0000u);
}

// ---------------------------------------------------------------------------
// RMSNorm -> bf16 hi/lo split
// ---------------------------------------------------------------------------
__global__ void rmsnorm_split_kernel(const float* __restrict__ x,
                                     const float* __restrict__ g,
                                     __nv_bfloat16* __restrict__ oh,
                                     __nv_bfloat16* __restrict__ ol) {
    int row = blockIdx.x;
    const float4* xr = reinterpret_cast<const float4*>(x + (size_t)row * D);
    float4 v = xr[threadIdx.x];
    float s = v.x * v.x + v.y * v.y + v.z * v.z + v.w * v.w;
    #pragma unroll
    for (int o = 16; o > 0; o >>= 1) s += __shfl_xor_sync(0xffffffffu, s, o);
    __shared__ float ws[8];
    if ((threadIdx.x & 31) == 0) ws[threadIdx.x >> 5] = s;
    __syncthreads();
    float tot = ws[0] + ws[1] + ws[2] + ws[3] + ws[4] + ws[5] + ws[6] + ws[7];
    float inv = rsqrtf(tot * (1.0f / (float)D) + EPS);
    float4 gv = reinterpret_cast<const float4*>(g)[threadIdx.x];
    float vals[4] = {v.x * inv * gv.x, v.y * inv * gv.y, v.z * inv * gv.z, v.w * inv * gv.w};
    __nv_bfloat16 h[4], l[4];
    #pragma unroll
    for (int j = 0; j < 4; j++) split2(vals[j], h[j], l[j]);
    size_t off = (size_t)row * D + threadIdx.x * 4;
    *reinterpret_cast<__nv_bfloat162*>(&oh[off])     = __halves2bfloat162(h[0], h[1]);
    *reinterpret_cast<__nv_bfloat162*>(&oh[off + 2]) = __halves2bfloat162(h[2], h[3]);
    *reinterpret_cast<__nv_bfloat162*>(&ol[off])     = __halves2bfloat162(l[0], l[1]);
    *reinterpret_cast<__nv_bfloat162*>(&ol[off + 2]) = __halves2bfloat162(l[2], l[3]);
}

// ---------------------------------------------------------------------------
// Weight transpose + bf16 split: W[K,N] -> Wt_hi/Wt_lo [N,K]
// ---------------------------------------------------------------------------
__global__ void transpose_split_kernel(const float* __restrict__ W, int K, int N,
                                       __nv_bfloat16* __restrict__ Th,
                                       __nv_bfloat16* __restrict__ Tl) {
    __shared__ float t[32][33];
    int k0 = blockIdx.y * 32, n0 = blockIdx.x * 32;
    int x = threadIdx.x, y = threadIdx.y;   // 32 x 8
    #pragma unroll
    for (int i = y; i < 32; i += 8)
        t[i][x] = W[(size_t)(k0 + i) * N + n0 + x];
    __syncthreads();
    #pragma unroll
    for (int b = y; b < 32; b += 8) {
        float v = t[x][b];
        __nv_bfloat16 h, l;
        split2(v, h, l);
        size_t o = (size_t)(n0 + b) * K + k0 + x;
        Th[o] = h;
        Tl[o] = l;
    }
}

// ---------------------------------------------------------------------------
// mma.sync split-bf16 GEMM: tile 128x128, BK=32, 3-stage, 2 CTAs/SM.
// Warp tile 64x32 (8 warps 2x4).
// ---------------------------------------------------------------------------
#define EPI_BIAS 0
#define EPI_GELU 1
#define EPI_RES  2
#define EPI_QKV  3

// stage: Ah 8K | Al 8K | Bh 8K | Bl 8K = 32K
#define STAGE_BYTES 32768
#define TCG_SMEM (3 * STAGE_BYTES)

template <int EPI>
__global__ __launch_bounds__(256, 2)
void tcgemm_kernel(const __nv_bfloat16* __restrict__ Ah, const __nv_bfloat16* __restrict__ Al,
                   const __nv_bfloat16* __restrict__ Bh, const __nv_bfloat16* __restrict__ Bl,
                   const float* __restrict__ bias, const float* __restrict__ R,
                   float* __restrict__ C,
                   __nv_bfloat16* __restrict__ Oh, __nv_bfloat16* __restrict__ Ol,
                   __nv_bfloat16* __restrict__ Qh, __nv_bfloat16* __restrict__ Ql,
                   __nv_bfloat16* __restrict__ Kh, __nv_bfloat16* __restrict__ Kl,
                   __nv_bfloat16* __restrict__ Vh, __nv_bfloat16* __restrict__ Vl,
                   int M, int N, int K) {
    extern __shared__ __align__(1024) char smem[];
    uint32_t sbase = smem_to_u32(smem);
    const int tid = threadIdx.x;
    const int wid = tid >> 5, lid = tid & 31;
    const int wm = wid >> 2, wn = wid & 3;        // warp tile 64(m) x 32(n)
    const int bm = blockIdx.y * 128, bn = blockIdx.x * 128;

    const __nv_bfloat16* srcs[4] = {Ah, Al, Bh, Bl};

    // one K-chunk (32 cols, 64B/row) of all 4 tiles into stage s
    auto load_chunk = [&](int c, int s) {
        uint32_t tb = sbase + s * STAGE_BYTES;
        #pragma unroll
        for (int t4 = 0; t4 < 4; t4++) {
            const __nv_bfloat16* src = srcs[t4];
            int rbase = (t4 < 2) ? bm : bn;
            uint32_t dst0 = tb + t4 * 8192;
            #pragma unroll
            for (int i = 0; i < 2; i++) {
                int u = tid + i * 256;          // 0..511
                int r = u >> 2, j = u & 3;
                uint32_t d = dst0 + SWZ32(r * 64 + j * 16);
                const void* g = src + (size_t)(rbase + r) * K + c * 32 + j * 8;
                asm volatile("cp.async.cg.shared.global [%0], [%1], 16;"
                             :: "r"(d), "l"(g) : "memory");
            }
        }
        asm volatile("cp.async.commit_group;" ::: "memory");
    };

    float acc[4][4][4];
    #pragma unroll
    for (int im = 0; im < 4; im++)
        #pragma unroll
        for (int in = 0; in < 4; in++)
            #pragma unroll
            for (int q = 0; q < 4; q++) acc[im][in][q] = 0.0f;

    const int nchunks = K >> 5;
    load_chunk(0, 0);
    load_chunk(1, 1);

    const int arow = wm * 64 + (lid & 15);
    const int acol = (lid >> 4) * 16;
    const int brow = wn * 32 + (lid & 7);
    const int bcol = ((lid >> 3) & 1) * 16;

    for (int c = 0; c < nchunks; c++) {
        int s = c % 3;
        if (c + 2 < nchunks) {
            load_chunk(c + 2, (c + 2) % 3);
            asm volatile("cp.async.wait_group 2;" ::: "memory");
        } else if (c + 1 < nchunks) {
            asm volatile("cp.async.wait_group 1;" ::: "memory");
        } else {
            asm volatile("cp.async.wait_group 0;" ::: "memory");
        }
        __syncthreads();

        uint32_t tb = sbase + s * STAGE_BYTES;
        uint32_t tAh = tb, tAl = tb + 8192, tBh = tb + 16384, tBl = tb + 24576;

        #pragma unroll
        for (int ks = 0; ks < 2; ks++) {
            uint32_t ah[4][4], al[4][4], bh[4][2], bl[4][2];
            #pragma unroll
            for (int im = 0; im < 4; im++) {
                uint32_t off = SWZ32((arow + im * 16) * 64 + ks * 32 + acol);
                ldsm_x4(ah[im], tAh + off);
            }
            #pragma unroll
            for (int in = 0; in < 4; in++) {
                uint32_t off = SWZ32((brow + in * 8) * 64 + ks * 32 + bcol);
                ldsm_x2(bh[in], tBh + off);
            }
            #pragma unroll
            for (int im = 0; im < 4; im++)
                #pragma unroll
                for (int in = 0; in < 4; in++)
                    mma_bf16_g(acc[im][in], ah[im], bh[in]);
            #pragma unroll
            for (int in = 0; in < 4; in++) {
                uint32_t off = SWZ32((brow + in * 8) * 64 + ks * 32 + bcol);
                ldsm_x2(bl[in], tBl + off);
            }
            #pragma unroll
            for (int im = 0; im < 4; im++)
                #pragma unroll
                for (int in = 0; in < 4; in++)
                    mma_bf16_g(acc[im][in], ah[im], bl[in]);
            #pragma unroll
            for (int im = 0; im < 4; im++) {
                uint32_t off = SWZ32((arow + im * 16) * 64 + ks * 32 + acol);
                ldsm_x4(al[im], tAl + off);
            }
            #pragma unroll
            for (int im = 0; im < 4; im++)
                #pragma unroll
                for (int in = 0; in < 4; in++)
                    mma_bf16_g(acc[im][in], al[im], bh[in]);
        }
        __syncthreads();
    }

    #pragma unroll
    for (int im = 0; im < 4; im++) {
        #pragma unroll
        for (int in = 0; in < 4; in++) {
            int m0 = bm + wm * 64 + im * 16 + (lid >> 2);
            int n0 = bn + wn * 32 + in * 8 + (lid & 3) * 2;
            float b0 = bias[n0], b1 = bias[n0 + 1];
            #pragma unroll
            for (int half = 0; half < 2; half++) {
                int m = m0 + half * 8;
                float v0 = acc[im][in][half * 2]     + b0;
                float v1 = acc[im][in][half * 2 + 1] + b1;
                if (EPI == EPI_QKV) {
                    int part = n0 >> 10;
                    int head = (n0 >> 6) & 15;
                    int d = n0 & 63;
                    int bb = m >> 11, t = m & 2047;
                    size_t dst = ((size_t)(bb * NH + head) * TSEQ + t) * HD + d;
                    __nv_bfloat16 h0, l0, h1, l1;
                    split2(v0, h0, l0);
                    split2(v1, h1, l1);
                    __nv_bfloat16* dh = (part == 0) ? Qh : (part == 1) ? Kh : Vh;
                    __nv_bfloat16* dl = (part == 0) ? Ql : (part == 1) ? Kl : Vl;
                    *reinterpret_cast<__nv_bfloat162*>(&dh[dst]) = __halves2bfloat162(h0, h1);
                    *reinterpret_cast<__nv_bfloat162*>(&dl[dst]) = __halves2bfloat162(l0, l1);
                } else if (EPI == EPI_GELU) {
                    size_t off = (size_t)m * N + n0;
                    float g0 = 0.5f * v0 * (1.0f + erff(v0 * 0.70710678118654752f));
                    float g1 = 0.5f * v1 * (1.0f + erff(v1 * 0.70710678118654752f));
                    __nv_bfloat16 h0, l0, h1, l1;
                    split2(g0, h0, l0);
                    split2(g1, h1, l1);
                    *reinterpret_cast<__nv_bfloat162*>(&Oh[off]) = __halves2bfloat162(h0, h1);
                    *reinterpret_cast<__nv_bfloat162*>(&Ol[off]) = __halves2bfloat162(l0, l1);
                } else {
                    size_t off = (size_t)m * N + n0;
                    if (EPI == EPI_RES) {
                        float2 rr = *reinterpret_cast<const float2*>(&R[off]);
                        v0 += rr.x; v1 += rr.y;
                    }
                    float2 o2 = make_float2(v0, v1);
                    *reinterpret_cast<float2*>(&C[off]) = o2;
                }
            }
        }
    }
}

// ---------------------------------------------------------------------------
// Tensor-core flash attention (unchanged from R6/R7 baseline, heavy-first).
// ---------------------------------------------------------------------------
#define ATTN_SMEM 98304

__global__ __launch_bounds__(256, 1)
void attn_mma_kernel(const __nv_bfloat16* __restrict__ Qh, const __nv_bfloat16* __restrict__ Ql,
                     const __nv_bfloat16* __restrict__ Kh, const __nv_bfloat16* __restrict__ Kl,
                     const __nv_bfloat16* __restrict__ Vh, const __nv_bfloat16* __restrict__ Vl,
                     __nv_bfloat16* __restrict__ oh, __nv_bfloat16* __restrict__ ol) {
    extern __shared__ __align__(1024) char smem_raw[];
    uint32_t sb = smem_to_u32(smem_raw);
    const uint32_t sQh = 0, sQl = 16384;

    const int tid = threadIdx.x;
    const int wid = tid >> 5, lid = tid & 31;
    const int qb = gridDim.x - 1 - blockIdx.x;
    const int h = blockIdx.y, b = blockIdx.z;
    const int qbase = qb * 128;
    const size_t hdbase = (size_t)(b * NH + h) * TSEQ * HD;

    const __nv_bfloat16* kvsrc[4] = {Kh + hdbase, Kl + hdbase, Vh + hdbase, Vl + hdbase};

    auto load_kv = [&](int c, int s) {
        uint32_t slot = sb + 32768 + s * 32768;
        int rowbase = c * 64;
        #pragma unroll
        for (int i = 0; i < 8; i++) {
            int u = tid + i * 256;
            int t4 = u >> 9;
            int c2 = u & 511;
            int r = c2 >> 3, j = c2 & 7;
            uint32_t d = slot + t4 * 8192 + SWZ(r * 128 + j * 16);
            const void* g = kvsrc[t4] + (size_t)(rowbase + r) * HD + j * 8;
            asm volatile("cp.async.cg.shared.global [%0], [%1], 16;"
                         :: "r"(d), "l"(g) : "memory");
        }
    };

    {
        const __nv_bfloat16* qhp = Qh + hdbase + (size_t)qbase * HD;
        const __nv_bfloat16* qlp = Ql + hdbase + (size_t)qbase * HD;
        #pragma unroll
        for (int i = 0; i < 4; i++) {
            int u = tid + i * 256;
            int r = u >> 3, j = u & 7;
            uint32_t o = SWZ(r * 128 + j * 16);
            asm volatile("cp.async.cg.shared.global [%0], [%1], 16;"
                         :: "r"(sb + sQh + o), "l"((const void*)(qhp + (size_t)r * HD + j * 8)) : "memory");
            asm volatile("cp.async.cg.shared.global [%0], [%1], 16;"
                         :: "r"(sb + sQl + o), "l"((const void*)(qlp + (size_t)r * HD + j * 8)) : "memory");
        }
        load_kv(0, 0);
        asm volatile("cp.async.commit_group;" ::: "memory");
    }

    float mrow[2] = {-1e30f, -1e30f};
    float lrow[2] = {0.0f, 0.0f};
    float oacc[8][4];
    #pragma unroll
    for (int t = 0; t < 8; t++)
        #pragma unroll
        for (int c = 0; c < 4; c++) oacc[t][c] = 0.0f;

    const int nchunks = 2 * qb + 2;
    const int wrow_hi = qbase + 16 * wid + 15;

    for (int kc = 0; kc < nchunks; kc++) {
        const int kbase = kc * 64;
        const int s = kc & 1;
        if (kc + 1 < nchunks) {
            load_kv(kc + 1, s ^ 1);
            asm volatile("cp.async.commit_group;" ::: "memory");
            asm volatile("cp.async.wait_group 1;" ::: "memory");
        } else {
            asm volatile("cp.async.wait_group 0;" ::: "memory");
        }
        __syncthreads();

        if (wrow_hi >= kbase) {
            const uint32_t slot = sb + 32768 + s * 32768;
            const uint32_t tKh = slot, tKl = slot + 8192, tVh = slot + 16384, tVl = slot + 24576;

            uint32_t qh[4][4], ql[4][4];
            {
                int qr = 16 * wid + (lid & 15);
                int qc = (lid >> 4) * 16;
                #pragma unroll
                for (int ks = 0; ks < 4; ks++) {
                    uint32_t off = SWZ(qr * 128 + ks * 32 + qc);
                    ldsm_x4(qh[ks], sb + sQh + off);
                    ldsm_x4(ql[ks], sb + sQl + off);
                }
            }
            float sacc[8][4];
            #pragma unroll
            for (int t = 0; t < 8; t++)
                #pragma unroll
                for (int c = 0; c < 4; c++) sacc[t][c] = 0.0f;

            {
                int kr = lid & 7;
                int kcb = ((lid >> 3) & 1) * 16;
                #pragma unroll
                for (int t = 0; t < 8; t++) {
                    #pragma unroll
                    for (int ks = 0; ks < 4; ks++) {
                        uint32_t off = SWZ((t * 8 + kr) * 128 + ks * 32 + kcb);
                        uint32_t bh2[2], bl2[2];
                        ldsm_x2(bh2, tKh + off);
                        ldsm_x2(bl2, tKl + off);
                        mma_bf16_g(sacc[t], qh[ks], bh2);
                        mma_bf16_g(sacc[t], ql[ks], bh2);
                        mma_bf16_g(sacc[t], qh[ks], bl2);
                    }
                }
            }

            if (kc >= 2 * qb) {
                int row0 = qbase + 16 * wid + (lid >> 2);
                #pragma unroll
                for (int t = 0; t < 8; t++) {
                    int col = kbase + t * 8 + 2 * (lid & 3);
                    if (col > row0)     sacc[t][0] = -1e30f;
                    if (col + 1 > row0) sacc[t][1] = -1e30f;
                    if (col > row0 + 8)     sacc[t][2] = -1e30f;
                    if (col + 1 > row0 + 8) sacc[t][3] = -1e30f;
                }
            }

            #pragma unroll
            for (int rr = 0; rr < 2; rr++) {
                float mx = -1e30f;
                #pragma unroll
                for (int t = 0; t < 8; t++)
                    mx = fmaxf(mx, fmaxf(sacc[t][2 * rr], sacc[t][2 * rr + 1]));
                mx = fmaxf(mx, __shfl_xor_sync(0xffffffffu, mx, 1));
                mx = fmaxf(mx, __shfl_xor_sync(0xffffffffu, mx, 2));
                float mn = fmaxf(mrow[rr], mx);
                float sc = __expf(mrow[rr] - mn);
                mrow[rr] = mn;
                float rs = 0.0f;
                #pragma unroll
                for (int t = 0; t < 8; t++) {
                    float p0 = __expf(sacc[t][2 * rr] - mn);
                    float p1 = __expf(sacc[t][2 * rr + 1] - mn);
                    sacc[t][2 * rr] = p0; sacc[t][2 * rr + 1] = p1;
                    rs += p0 + p1;
                }
                lrow[rr] = lrow[rr] * sc + rs;
                #pragma unroll
                for (int t = 0; t < 8; t++) {
                    oacc[t][2 * rr]     *= sc;
                    oacc[t][2 * rr + 1] *= sc;
                }
            }

            {
                int vr = (lid & 7) + ((lid >> 3) & 1) * 8;
                #pragma unroll
                for (int j = 0; j < 4; j++) {
                    uint32_t ph[4], pl[4];
                    #pragma unroll
                    for (int half = 0; half < 2; half++) {
                        float a0 = sacc[2 * j + half][0], a1 = sacc[2 * j + half][1];
                        float a2 = sacc[2 * j + half][2], a3 = sacc[2 * j + half][3];
                        ph[0 + 2 * half] = pack_hi16(a0, a1);
                        ph[1 + 2 * half] = pack_hi16(a2, a3);
                        pl[0 + 2 * half] = pack_bf16x2(a0 - trunc_bf16f(a0), a1 - trunc_bf16f(a1));
                        pl[1 + 2 * half] = pack_bf16x2(a2 - trunc_bf16f(a2), a3 - trunc_bf16f(a3));
                    }
                    #pragma unroll
                    for (int t = 0; t < 8; t++) {
                        uint32_t voff = SWZ((j * 16 + vr) * 128 + t * 16);
                        uint32_t vh2[2], vl2[2];
                        ldsm_x2_trans(vh2, tVh + voff);
                        ldsm_x2_trans(vl2, tVl + voff);
                        mma_bf16_g(oacc[t], ph, vh2);
                        mma_bf16_g(oacc[t], pl, vh2);
                        mma_bf16_g(oacc[t], ph, vl2);
                    }
                }
            }
        }
        __syncthreads();
    }

    lrow[0] += __shfl_xor_sync(0xffffffffu, lrow[0], 1);
    lrow[0] += __shfl_xor_sync(0xffffffffu, lrow[0], 2);
    lrow[1] += __shfl_xor_sync(0xffffffffu, lrow[1], 1);
    lrow[1] += __shfl_xor_sync(0xffffffffu, lrow[1], 2);
    float inv0 = 0.03125f / lrow[0];
    float inv1 = 0.03125f / lrow[1];

    const size_t tok0 = (size_t)b * TSEQ;
    #pragma unroll
    for (int rr = 0; rr < 2; rr++) {
        float inv = rr ? inv1 : inv0;
        int row = qbase + 16 * wid + (lid >> 2) + rr * 8;
        size_t base = (tok0 + row) * (size_t)D + h * HD + 2 * (lid & 3);
        #pragma unroll
        for (int t = 0; t < 8; t++) {
            float v0 = oacc[t][2 * rr] * inv;
            float v1 = oacc[t][2 * rr + 1] * inv;
            __nv_bfloat16 h0, l0, h1, l1;
            split2(v0, h0, l0);
            split2(v1, h1, l1);
            *reinterpret_cast<__nv_bfloat162*>(&oh[base + t * 8]) = __halves2bfloat162(h0, h1);
            *reinterpret_cast<__nv_bfloat162*>(&ol[base + t * 8]) = __halves2bfloat162(l0, l1);
        }
    }
}

// ---------------------------------------------------------------------------
// Launch
// ---------------------------------------------------------------------------
extern "C" void kernel_launch(void* const* d_in, const int* in_sizes, int n_in,
                              void* d_out, int out_size) {
    const float* x      = (const float*)d_in[0];
    const float* w_attn = (const float*)d_in[1];
    const float* b_attn = (const float*)d_in[2];
    const float* w_proj = (const float*)d_in[3];
    const float* b_proj = (const float*)d_in[4];
    const float* w_fc1  = (const float*)d_in[5];
    const float* b_fc1  = (const float*)d_in[6];
    const float* w_fc2  = (const float*)d_in[7];
    const float* b_fc2  = (const float*)d_in[8];
    const float* g1     = (const float*)d_in[9];
    const float* g2     = (const float*)d_in[10];
    float* out = (float*)d_out;

    __nv_bfloat16 *ah, *al, *bh, *bl, *wth, *wtl;
    __nv_bfloat16 *qh, *ql, *kh, *kl, *vh, *vl;
    cudaGetSymbolAddress((void**)&ah,  g_ah);
    cudaGetSymbolAddress((void**)&al,  g_al);
    cudaGetSymbolAddress((void**)&bh,  g_bh);
    cudaGetSymbolAddress((void**)&bl,  g_bl);
    cudaGetSymbolAddress((void**)&wth, g_wth);
    cudaGetSymbolAddress((void**)&wtl, g_wtl);
    cudaGetSymbolAddress((void**)&qh,  g_qh);
    cudaGetSymbolAddress((void**)&ql,  g_ql);
    cudaGetSymbolAddress((void**)&kh,  g_kh);
    cudaGetSymbolAddress((void**)&kl,  g_kl);
    cudaGetSymbolAddress((void**)&vh,  g_vh);
    cudaGetSymbolAddress((void**)&vl,  g_vl);

    cudaFuncSetAttribute(attn_mma_kernel, cudaFuncAttributeMaxDynamicSharedMemorySize, ATTN_SMEM);
    cudaFuncSetAttribute(tcgemm_kernel<EPI_BIAS>, cudaFuncAttributeMaxDynamicSharedMemorySize, TCG_SMEM);
    cudaFuncSetAttribute(tcgemm_kernel<EPI_GELU>, cudaFuncAttributeMaxDynamicSharedMemorySize, TCG_SMEM);
    cudaFuncSetAttribute(tcgemm_kernel<EPI_RES>,  cudaFuncAttributeMaxDynamicSharedMemorySize, TCG_SMEM);
    cudaFuncSetAttribute(tcgemm_kernel<EPI_QKV>,  cudaFuncAttributeMaxDynamicSharedMemorySize, TCG_SMEM);

    dim3 tp(32, 8);

    // 1. rmsnorm(x, g1) -> ah/al
    rmsnorm_split_kernel<<<NTOK, 256>>>(x, g1, ah, al);
    // 2. qkv gemm -> pre-split q/k/v per head
    transpose_split_kernel<<<dim3(D3 / 32, D / 32), tp>>>(w_attn, D, D3, wth, wtl);
    tcgemm_kernel<EPI_QKV><<<dim3(D3 / 128, NTOK / 128), 256, TCG_SMEM>>>(
        ah, al, wth, wtl, b_attn, nullptr, nullptr, nullptr, nullptr,
        qh, ql, kh, kl, vh, vl, NTOK, D3, D);
    // 3. attention -> ah/al
    attn_mma_kernel<<<dim3(TSEQ / 128, NH, NBATCH), 256, ATTN_SMEM>>>(
        qh, ql, kh, kl, vh, vl, ah, al);
    // 4. out = x + o @ w_proj + b_proj
    transpose_split_kernel<<<dim3(D / 32, D / 32), tp>>>(w_proj, D, D, wth, wtl);
    tcgemm_kernel<EPI_RES><<<dim3(D / 128, NTOK / 128), 256, TCG_SMEM>>>(
        ah, al, wth, wtl, b_proj, x, out, nullptr, nullptr,
        nullptr, nullptr, nullptr, nullptr, nullptr, nullptr, NTOK, D, D);
    // 5. rmsnorm(out, g2) -> ah/al
    rmsnorm_split_kernel<<<NTOK, 256>>>(out, g2, ah, al);
    // 6. bh/bl = gelu(h @ w_fc1 + b_fc1) split
    transpose_split_kernel<<<dim3(D4 / 32, D / 32), tp>>>(w_fc1, D, D4, wth, wtl);
    tcgemm_kernel<EPI_GELU><<<dim3(D4 / 128, NTOK / 128), 256, TCG_SMEM>>>(
        ah, al, wth, wtl, b_fc1, nullptr, nullptr, bh, bl,
        nullptr, nullptr, nullptr, nullptr, nullptr, nullptr, NTOK, D4, D);
    // 7. out = out + act @ w_fc2 + b_fc2
    transpose_split_kernel<<<dim3(D / 32, D4 / 32), tp>>>(w_fc2, D4, D, wth, wtl);
    tcgemm_kernel<EPI_RES><<<dim3(D / 128, NTOK / 128), 256, TCG_SMEM>>>(
        bh, bl, wth, wtl, b_fc2, out, out, nullptr, nullptr,
        nullptr, nullptr, nullptr, nullptr, nullptr, nullptr, NTOK, D, D4);
}

// round 9
// speedup vs baseline: 1.0240x; 1.0240x over previous
#include <cuda_runtime.h>
#include <cuda_bf16.h>
#include <math.h>
#include <cstdint>

#define D      1024
#define D3     3072
#define D4     4096
#define TSEQ   2048
#define NBATCH 2
#define NTOK   4096
#define NH     16
#define HD     64
#define EPS    1.1920929e-07f

// ---------------------------------------------------------------------------
// Scratch (device globals; no allocations allowed)
// ---------------------------------------------------------------------------
__device__ __nv_bfloat16 g_ah[NTOK * D];
__device__ __nv_bfloat16 g_al[NTOK * D];
__device__ __nv_bfloat16 g_bh[NTOK * D4];
__device__ __nv_bfloat16 g_bl[NTOK * D4];
__device__ __nv_bfloat16 g_wth[D * D4];
__device__ __nv_bfloat16 g_wtl[D * D4];
__device__ __nv_bfloat16 g_qh[NTOK * D];
__device__ __nv_bfloat16 g_ql[NTOK * D];
__device__ __nv_bfloat16 g_kh[NTOK * D];
__device__ __nv_bfloat16 g_kl[NTOK * D];
__device__ __nv_bfloat16 g_vh[NTOK * D];
__device__ __nv_bfloat16 g_vl[NTOK * D];

// ---------------------------------------------------------------------------
// Helpers
// ---------------------------------------------------------------------------
__device__ __forceinline__ uint32_t smem_to_u32(const void* p) {
    uint32_t a;
    asm("{ .reg .u64 t; cvta.to.shared.u64 t, %1; cvt.u32.u64 %0, t; }" : "=r"(a) : "l"(p));
    return a;
}

// 128B-row swizzle (16B chunk ^= row&7)
#define SWZ(off) ((uint32_t)(off) ^ ((((uint32_t)(off) >> 7) & 7) << 4))

__device__ __forceinline__ void ldsm_x4(uint32_t* r, uint32_t addr) {
    asm volatile("ldmatrix.sync.aligned.m8n8.x4.shared.b16 {%0,%1,%2,%3}, [%4];"
                 : "=r"(r[0]), "=r"(r[1]), "=r"(r[2]), "=r"(r[3]) : "r"(addr));
}
__device__ __forceinline__ void ldsm_x2(uint32_t* r, uint32_t addr) {
    asm volatile("ldmatrix.sync.aligned.m8n8.x2.shared.b16 {%0,%1}, [%2];"
                 : "=r"(r[0]), "=r"(r[1]) : "r"(addr));
}
__device__ __forceinline__ void ldsm_x2_trans(uint32_t* r, uint32_t addr) {
    asm volatile("ldmatrix.sync.aligned.m8n8.x2.trans.shared.b16 {%0,%1}, [%2];"
                 : "=r"(r[0]), "=r"(r[1]) : "r"(addr));
}
__device__ __forceinline__ void mma_bf16_g(float* d, const uint32_t* a, const uint32_t* b) {
    asm volatile(
        "mma.sync.aligned.m16n8k16.row.col.f32.bf16.bf16.f32 "
        "{%0,%1,%2,%3}, {%4,%5,%6,%7}, {%8,%9}, {%0,%1,%2,%3};"
        : "+f"(d[0]), "+f"(d[1]), "+f"(d[2]), "+f"(d[3])
        : "r"(a[0]), "r"(a[1]), "r"(a[2]), "r"(a[3]), "r"(b[0]), "r"(b[1]));
}

__device__ __forceinline__ void split2(float v, __nv_bfloat16& h, __nv_bfloat16& l) {
    h = __float2bfloat16(v);
    l = __float2bfloat16(v - __bfloat162float(h));
}
__device__ __forceinline__ uint32_t pack_bf16x2(float a, float b) {
    uint32_t r;
    asm("cvt.rn.bf16x2.f32 %0, %1, %2;" : "=r"(r) : "f"(b), "f"(a));
    return r;
}
__device__ __forceinline__ uint32_t pack_hi16(float a, float b) {
    uint32_t r;
    asm("prmt.b32 %0, %1, %2, 0x7632;" : "=r"(r) : "r"(__float_as_uint(a)), "r"(__float_as_uint(b)));
    return r;
}
__device__ __forceinline__ float trunc_bf16f(float v) {
    return __uint_as_float(__float_as_uint(v) & 0xFFFF0000u);
}

// ---------------------------------------------------------------------------
// RMSNorm -> bf16 hi/lo split
// ---------------------------------------------------------------------------
__global__ void rmsnorm_split_kernel(const float* __restrict__ x,
                                     const float* __restrict__ g,
                                     __nv_bfloat16* __restrict__ oh,
                                     __nv_bfloat16* __restrict__ ol) {
    int row = blockIdx.x;
    const float4* xr = reinterpret_cast<const float4*>(x + (size_t)row * D);
    float4 v = xr[threadIdx.x];
    float s = v.x * v.x + v.y * v.y + v.z * v.z + v.w * v.w;
    #pragma unroll
    for (int o = 16; o > 0; o >>= 1) s += __shfl_xor_sync(0xffffffffu, s, o);
    __shared__ float ws[8];
    if ((threadIdx.x & 31) == 0) ws[threadIdx.x >> 5] = s;
    __syncthreads();
    float tot = ws[0] + ws[1] + ws[2] + ws[3] + ws[4] + ws[5] + ws[6] + ws[7];
    float inv = rsqrtf(tot * (1.0f / (float)D) + EPS);
    float4 gv = reinterpret_cast<const float4*>(g)[threadIdx.x];
    float vals[4] = {v.x * inv * gv.x, v.y * inv * gv.y, v.z * inv * gv.z, v.w * inv * gv.w};
    __nv_bfloat16 h[4], l[4];
    #pragma unroll
    for (int j = 0; j < 4; j++) split2(vals[j], h[j], l[j]);
    size_t off = (size_t)row * D + threadIdx.x * 4;
    *reinterpret_cast<__nv_bfloat162*>(&oh[off])     = __halves2bfloat162(h[0], h[1]);
    *reinterpret_cast<__nv_bfloat162*>(&oh[off + 2]) = __halves2bfloat162(h[2], h[3]);
    *reinterpret_cast<__nv_bfloat162*>(&ol[off])     = __halves2bfloat162(l[0], l[1]);
    *reinterpret_cast<__nv_bfloat162*>(&ol[off + 2]) = __halves2bfloat162(l[2], l[3]);
}

// ---------------------------------------------------------------------------
// Weight transpose + bf16 split: W[K,N] -> Wt_hi/Wt_lo [N,K]
// ---------------------------------------------------------------------------
__global__ void transpose_split_kernel(const float* __restrict__ W, int K, int N,
                                       __nv_bfloat16* __restrict__ Th,
                                       __nv_bfloat16* __restrict__ Tl) {
    __shared__ float t[32][33];
    int k0 = blockIdx.y * 32, n0 = blockIdx.x * 32;
    int x = threadIdx.x, y = threadIdx.y;   // 32 x 8
    #pragma unroll
    for (int i = y; i < 32; i += 8)
        t[i][x] = W[(size_t)(k0 + i) * N + n0 + x];
    __syncthreads();
    #pragma unroll
    for (int b = y; b < 32; b += 8) {
        float v = t[x][b];
        __nv_bfloat16 h, l;
        split2(v, h, l);
        size_t o = (size_t)(n0 + b) * K + k0 + x;
        Th[o] = h;
        Tl[o] = l;
    }
}

// ---------------------------------------------------------------------------
// mma.sync split-bf16 GEMM: CTA 256x128, BK=64, 512 threads (16 warps 4x4),
// warp tile 64x32, 2-stage cp.async, 1 CTA/SM (4 warps/SMSP).
// ---------------------------------------------------------------------------
#define EPI_BIAS 0
#define EPI_GELU 1
#define EPI_RES  2
#define EPI_QKV  3

// stage: Ah 32K | Al 32K | Bh 16K | Bl 16K = 96K
#define STAGE_BYTES 98304
#define TCG_SMEM (2 * STAGE_BYTES)

template <int EPI>
__global__ __launch_bounds__(512, 1)
void tcgemm_kernel(const __nv_bfloat16* __restrict__ Ah, const __nv_bfloat16* __restrict__ Al,
                   const __nv_bfloat16* __restrict__ Bh, const __nv_bfloat16* __restrict__ Bl,
                   const float* __restrict__ bias, const float* __restrict__ R,
                   float* __restrict__ C,
                   __nv_bfloat16* __restrict__ Oh, __nv_bfloat16* __restrict__ Ol,
                   __nv_bfloat16* __restrict__ Qh, __nv_bfloat16* __restrict__ Ql,
                   __nv_bfloat16* __restrict__ Kh, __nv_bfloat16* __restrict__ Kl,
                   __nv_bfloat16* __restrict__ Vh, __nv_bfloat16* __restrict__ Vl,
                   int M, int N, int K) {
    extern __shared__ __align__(1024) char smem[];
    uint32_t sbase = smem_to_u32(smem);
    const int tid = threadIdx.x;
    const int wid = tid >> 5, lid = tid & 31;
    const int wm = wid >> 2, wn = wid & 3;        // 4x4 warps, warp tile 64x32
    const int bm = blockIdx.y * 256, bn = blockIdx.x * 128;

    auto load_chunk = [&](int c, int s) {
        uint32_t tb = sbase + s * STAGE_BYTES;
        // A hi/lo: 256 rows x 128B
        #pragma unroll
        for (int t2 = 0; t2 < 2; t2++) {
            const __nv_bfloat16* src = t2 ? Al : Ah;
            uint32_t dst0 = tb + t2 * 32768;
            #pragma unroll
            for (int i = 0; i < 4; i++) {
                int u = tid + i * 512;          // 0..2047
                int r = u >> 3, j = u & 7;
                uint32_t d = dst0 + SWZ(r * 128 + j * 16);
                const void* g = src + (size_t)(bm + r) * K + c * 64 + j * 8;
                asm volatile("cp.async.cg.shared.global [%0], [%1], 16;"
                             :: "r"(d), "l"(g) : "memory");
            }
        }
        // B hi/lo: 128 rows x 128B
        #pragma unroll
        for (int t2 = 0; t2 < 2; t2++) {
            const __nv_bfloat16* src = t2 ? Bl : Bh;
            uint32_t dst0 = tb + 65536 + t2 * 16384;
            #pragma unroll
            for (int i = 0; i < 2; i++) {
                int u = tid + i * 512;          // 0..1023
                int r = u >> 3, j = u & 7;
                uint32_t d = dst0 + SWZ(r * 128 + j * 16);
                const void* g = src + (size_t)(bn + r) * K + c * 64 + j * 8;
                asm volatile("cp.async.cg.shared.global [%0], [%1], 16;"
                             :: "r"(d), "l"(g) : "memory");
            }
        }
        asm volatile("cp.async.commit_group;" ::: "memory");
    };

    float acc[4][4][4];
    #pragma unroll
    for (int im = 0; im < 4; im++)
        #pragma unroll
        for (int in = 0; in < 4; in++)
            #pragma unroll
            for (int q = 0; q < 4; q++) acc[im][in][q] = 0.0f;

    const int nchunks = K >> 6;
    load_chunk(0, 0);

    const int arow = wm * 64 + (lid & 15);
    const int acol = (lid >> 4) * 16;
    const int brow = wn * 32 + (lid & 7);
    const int bcol = ((lid >> 3) & 1) * 16;

    for (int c = 0; c < nchunks; c++) {
        int s = c & 1;
        if (c + 1 < nchunks) {
            load_chunk(c + 1, s ^ 1);
            asm volatile("cp.async.wait_group 1;" ::: "memory");
        } else {
            asm volatile("cp.async.wait_group 0;" ::: "memory");
        }
        __syncthreads();

        uint32_t tb = sbase + s * STAGE_BYTES;
        uint32_t tAh = tb, tAl = tb + 32768, tBh = tb + 65536, tBl = tb + 81920;

        #pragma unroll
        for (int ks = 0; ks < 4; ks++) {
            uint32_t ah[4][4], al[4][4], bh[4][2], bl[4][2];
            #pragma unroll
            for (int im = 0; im < 4; im++) {
                uint32_t off = SWZ((arow + im * 16) * 128 + ks * 32 + acol);
                ldsm_x4(ah[im], tAh + off);
            }
            #pragma unroll
            for (int in = 0; in < 4; in++) {
                uint32_t off = SWZ((brow + in * 8) * 128 + ks * 32 + bcol);
                ldsm_x2(bh[in], tBh + off);
            }
            #pragma unroll
            for (int im = 0; im < 4; im++)
                #pragma unroll
                for (int in = 0; in < 4; in++)
                    mma_bf16_g(acc[im][in], ah[im], bh[in]);
            #pragma unroll
            for (int in = 0; in < 4; in++) {
                uint32_t off = SWZ((brow + in * 8) * 128 + ks * 32 + bcol);
                ldsm_x2(bl[in], tBl + off);
            }
            #pragma unroll
            for (int im = 0; im < 4; im++)
                #pragma unroll
                for (int in = 0; in < 4; in++)
                    mma_bf16_g(acc[im][in], ah[im], bl[in]);
            #pragma unroll
            for (int im = 0; im < 4; im++) {
                uint32_t off = SWZ((arow + im * 16) * 128 + ks * 32 + acol);
                ldsm_x4(al[im], tAl + off);
            }
            #pragma unroll
            for (int im = 0; im < 4; im++)
                #pragma unroll
                for (int in = 0; in < 4; in++)
                    mma_bf16_g(acc[im][in], al[im], bh[in]);
        }
        __syncthreads();
    }

    #pragma unroll
    for (int im = 0; im < 4; im++) {
        #pragma unroll
        for (int in = 0; in < 4; in++) {
            int m0 = bm + wm * 64 + im * 16 + (lid >> 2);
            int n0 = bn + wn * 32 + in * 8 + (lid & 3) * 2;
            float b0 = bias[n0], b1 = bias[n0 + 1];
            #pragma unroll
            for (int half = 0; half < 2; half++) {
                int m = m0 + half * 8;
                float v0 = acc[im][in][half * 2]     + b0;
                float v1 = acc[im][in][half * 2 + 1] + b1;
                if (EPI == EPI_QKV) {
                    int part = n0 >> 10;
                    int head = (n0 >> 6) & 15;
                    int d = n0 & 63;
                    int bb = m >> 11, t = m & 2047;
                    size_t dst = ((size_t)(bb * NH + head) * TSEQ + t) * HD + d;
                    __nv_bfloat16 h0, l0, h1, l1;
                    split2(v0, h0, l0);
                    split2(v1, h1, l1);
                    __nv_bfloat16* dh = (part == 0) ? Qh : (part == 1) ? Kh : Vh;
                    __nv_bfloat16* dl = (part == 0) ? Ql : (part == 1) ? Kl : Vl;
                    *reinterpret_cast<__nv_bfloat162*>(&dh[dst]) = __halves2bfloat162(h0, h1);
                    *reinterpret_cast<__nv_bfloat162*>(&dl[dst]) = __halves2bfloat162(l0, l1);
                } else if (EPI == EPI_GELU) {
                    size_t off = (size_t)m * N + n0;
                    float g0 = 0.5f * v0 * (1.0f + erff(v0 * 0.70710678118654752f));
                    float g1 = 0.5f * v1 * (1.0f + erff(v1 * 0.70710678118654752f));
                    __nv_bfloat16 h0, l0, h1, l1;
                    split2(g0, h0, l0);
                    split2(g1, h1, l1);
                    *reinterpret_cast<__nv_bfloat162*>(&Oh[off]) = __halves2bfloat162(h0, h1);
                    *reinterpret_cast<__nv_bfloat162*>(&Ol[off]) = __halves2bfloat162(l0, l1);
                } else {
                    size_t off = (size_t)m * N + n0;
                    if (EPI == EPI_RES) {
                        float2 rr = *reinterpret_cast<const float2*>(&R[off]);
                        v0 += rr.x; v1 += rr.y;
                    }
                    float2 o2 = make_float2(v0, v1);
                    *reinterpret_cast<float2*>(&C[off]) = o2;
                }
            }
        }
    }
}

// ---------------------------------------------------------------------------
// Tensor-core flash attention (unchanged 1039us baseline, heavy-first).
// ---------------------------------------------------------------------------
#define ATTN_SMEM 98304

__global__ __launch_bounds__(256, 1)
void attn_mma_kernel(const __nv_bfloat16* __restrict__ Qh, const __nv_bfloat16* __restrict__ Ql,
                     const __nv_bfloat16* __restrict__ Kh, const __nv_bfloat16* __restrict__ Kl,
                     const __nv_bfloat16* __restrict__ Vh, const __nv_bfloat16* __restrict__ Vl,
                     __nv_bfloat16* __restrict__ oh, __nv_bfloat16* __restrict__ ol) {
    extern __shared__ __align__(1024) char smem_raw[];
    uint32_t sb = smem_to_u32(smem_raw);
    const uint32_t sQh = 0, sQl = 16384;

    const int tid = threadIdx.x;
    const int wid = tid >> 5, lid = tid & 31;
    const int qb = gridDim.x - 1 - blockIdx.x;
    const int h = blockIdx.y, b = blockIdx.z;
    const int qbase = qb * 128;
    const size_t hdbase = (size_t)(b * NH + h) * TSEQ * HD;

    const __nv_bfloat16* kvsrc[4] = {Kh + hdbase, Kl + hdbase, Vh + hdbase, Vl + hdbase};

    auto load_kv = [&](int c, int s) {
        uint32_t slot = sb + 32768 + s * 32768;
        int rowbase = c * 64;
        #pragma unroll
        for (int i = 0; i < 8; i++) {
            int u = tid + i * 256;
            int t4 = u >> 9;
            int c2 = u & 511;
            int r = c2 >> 3, j = c2 & 7;
            uint32_t d = slot + t4 * 8192 + SWZ(r * 128 + j * 16);
            const void* g = kvsrc[t4] + (size_t)(rowbase + r) * HD + j * 8;
            asm volatile("cp.async.cg.shared.global [%0], [%1], 16;"
                         :: "r"(d), "l"(g) : "memory");
        }
    };

    {
        const __nv_bfloat16* qhp = Qh + hdbase + (size_t)qbase * HD;
        const __nv_bfloat16* qlp = Ql + hdbase + (size_t)qbase * HD;
        #pragma unroll
        for (int i = 0; i < 4; i++) {
            int u = tid + i * 256;
            int r = u >> 3, j = u & 7;
            uint32_t o = SWZ(r * 128 + j * 16);
            asm volatile("cp.async.cg.shared.global [%0], [%1], 16;"
                         :: "r"(sb + sQh + o), "l"((const void*)(qhp + (size_t)r * HD + j * 8)) : "memory");
            asm volatile("cp.async.cg.shared.global [%0], [%1], 16;"
                         :: "r"(sb + sQl + o), "l"((const void*)(qlp + (size_t)r * HD + j * 8)) : "memory");
        }
        load_kv(0, 0);
        asm volatile("cp.async.commit_group;" ::: "memory");
    }

    float mrow[2] = {-1e30f, -1e30f};
    float lrow[2] = {0.0f, 0.0f};
    float oacc[8][4];
    #pragma unroll
    for (int t = 0; t < 8; t++)
        #pragma unroll
        for (int c = 0; c < 4; c++) oacc[t][c] = 0.0f;

    const int nchunks = 2 * qb + 2;
    const int wrow_hi = qbase + 16 * wid + 15;

    for (int kc = 0; kc < nchunks; kc++) {
        const int kbase = kc * 64;
        const int s = kc & 1;
        if (kc + 1 < nchunks) {
            load_kv(kc + 1, s ^ 1);
            asm volatile("cp.async.commit_group;" ::: "memory");
            asm volatile("cp.async.wait_group 1;" ::: "memory");
        } else {
            asm volatile("cp.async.wait_group 0;" ::: "memory");
        }
        __syncthreads();

        if (wrow_hi >= kbase) {
            const uint32_t slot = sb + 32768 + s * 32768;
            const uint32_t tKh = slot, tKl = slot + 8192, tVh = slot + 16384, tVl = slot + 24576;

            uint32_t qh[4][4], ql[4][4];
            {
                int qr = 16 * wid + (lid & 15);
                int qc = (lid >> 4) * 16;
                #pragma unroll
                for (int ks = 0; ks < 4; ks++) {
                    uint32_t off = SWZ(qr * 128 + ks * 32 + qc);
                    ldsm_x4(qh[ks], sb + sQh + off);
                    ldsm_x4(ql[ks], sb + sQl + off);
                }
            }
            float sacc[8][4];
            #pragma unroll
            for (int t = 0; t < 8; t++)
                #pragma unroll
                for (int c = 0; c < 4; c++) sacc[t][c] = 0.0f;

            {
                int kr = lid & 7;
                int kcb = ((lid >> 3) & 1) * 16;
                #pragma unroll
                for (int t = 0; t < 8; t++) {
                    #pragma unroll
                    for (int ks = 0; ks < 4; ks++) {
                        uint32_t off = SWZ((t * 8 + kr) * 128 + ks * 32 + kcb);
                        uint32_t bh2[2], bl2[2];
                        ldsm_x2(bh2, tKh + off);
                        ldsm_x2(bl2, tKl + off);
                        mma_bf16_g(sacc[t], qh[ks], bh2);
                        mma_bf16_g(sacc[t], ql[ks], bh2);
                        mma_bf16_g(sacc[t], qh[ks], bl2);
                    }
                }
            }

            if (kc >= 2 * qb) {
                int row0 = qbase + 16 * wid + (lid >> 2);
                #pragma unroll
                for (int t = 0; t < 8; t++) {
                    int col = kbase + t * 8 + 2 * (lid & 3);
                    if (col > row0)     sacc[t][0] = -1e30f;
                    if (col + 1 > row0) sacc[t][1] = -1e30f;
                    if (col > row0 + 8)     sacc[t][2] = -1e30f;
                    if (col + 1 > row0 + 8) sacc[t][3] = -1e30f;
                }
            }

            #pragma unroll
            for (int rr = 0; rr < 2; rr++) {
                float mx = -1e30f;
                #pragma unroll
                for (int t = 0; t < 8; t++)
                    mx = fmaxf(mx, fmaxf(sacc[t][2 * rr], sacc[t][2 * rr + 1]));
                mx = fmaxf(mx, __shfl_xor_sync(0xffffffffu, mx, 1));
                mx = fmaxf(mx, __shfl_xor_sync(0xffffffffu, mx, 2));
                float mn = fmaxf(mrow[rr], mx);
                float sc = __expf(mrow[rr] - mn);
                mrow[rr] = mn;
                float rs = 0.0f;
                #pragma unroll
                for (int t = 0; t < 8; t++) {
                    float p0 = __expf(sacc[t][2 * rr] - mn);
                    float p1 = __expf(sacc[t][2 * rr + 1] - mn);
                    sacc[t][2 * rr] = p0; sacc[t][2 * rr + 1] = p1;
                    rs += p0 + p1;
                }
                lrow[rr] = lrow[rr] * sc + rs;
                #pragma unroll
                for (int t = 0; t < 8; t++) {
                    oacc[t][2 * rr]     *= sc;
                    oacc[t][2 * rr + 1] *= sc;
                }
            }

            {
                int vr = (lid & 7) + ((lid >> 3) & 1) * 8;
                #pragma unroll
                for (int j = 0; j < 4; j++) {
                    uint32_t ph[4], pl[4];
                    #pragma unroll
                    for (int half = 0; half < 2; half++) {
                        float a0 = sacc[2 * j + half][0], a1 = sacc[2 * j + half][1];
                        float a2 = sacc[2 * j + half][2], a3 = sacc[2 * j + half][3];
                        ph[0 + 2 * half] = pack_hi16(a0, a1);
                        ph[1 + 2 * half] = pack_hi16(a2, a3);
                        pl[0 + 2 * half] = pack_bf16x2(a0 - trunc_bf16f(a0), a1 - trunc_bf16f(a1));
                        pl[1 + 2 * half] = pack_bf16x2(a2 - trunc_bf16f(a2), a3 - trunc_bf16f(a3));
                    }
                    #pragma unroll
                    for (int t = 0; t < 8; t++) {
                        uint32_t voff = SWZ((j * 16 + vr) * 128 + t * 16);
                        uint32_t vh2[2], vl2[2];
                        ldsm_x2_trans(vh2, tVh + voff);
                        ldsm_x2_trans(vl2, tVl + voff);
                        mma_bf16_g(oacc[t], ph, vh2);
                        mma_bf16_g(oacc[t], pl, vh2);
                        mma_bf16_g(oacc[t], ph, vl2);
                    }
                }
            }
        }
        __syncthreads();
    }

    lrow[0] += __shfl_xor_sync(0xffffffffu, lrow[0], 1);
    lrow[0] += __shfl_xor_sync(0xffffffffu, lrow[0], 2);
    lrow[1] += __shfl_xor_sync(0xffffffffu, lrow[1], 1);
    lrow[1] += __shfl_xor_sync(0xffffffffu, lrow[1], 2);
    float inv0 = 0.03125f / lrow[0];
    float inv1 = 0.03125f / lrow[1];

    const size_t tok0 = (size_t)b * TSEQ;
    #pragma unroll
    for (int rr = 0; rr < 2; rr++) {
        float inv = rr ? inv1 : inv0;
        int row = qbase + 16 * wid + (lid >> 2) + rr * 8;
        size_t base = (tok0 + row) * (size_t)D + h * HD + 2 * (lid & 3);
        #pragma unroll
        for (int t = 0; t < 8; t++) {
            float v0 = oacc[t][2 * rr] * inv;
            float v1 = oacc[t][2 * rr + 1] * inv;
            __nv_bfloat16 h0, l0, h1, l1;
            split2(v0, h0, l0);
            split2(v1, h1, l1);
            *reinterpret_cast<__nv_bfloat162*>(&oh[base + t * 8]) = __halves2bfloat162(h0, h1);
            *reinterpret_cast<__nv_bfloat162*>(&ol[base + t * 8]) = __halves2bfloat162(l0, l1);
        }
    }
}

// ---------------------------------------------------------------------------
// Launch
// ---------------------------------------------------------------------------
extern "C" void kernel_launch(void* const* d_in, const int* in_sizes, int n_in,
                              void* d_out, int out_size) {
    const float* x      = (const float*)d_in[0];
    const float* w_attn = (const float*)d_in[1];
    const float* b_attn = (const float*)d_in[2];
    const float* w_proj = (const float*)d_in[3];
    const float* b_proj = (const float*)d_in[4];
    const float* w_fc1  = (const float*)d_in[5];
    const float* b_fc1  = (const float*)d_in[6];
    const float* w_fc2  = (const float*)d_in[7];
    const float* b_fc2  = (const float*)d_in[8];
    const float* g1     = (const float*)d_in[9];
    const float* g2     = (const float*)d_in[10];
    float* out = (float*)d_out;

    __nv_bfloat16 *ah, *al, *bh, *bl, *wth, *wtl;
    __nv_bfloat16 *qh, *ql, *kh, *kl, *vh, *vl;
    cudaGetSymbolAddress((void**)&ah,  g_ah);
    cudaGetSymbolAddress((void**)&al,  g_al);
    cudaGetSymbolAddress((void**)&bh,  g_bh);
    cudaGetSymbolAddress((void**)&bl,  g_bl);
    cudaGetSymbolAddress((void**)&wth, g_wth);
    cudaGetSymbolAddress((void**)&wtl, g_wtl);
    cudaGetSymbolAddress((void**)&qh,  g_qh);
    cudaGetSymbolAddress((void**)&ql,  g_ql);
    cudaGetSymbolAddress((void**)&kh,  g_kh);
    cudaGetSymbolAddress((void**)&kl,  g_kl);
    cudaGetSymbolAddress((void**)&vh,  g_vh);
    cudaGetSymbolAddress((void**)&vl,  g_vl);

    cudaFuncSetAttribute(attn_mma_kernel, cudaFuncAttributeMaxDynamicSharedMemorySize, ATTN_SMEM);
    cudaFuncSetAttribute(tcgemm_kernel<EPI_BIAS>, cudaFuncAttributeMaxDynamicSharedMemorySize, TCG_SMEM);
    cudaFuncSetAttribute(tcgemm_kernel<EPI_GELU>, cudaFuncAttributeMaxDynamicSharedMemorySize, TCG_SMEM);
    cudaFuncSetAttribute(tcgemm_kernel<EPI_RES>,  cudaFuncAttributeMaxDynamicSharedMemorySize, TCG_SMEM);
    cudaFuncSetAttribute(tcgemm_kernel<EPI_QKV>,  cudaFuncAttributeMaxDynamicSharedMemorySize, TCG_SMEM);

    dim3 tp(32, 8);

    // 1. rmsnorm(x, g1) -> ah/al
    rmsnorm_split_kernel<<<NTOK, 256>>>(x, g1, ah, al);
    // 2. qkv gemm -> pre-split q/k/v per head
    transpose_split_kernel<<<dim3(D3 / 32, D / 32), tp>>>(w_attn, D, D3, wth, wtl);
    tcgemm_kernel<EPI_QKV><<<dim3(D3 / 128, NTOK / 256), 512, TCG_SMEM>>>(
        ah, al, wth, wtl, b_attn, nullptr, nullptr, nullptr, nullptr,
        qh, ql, kh, kl, vh, vl, NTOK, D3, D);
    // 3. attention -> ah/al
    attn_mma_kernel<<<dim3(TSEQ / 128, NH, NBATCH), 256, ATTN_SMEM>>>(
        qh, ql, kh, kl, vh, vl, ah, al);
    // 4. out = x + o @ w_proj + b_proj
    transpose_split_kernel<<<dim3(D / 32, D / 32), tp>>>(w_proj, D, D, wth, wtl);
    tcgemm_kernel<EPI_RES><<<dim3(D / 128, NTOK / 256), 512, TCG_SMEM>>>(
        ah, al, wth, wtl, b_proj, x, out, nullptr, nullptr,
        nullptr, nullptr, nullptr, nullptr, nullptr, nullptr, NTOK, D, D);
    // 5. rmsnorm(out, g2) -> ah/al
    rmsnorm_split_kernel<<<NTOK, 256>>>(out, g2, ah, al);
    // 6. bh/bl = gelu(h @ w_fc1 + b_fc1) split
    transpose_split_kernel<<<dim3(D4 / 32, D / 32), tp>>>(w_fc1, D, D4, wth, wtl);
    tcgemm_kernel<EPI_GELU><<<dim3(D4 / 128, NTOK / 256), 512, TCG_SMEM>>>(
        ah, al, wth, wtl, b_fc1, nullptr, nullptr, bh, bl,
        nullptr, nullptr, nullptr, nullptr, nullptr, nullptr, NTOK, D4, D);
    // 7. out = out + act @ w_fc2 + b_fc2
    transpose_split_kernel<<<dim3(D / 32, D4 / 32), tp>>>(w_fc2, D4, D, wth, wtl);
    tcgemm_kernel<EPI_RES><<<dim3(D / 128, NTOK / 256), 512, TCG_SMEM>>>(
        bh, bl, wth, wtl, b_fc2, out, out, nullptr, nullptr,
        nullptr, nullptr, nullptr, nullptr, nullptr, nullptr, NTOK, D, D4);
}

// round 11
// speedup vs baseline: 1.0632x; 1.0383x over previous
#include <cuda_runtime.h>
#include <cuda_bf16.h>
#include <math.h>
#include <cstdint>

#define D      1024
#define D3     3072
#define D4     4096
#define TSEQ   2048
#define NBATCH 2
#define NTOK   4096
#define NH     16
#define HD     64
#define EPS    1.1920929e-07f

// ---------------------------------------------------------------------------
// Scratch (device globals; no allocations allowed)
// ---------------------------------------------------------------------------
__device__ __nv_bfloat16 g_ah[NTOK * D];
__device__ __nv_bfloat16 g_al[NTOK * D];
__device__ __nv_bfloat16 g_bh[NTOK * D4];
__device__ __nv_bfloat16 g_bl[NTOK * D4];
// per-weight transposed split buffers
__device__ __nv_bfloat16 g_wA_h[D * D3];
__device__ __nv_bfloat16 g_wA_l[D * D3];
__device__ __nv_bfloat16 g_wP_h[D * D];
__device__ __nv_bfloat16 g_wP_l[D * D];
__device__ __nv_bfloat16 g_wF1_h[D * D4];
__device__ __nv_bfloat16 g_wF1_l[D * D4];
__device__ __nv_bfloat16 g_wF2_h[D4 * D];
__device__ __nv_bfloat16 g_wF2_l[D4 * D];
// pre-split q/k/v, layout [b, h, t, d]
__device__ __nv_bfloat16 g_qh[NTOK * D];
__device__ __nv_bfloat16 g_ql[NTOK * D];
__device__ __nv_bfloat16 g_kh[NTOK * D];
__device__ __nv_bfloat16 g_kl[NTOK * D];
__device__ __nv_bfloat16 g_vh[NTOK * D];
__device__ __nv_bfloat16 g_vl[NTOK * D];

// ---------------------------------------------------------------------------
// Helpers
// ---------------------------------------------------------------------------
__device__ __forceinline__ uint32_t smem_to_u32(const void* p) {
    uint32_t a;
    asm("{ .reg .u64 t; cvta.to.shared.u64 t, %1; cvt.u32.u64 %0, t; }" : "=r"(a) : "l"(p));
    return a;
}

#define SWZ(off) ((uint32_t)(off) ^ ((((uint32_t)(off) >> 7) & 7) << 4))

__device__ __forceinline__ void ldsm_x4(uint32_t* r, uint32_t addr) {
    asm volatile("ldmatrix.sync.aligned.m8n8.x4.shared.b16 {%0,%1,%2,%3}, [%4];"
                 : "=r"(r[0]), "=r"(r[1]), "=r"(r[2]), "=r"(r[3]) : "r"(addr));
}
__device__ __forceinline__ void ldsm_x2(uint32_t* r, uint32_t addr) {
    asm volatile("ldmatrix.sync.aligned.m8n8.x2.shared.b16 {%0,%1}, [%2];"
                 : "=r"(r[0]), "=r"(r[1]) : "r"(addr));
}
__device__ __forceinline__ void ldsm_x2_trans(uint32_t* r, uint32_t addr) {
    asm volatile("ldmatrix.sync.aligned.m8n8.x2.trans.shared.b16 {%0,%1}, [%2];"
                 : "=r"(r[0]), "=r"(r[1]) : "r"(addr));
}
__device__ __forceinline__ void mma_bf16_g(float* d, const uint32_t* a, const uint32_t* b) {
    asm volatile(
        "mma.sync.aligned.m16n8k16.row.col.f32.bf16.bf16.f32 "
        "{%0,%1,%2,%3}, {%4,%5,%6,%7}, {%8,%9}, {%0,%1,%2,%3};"
        : "+f"(d[0]), "+f"(d[1]), "+f"(d[2]), "+f"(d[3])
        : "r"(a[0]), "r"(a[1]), "r"(a[2]), "r"(a[3]), "r"(b[0]), "r"(b[1]));
}

__device__ __forceinline__ void split2(float v, __nv_bfloat16& h, __nv_bfloat16& l) {
    h = __float2bfloat16(v);
    l = __float2bfloat16(v - __bfloat162float(h));
}
__device__ __forceinline__ uint32_t pack_bf16x2(float a, float b) {
    uint32_t r;
    asm("cvt.rn.bf16x2.f32 %0, %1, %2;" : "=r"(r) : "f"(b), "f"(a));
    return r;
}
__device__ __forceinline__ uint32_t pack_hi16(float a, float b) {
    uint32_t r;
    asm("prmt.b32 %0, %1, %2, 0x7632;" : "=r"(r) : "r"(__float_as_uint(a)), "r"(__float_as_uint(b)));
    return r;
}
__device__ __forceinline__ float trunc_bf16f(float v) {
    return __uint_as_float(__float_as_uint(v) & 0xFFFF0000u);
}

// ---------------------------------------------------------------------------
// Fused prep kernel: rmsnorm(x,g1) + all 4 weight transposes, one launch.
// ---------------------------------------------------------------------------
__device__ __forceinline__ void do_transpose(const float* __restrict__ W, int K, int N,
                                             __nv_bfloat16* __restrict__ Th,
                                             __nv_bfloat16* __restrict__ Tl,
                                             int tile, float* tbuf /* [32][33] */) {
    int tiles_n = N >> 5;
    int k0 = (tile / tiles_n) << 5;
    int n0 = (tile % tiles_n) << 5;
    int x = threadIdx.x & 31, y = threadIdx.x >> 5;   // 32 x 8
    #pragma unroll
    for (int i = y; i < 32; i += 8)
        tbuf[i * 33 + x] = W[(size_t)(k0 + i) * N + n0 + x];
    __syncthreads();
    #pragma unroll
    for (int b = y; b < 32; b += 8) {
        float v = tbuf[x * 33 + b];
        __nv_bfloat16 h, l;
        split2(v, h, l);
        size_t o = (size_t)(n0 + b) * K + k0 + x;
        Th[o] = h;
        Tl[o] = l;
    }
}

__global__ void prep_kernel(const float* __restrict__ x, const float* __restrict__ g1,
                            __nv_bfloat16* __restrict__ oh, __nv_bfloat16* __restrict__ ol,
                            const float* __restrict__ wA, const float* __restrict__ wP,
                            const float* __restrict__ wF1, const float* __restrict__ wF2,
                            __nv_bfloat16* wAh, __nv_bfloat16* wAl,
                            __nv_bfloat16* wPh, __nv_bfloat16* wPl,
                            __nv_bfloat16* wF1h, __nv_bfloat16* wF1l,
                            __nv_bfloat16* wF2h, __nv_bfloat16* wF2l) {
    __shared__ float tbuf[32 * 33];
    int bid = blockIdx.x;
    if (bid < NTOK) {
        int row = bid;
        const float4* xr = reinterpret_cast<const float4*>(x + (size_t)row * D);
        float4 v = xr[threadIdx.x];
        float s = v.x * v.x + v.y * v.y + v.z * v.z + v.w * v.w;
        #pragma unroll
        for (int o = 16; o > 0; o >>= 1) s += __shfl_xor_sync(0xffffffffu, s, o);
        __shared__ float ws[8];
        if ((threadIdx.x & 31) == 0) ws[threadIdx.x >> 5] = s;
        __syncthreads();
        float tot = ws[0] + ws[1] + ws[2] + ws[3] + ws[4] + ws[5] + ws[6] + ws[7];
        float inv = rsqrtf(tot * (1.0f / (float)D) + EPS);
        float4 gv = reinterpret_cast<const float4*>(g1)[threadIdx.x];
        float vals[4] = {v.x * inv * gv.x, v.y * inv * gv.y, v.z * inv * gv.z, v.w * inv * gv.w};
        __nv_bfloat16 h[4], l[4];
        #pragma unroll
        for (int j = 0; j < 4; j++) split2(vals[j], h[j], l[j]);
        size_t off = (size_t)row * D + threadIdx.x * 4;
        *reinterpret_cast<__nv_bfloat162*>(&oh[off])     = __halves2bfloat162(h[0], h[1]);
        *reinterpret_cast<__nv_bfloat162*>(&oh[off + 2]) = __halves2bfloat162(h[2], h[3]);
        *reinterpret_cast<__nv_bfloat162*>(&ol[off])     = __halves2bfloat162(l[0], l[1]);
        *reinterpret_cast<__nv_bfloat162*>(&ol[off + 2]) = __halves2bfloat162(l[2], l[3]);
    } else if (bid < NTOK + 3072) {
        do_transpose(wA, D, D3, wAh, wAl, bid - NTOK, tbuf);
    } else if (bid < NTOK + 3072 + 1024) {
        do_transpose(wP, D, D, wPh, wPl, bid - NTOK - 3072, tbuf);
    } else if (bid < NTOK + 3072 + 1024 + 4096) {
        do_transpose(wF1, D, D4, wF1h, wF1l, bid - NTOK - 3072 - 1024, tbuf);
    } else {
        do_transpose(wF2, D4, D, wF2h, wF2l, bid - NTOK - 3072 - 1024 - 4096, tbuf);
    }
}

// ---------------------------------------------------------------------------
// rmsnorm (standalone, for norm2)
// ---------------------------------------------------------------------------
__global__ void rmsnorm_split_kernel(const float* __restrict__ x,
                                     const float* __restrict__ g,
                                     __nv_bfloat16* __restrict__ oh,
                                     __nv_bfloat16* __restrict__ ol) {
    int row = blockIdx.x;
    const float4* xr = reinterpret_cast<const float4*>(x + (size_t)row * D);
    float4 v = xr[threadIdx.x];
    float s = v.x * v.x + v.y * v.y + v.z * v.z + v.w * v.w;
    #pragma unroll
    for (int o = 16; o > 0; o >>= 1) s += __shfl_xor_sync(0xffffffffu, s, o);
    __shared__ float ws[8];
    if ((threadIdx.x & 31) == 0) ws[threadIdx.x >> 5] = s;
    __syncthreads();
    float tot = ws[0] + ws[1] + ws[2] + ws[3] + ws[4] + ws[5] + ws[6] + ws[7];
    float inv = rsqrtf(tot * (1.0f / (float)D) + EPS);
    float4 gv = reinterpret_cast<const float4*>(g)[threadIdx.x];
    float vals[4] = {v.x * inv * gv.x, v.y * inv * gv.y, v.z * inv * gv.z, v.w * inv * gv.w};
    __nv_bfloat16 h[4], l[4];
    #pragma unroll
    for (int j = 0; j < 4; j++) split2(vals[j], h[j], l[j]);
    size_t off = (size_t)row * D + threadIdx.x * 4;
    *reinterpret_cast<__nv_bfloat162*>(&oh[off])     = __halves2bfloat162(h[0], h[1]);
    *reinterpret_cast<__nv_bfloat162*>(&oh[off + 2]) = __halves2bfloat162(h[2], h[3]);
    *reinterpret_cast<__nv_bfloat162*>(&ol[off])     = __halves2bfloat162(l[0], l[1]);
    *reinterpret_cast<__nv_bfloat162*>(&ol[off + 2]) = __halves2bfloat162(l[2], l[3]);
}

// ---------------------------------------------------------------------------
// mma.sync split-bf16 GEMM: 128x128, BK=64, 3-stage, 256 threads.
// SAFE single-barrier pipeline: wait -> barrier -> issue load(c+2) -> compute.
// The load reusing slot (c-1)%3 is only issued after the barrier proves all
// warps finished iteration c-1.
// ---------------------------------------------------------------------------
#define EPI_BIAS 0
#define EPI_GELU 1
#define EPI_RES  2
#define EPI_QKV  3

#define STAGE_BYTES 65536
#define TCG_SMEM (3 * STAGE_BYTES)

template <int EPI>
__global__ __launch_bounds__(256, 1)
void tcgemm_kernel(const __nv_bfloat16* __restrict__ Ah, const __nv_bfloat16* __restrict__ Al,
                   const __nv_bfloat16* __restrict__ Bh, const __nv_bfloat16* __restrict__ Bl,
                   const float* __restrict__ bias, const float* __restrict__ R,
                   float* __restrict__ C,
                   __nv_bfloat16* __restrict__ Oh, __nv_bfloat16* __restrict__ Ol,
                   __nv_bfloat16* __restrict__ Qh, __nv_bfloat16* __restrict__ Ql,
                   __nv_bfloat16* __restrict__ Kh, __nv_bfloat16* __restrict__ Kl,
                   __nv_bfloat16* __restrict__ Vh, __nv_bfloat16* __restrict__ Vl,
                   int M, int N, int K) {
    extern __shared__ __align__(1024) char smem[];
    uint32_t sbase = smem_to_u32(smem);
    const int tid = threadIdx.x;
    const int wid = tid >> 5, lid = tid & 31;
    const int wm = wid >> 2, wn = wid & 3;
    const int bm = blockIdx.y * 128, bn = blockIdx.x * 128;

    const __nv_bfloat16* srcs[4] = {Ah, Al, Bh, Bl};

    auto load_chunk = [&](int c, int s) {
        uint32_t tb = sbase + s * STAGE_BYTES;
        #pragma unroll
        for (int t4 = 0; t4 < 4; t4++) {
            const __nv_bfloat16* src = srcs[t4];
            int rbase = (t4 < 2) ? bm : bn;
            uint32_t dst0 = tb + t4 * 16384;
            #pragma unroll
            for (int i = 0; i < 4; i++) {
                int u = tid + i * 256;
                int r = u >> 3, j = u & 7;
                uint32_t d = dst0 + SWZ(r * 128 + j * 16);
                const void* g = src + (size_t)(rbase + r) * K + c * 64 + j * 8;
                asm volatile("cp.async.cg.shared.global [%0], [%1], 16;"
                             :: "r"(d), "l"(g) : "memory");
            }
        }
        asm volatile("cp.async.commit_group;" ::: "memory");
    };

    float acc[4][4][4];
    #pragma unroll
    for (int im = 0; im < 4; im++)
        #pragma unroll
        for (int in = 0; in < 4; in++)
            #pragma unroll
            for (int q = 0; q < 4; q++) acc[im][in][q] = 0.0f;

    const int nchunks = K >> 6;
    load_chunk(0, 0);
    load_chunk(1, 1);

    const int arow = wm * 64 + (lid & 15);
    const int acol = (lid >> 4) * 16;
    const int brow = wn * 32 + (lid & 7);
    const int bcol = ((lid >> 3) & 1) * 16;

    for (int c = 0; c < nchunks; c++) {
        // pending groups here: {c, c+1} (for c < nchunks-1), {c} at the tail
        if (c + 1 < nchunks) {
            asm volatile("cp.async.wait_group 1;" ::: "memory");
        } else {
            asm volatile("cp.async.wait_group 0;" ::: "memory");
        }
        __syncthreads();          // all warps done with compute c-1; chunk c visible
        if (c + 2 < nchunks)
            load_chunk(c + 2, (c + 2) % 3);   // reuses slot (c-1)%3 — safe now

        int s = c % 3;
        uint32_t tb = sbase + s * STAGE_BYTES;
        uint32_t tAh = tb, tAl = tb + 16384, tBh = tb + 32768, tBl = tb + 49152;

        #pragma unroll
        for (int ks = 0; ks < 4; ks++) {
            uint32_t ah[4][4], al[4][4], bh[4][2], bl[4][2];
            #pragma unroll
            for (int im = 0; im < 4; im++) {
                uint32_t off = SWZ((arow + im * 16) * 128 + ks * 32 + acol);
                ldsm_x4(ah[im], tAh + off);
            }
            #pragma unroll
            for (int in = 0; in < 4; in++) {
                uint32_t off = SWZ((brow + in * 8) * 128 + ks * 32 + bcol);
                ldsm_x2(bh[in], tBh + off);
            }
            #pragma unroll
            for (int im = 0; im < 4; im++)
                #pragma unroll
                for (int in = 0; in < 4; in++)
                    mma_bf16_g(acc[im][in], ah[im], bh[in]);
            #pragma unroll
            for (int in = 0; in < 4; in++) {
                uint32_t off = SWZ((brow + in * 8) * 128 + ks * 32 + bcol);
                ldsm_x2(bl[in], tBl + off);
            }
            #pragma unroll
            for (int im = 0; im < 4; im++)
                #pragma unroll
                for (int in = 0; in < 4; in++)
                    mma_bf16_g(acc[im][in], ah[im], bl[in]);
            #pragma unroll
            for (int im = 0; im < 4; im++) {
                uint32_t off = SWZ((arow + im * 16) * 128 + ks * 32 + acol);
                ldsm_x4(al[im], tAl + off);
            }
            #pragma unroll
            for (int im = 0; im < 4; im++)
                #pragma unroll
                for (int in = 0; in < 4; in++)
                    mma_bf16_g(acc[im][in], al[im], bh[in]);
        }
    }

    #pragma unroll
    for (int im = 0; im < 4; im++) {
        #pragma unroll
        for (int in = 0; in < 4; in++) {
            int m0 = bm + wm * 64 + im * 16 + (lid >> 2);
            int n0 = bn + wn * 32 + in * 8 + (lid & 3) * 2;
            float b0 = bias[n0], b1 = bias[n0 + 1];
            #pragma unroll
            for (int half = 0; half < 2; half++) {
                int m = m0 + half * 8;
                float v0 = acc[im][in][half * 2]     + b0;
                float v1 = acc[im][in][half * 2 + 1] + b1;
                if (EPI == EPI_QKV) {
                    int part = n0 >> 10;
                    int head = (n0 >> 6) & 15;
                    int d = n0 & 63;
                    int bb = m >> 11, t = m & 2047;
                    size_t dst = ((size_t)(bb * NH + head) * TSEQ + t) * HD + d;
                    __nv_bfloat16 h0, l0, h1, l1;
                    split2(v0, h0, l0);
                    split2(v1, h1, l1);
                    __nv_bfloat16* dh = (part == 0) ? Qh : (part == 1) ? Kh : Vh;
                    __nv_bfloat16* dl = (part == 0) ? Ql : (part == 1) ? Kl : Vl;
                    *reinterpret_cast<__nv_bfloat162*>(&dh[dst]) = __halves2bfloat162(h0, h1);
                    *reinterpret_cast<__nv_bfloat162*>(&dl[dst]) = __halves2bfloat162(l0, l1);
                } else if (EPI == EPI_GELU) {
                    size_t off = (size_t)m * N + n0;
                    float g0 = 0.5f * v0 * (1.0f + erff(v0 * 0.70710678118654752f));
                    float g1 = 0.5f * v1 * (1.0f + erff(v1 * 0.70710678118654752f));
                    __nv_bfloat16 h0, l0, h1, l1;
                    split2(g0, h0, l0);
                    split2(g1, h1, l1);
                    *reinterpret_cast<__nv_bfloat162*>(&Oh[off]) = __halves2bfloat162(h0, h1);
                    *reinterpret_cast<__nv_bfloat162*>(&Ol[off]) = __halves2bfloat162(l0, l1);
                } else {
                    size_t off = (size_t)m * N + n0;
                    if (EPI == EPI_RES) {
                        float2 rr = *reinterpret_cast<const float2*>(&R[off]);
                        v0 += rr.x; v1 += rr.y;
                    }
                    float2 o2 = make_float2(v0, v1);
                    *reinterpret_cast<float2*>(&C[off]) = o2;
                }
            }
        }
    }
}

// ---------------------------------------------------------------------------
// Tensor-core flash attention (1039us baseline, heavy-first).
// ---------------------------------------------------------------------------
#define ATTN_SMEM 98304

__global__ __launch_bounds__(256, 1)
void attn_mma_kernel(const __nv_bfloat16* __restrict__ Qh, const __nv_bfloat16* __restrict__ Ql,
                     const __nv_bfloat16* __restrict__ Kh, const __nv_bfloat16* __restrict__ Kl,
                     const __nv_bfloat16* __restrict__ Vh, const __nv_bfloat16* __restrict__ Vl,
                     __nv_bfloat16* __restrict__ oh, __nv_bfloat16* __restrict__ ol) {
    extern __shared__ __align__(1024) char smem_raw[];
    uint32_t sb = smem_to_u32(smem_raw);
    const uint32_t sQh = 0, sQl = 16384;

    const int tid = threadIdx.x;
    const int wid = tid >> 5, lid = tid & 31;
    const int qb = gridDim.x - 1 - blockIdx.x;
    const int h = blockIdx.y, b = blockIdx.z;
    const int qbase = qb * 128;
    const size_t hdbase = (size_t)(b * NH + h) * TSEQ * HD;

    const __nv_bfloat16* kvsrc[4] = {Kh + hdbase, Kl + hdbase, Vh + hdbase, Vl + hdbase};

    auto load_kv = [&](int c, int s) {
        uint32_t slot = sb + 32768 + s * 32768;
        int rowbase = c * 64;
        #pragma unroll
        for (int i = 0; i < 8; i++) {
            int u = tid + i * 256;
            int t4 = u >> 9;
            int c2 = u & 511;
            int r = c2 >> 3, j = c2 & 7;
            uint32_t d = slot + t4 * 8192 + SWZ(r * 128 + j * 16);
            const void* g = kvsrc[t4] + (size_t)(rowbase + r) * HD + j * 8;
            asm volatile("cp.async.cg.shared.global [%0], [%1], 16;"
                         :: "r"(d), "l"(g) : "memory");
        }
    };

    {
        const __nv_bfloat16* qhp = Qh + hdbase + (size_t)qbase * HD;
        const __nv_bfloat16* qlp = Ql + hdbase + (size_t)qbase * HD;
        #pragma unroll
        for (int i = 0; i < 4; i++) {
            int u = tid + i * 256;
            int r = u >> 3, j = u & 7;
            uint32_t o = SWZ(r * 128 + j * 16);
            asm volatile("cp.async.cg.shared.global [%0], [%1], 16;"
                         :: "r"(sb + sQh + o), "l"((const void*)(qhp + (size_t)r * HD + j * 8)) : "memory");
            asm volatile("cp.async.cg.shared.global [%0], [%1], 16;"
                         :: "r"(sb + sQl + o), "l"((const void*)(qlp + (size_t)r * HD + j * 8)) : "memory");
        }
        load_kv(0, 0);
        asm volatile("cp.async.commit_group;" ::: "memory");
    }

    float mrow[2] = {-1e30f, -1e30f};
    float lrow[2] = {0.0f, 0.0f};
    float oacc[8][4];
    #pragma unroll
    for (int t = 0; t < 8; t++)
        #pragma unroll
        for (int c = 0; c < 4; c++) oacc[t][c] = 0.0f;

    const int nchunks = 2 * qb + 2;
    const int wrow_hi = qbase + 16 * wid + 15;

    for (int kc = 0; kc < nchunks; kc++) {
        const int kbase = kc * 64;
        const int s = kc & 1;
        if (kc + 1 < nchunks) {
            load_kv(kc + 1, s ^ 1);
            asm volatile("cp.async.commit_group;" ::: "memory");
            asm volatile("cp.async.wait_group 1;" ::: "memory");
        } else {
            asm volatile("cp.async.wait_group 0;" ::: "memory");
        }
        __syncthreads();

        if (wrow_hi >= kbase) {
            const uint32_t slot = sb + 32768 + s * 32768;
            const uint32_t tKh = slot, tKl = slot + 8192, tVh = slot + 16384, tVl = slot + 24576;

            uint32_t qh[4][4], ql[4][4];
            {
                int qr = 16 * wid + (lid & 15);
                int qc = (lid >> 4) * 16;
                #pragma unroll
                for (int ks = 0; ks < 4; ks++) {
                    uint32_t off = SWZ(qr * 128 + ks * 32 + qc);
                    ldsm_x4(qh[ks], sb + sQh + off);
                    ldsm_x4(ql[ks], sb + sQl + off);
                }
            }
            float sacc[8][4];
            #pragma unroll
            for (int t = 0; t < 8; t++)
                #pragma unroll
                for (int c = 0; c < 4; c++) sacc[t][c] = 0.0f;

            {
                int kr = lid & 7;
                int kcb = ((lid >> 3) & 1) * 16;
                #pragma unroll
                for (int t = 0; t < 8; t++) {
                    #pragma unroll
                    for (int ks = 0; ks < 4; ks++) {
                        uint32_t off = SWZ((t * 8 + kr) * 128 + ks * 32 + kcb);
                        uint32_t bh2[2], bl2[2];
                        ldsm_x2(bh2, tKh + off);
                        ldsm_x2(bl2, tKl + off);
                        mma_bf16_g(sacc[t], qh[ks], bh2);
                        mma_bf16_g(sacc[t], ql[ks], bh2);
                        mma_bf16_g(sacc[t], qh[ks], bl2);
                    }
                }
            }

            if (kc >= 2 * qb) {
                int row0 = qbase + 16 * wid + (lid >> 2);
                #pragma unroll
                for (int t = 0; t < 8; t++) {
                    int col = kbase + t * 8 + 2 * (lid & 3);
                    if (col > row0)     sacc[t][0] = -1e30f;
                    if (col + 1 > row0) sacc[t][1] = -1e30f;
                    if (col > row0 + 8)     sacc[t][2] = -1e30f;
                    if (col + 1 > row0 + 8) sacc[t][3] = -1e30f;
                }
            }

            #pragma unroll
            for (int rr = 0; rr < 2; rr++) {
                float mx = -1e30f;
                #pragma unroll
                for (int t = 0; t < 8; t++)
                    mx = fmaxf(mx, fmaxf(sacc[t][2 * rr], sacc[t][2 * rr + 1]));
                mx = fmaxf(mx, __shfl_xor_sync(0xffffffffu, mx, 1));
                mx = fmaxf(mx, __shfl_xor_sync(0xffffffffu, mx, 2));
                float mn = fmaxf(mrow[rr], mx);
                float sc = __expf(mrow[rr] - mn);
                mrow[rr] = mn;
                float rs = 0.0f;
                #pragma unroll
                for (int t = 0; t < 8; t++) {
                    float p0 = __expf(sacc[t][2 * rr] - mn);
                    float p1 = __expf(sacc[t][2 * rr + 1] - mn);
                    sacc[t][2 * rr] = p0; sacc[t][2 * rr + 1] = p1;
                    rs += p0 + p1;
                }
                lrow[rr] = lrow[rr] * sc + rs;
                #pragma unroll
                for (int t = 0; t < 8; t++) {
                    oacc[t][2 * rr]     *= sc;
                    oacc[t][2 * rr + 1] *= sc;
                }
            }

            {
                int vr = (lid & 7) + ((lid >> 3) & 1) * 8;
                #pragma unroll
                for (int j = 0; j < 4; j++) {
                    uint32_t ph[4], pl[4];
                    #pragma unroll
                    for (int half = 0; half < 2; half++) {
                        float a0 = sacc[2 * j + half][0], a1 = sacc[2 * j + half][1];
                        float a2 = sacc[2 * j + half][2], a3 = sacc[2 * j + half][3];
                        ph[0 + 2 * half] = pack_hi16(a0, a1);
                        ph[1 + 2 * half] = pack_hi16(a2, a3);
                        pl[0 + 2 * half] = pack_bf16x2(a0 - trunc_bf16f(a0), a1 - trunc_bf16f(a1));
                        pl[1 + 2 * half] = pack_bf16x2(a2 - trunc_bf16f(a2), a3 - trunc_bf16f(a3));
                    }
                    #pragma unroll
                    for (int t = 0; t < 8; t++) {
                        uint32_t voff = SWZ((j * 16 + vr) * 128 + t * 16);
                        uint32_t vh2[2], vl2[2];
                        ldsm_x2_trans(vh2, tVh + voff);
                        ldsm_x2_trans(vl2, tVl + voff);
                        mma_bf16_g(oacc[t], ph, vh2);
                        mma_bf16_g(oacc[t], pl, vh2);
                        mma_bf16_g(oacc[t], ph, vl2);
                    }
                }
            }
        }
        __syncthreads();
    }

    lrow[0] += __shfl_xor_sync(0xffffffffu, lrow[0], 1);
    lrow[0] += __shfl_xor_sync(0xffffffffu, lrow[0], 2);
    lrow[1] += __shfl_xor_sync(0xffffffffu, lrow[1], 1);
    lrow[1] += __shfl_xor_sync(0xffffffffu, lrow[1], 2);
    float inv0 = 0.03125f / lrow[0];
    float inv1 = 0.03125f / lrow[1];

    const size_t tok0 = (size_t)b * TSEQ;
    #pragma unroll
    for (int rr = 0; rr < 2; rr++) {
        float inv = rr ? inv1 : inv0;
        int row = qbase + 16 * wid + (lid >> 2) + rr * 8;
        size_t base = (tok0 + row) * (size_t)D + h * HD + 2 * (lid & 3);
        #pragma unroll
        for (int t = 0; t < 8; t++) {
            float v0 = oacc[t][2 * rr] * inv;
            float v1 = oacc[t][2 * rr + 1] * inv;
            __nv_bfloat16 h0, l0, h1, l1;
            split2(v0, h0, l0);
            split2(v1, h1, l1);
            *reinterpret_cast<__nv_bfloat162*>(&oh[base + t * 8]) = __halves2bfloat162(h0, h1);
            *reinterpret_cast<__nv_bfloat162*>(&ol[base + t * 8]) = __halves2bfloat162(l0, l1);
        }
    }
}

// ---------------------------------------------------------------------------
// Launch
// ---------------------------------------------------------------------------
extern "C" void kernel_launch(void* const* d_in, const int* in_sizes, int n_in,
                              void* d_out, int out_size) {
    const float* x      = (const float*)d_in[0];
    const float* w_attn = (const float*)d_in[1];
    const float* b_attn = (const float*)d_in[2];
    const float* w_proj = (const float*)d_in[3];
    const float* b_proj = (const float*)d_in[4];
    const float* w_fc1  = (const float*)d_in[5];
    const float* b_fc1  = (const float*)d_in[6];
    const float* w_fc2  = (const float*)d_in[7];
    const float* b_fc2  = (const float*)d_in[8];
    const float* g1     = (const float*)d_in[9];
    const float* g2     = (const float*)d_in[10];
    float* out = (float*)d_out;

    __nv_bfloat16 *ah, *al, *bh, *bl;
    __nv_bfloat16 *wAh, *wAl, *wPh, *wPl, *wF1h, *wF1l, *wF2h, *wF2l;
    __nv_bfloat16 *qh, *ql, *kh, *kl, *vh, *vl;
    cudaGetSymbolAddress((void**)&ah,   g_ah);
    cudaGetSymbolAddress((void**)&al,   g_al);
    cudaGetSymbolAddress((void**)&bh,   g_bh);
    cudaGetSymbolAddress((void**)&bl,   g_bl);
    cudaGetSymbolAddress((void**)&wAh,  g_wA_h);
    cudaGetSymbolAddress((void**)&wAl,  g_wA_l);
    cudaGetSymbolAddress((void**)&wPh,  g_wP_h);
    cudaGetSymbolAddress((void**)&wPl,  g_wP_l);
    cudaGetSymbolAddress((void**)&wF1h, g_wF1_h);
    cudaGetSymbolAddress((void**)&wF1l, g_wF1_l);
    cudaGetSymbolAddress((void**)&wF2h, g_wF2_h);
    cudaGetSymbolAddress((void**)&wF2l, g_wF2_l);
    cudaGetSymbolAddress((void**)&qh,   g_qh);
    cudaGetSymbolAddress((void**)&ql,   g_ql);
    cudaGetSymbolAddress((void**)&kh,   g_kh);
    cudaGetSymbolAddress((void**)&kl,   g_kl);
    cudaGetSymbolAddress((void**)&vh,   g_vh);
    cudaGetSymbolAddress((void**)&vl,   g_vl);

    cudaFuncSetAttribute(attn_mma_kernel, cudaFuncAttributeMaxDynamicSharedMemorySize, ATTN_SMEM);
    cudaFuncSetAttribute(tcgemm_kernel<EPI_BIAS>, cudaFuncAttributeMaxDynamicSharedMemorySize, TCG_SMEM);
    cudaFuncSetAttribute(tcgemm_kernel<EPI_GELU>, cudaFuncAttributeMaxDynamicSharedMemorySize, TCG_SMEM);
    cudaFuncSetAttribute(tcgemm_kernel<EPI_RES>,  cudaFuncAttributeMaxDynamicSharedMemorySize, TCG_SMEM);
    cudaFuncSetAttribute(tcgemm_kernel<EPI_QKV>,  cudaFuncAttributeMaxDynamicSharedMemorySize, TCG_SMEM);

    // 1. fused prep: rmsnorm1 + all 4 weight transposes
    prep_kernel<<<16384, 256>>>(x, g1, ah, al, w_attn, w_proj, w_fc1, w_fc2,
                                wAh, wAl, wPh, wPl, wF1h, wF1l, wF2h, wF2l);
    // 2. qkv gemm -> pre-split q/k/v per head
    tcgemm_kernel<EPI_QKV><<<dim3(D3 / 128, NTOK / 128), 256, TCG_SMEM>>>(
        ah, al, wAh, wAl, b_attn, nullptr, nullptr, nullptr, nullptr,
        qh, ql, kh, kl, vh, vl, NTOK, D3, D);
    // 3. attention -> ah/al
    attn_mma_kernel<<<dim3(TSEQ / 128, NH, NBATCH), 256, ATTN_SMEM>>>(
        qh, ql, kh, kl, vh, vl, ah, al);
    // 4. out = x + o @ w_proj + b_proj
    tcgemm_kernel<EPI_RES><<<dim3(D / 128, NTOK / 128), 256, TCG_SMEM>>>(
        ah, al, wPh, wPl, b_proj, x, out, nullptr, nullptr,
        nullptr, nullptr, nullptr, nullptr, nullptr, nullptr, NTOK, D, D);
    // 5. rmsnorm2
    rmsnorm_split_kernel<<<NTOK, 256>>>(out, g2, ah, al);
    // 6. bh/bl = gelu(h @ w_fc1 + b_fc1) split
    tcgemm_kernel<EPI_GELU><<<dim3(D4 / 128, NTOK / 128), 256, TCG_SMEM>>>(
        ah, al, wF1h, wF1l, b_fc1, nullptr, nullptr, bh, bl,
        nullptr, nullptr, nullptr, nullptr, nullptr, nullptr, NTOK, D4, D);
    // 7. out = out + act @ w_fc2 + b_fc2
    tcgemm_kernel<EPI_RES><<<dim3(D / 128, NTOK / 128), 256, TCG_SMEM>>>(
        bh, bl, wF2h, wF2l, b_fc2, out, out, nullptr, nullptr,
        nullptr, nullptr, nullptr, nullptr, nullptr, nullptr, NTOK, D, D4);
}

// round 12
// speedup vs baseline: 1.3591x; 1.2783x over previous
#include <cuda_runtime.h>
#include <cuda_bf16.h>
#include <cuda_fp16.h>
#include <math.h>
#include <cstdint>

#define D      1024
#define D3     3072
#define D4     4096
#define TSEQ   2048
#define NBATCH 2
#define NTOK   4096
#define NH     16
#define HD     64
#define EPS    1.1920929e-07f

// ---------------------------------------------------------------------------
// Scratch (device globals; no allocations allowed)
// ---------------------------------------------------------------------------
__device__ __half g_a[NTOK * D];        // activations, single fp16 (GEMM A side)
__device__ __half g_act[NTOK * D4];     // fc1 output, single fp16
// per-weight transposed split fp16 buffers [N,K]
__device__ __half g_wA_h[D * D3];
__device__ __half g_wA_l[D * D3];
__device__ __half g_wP_h[D * D];
__device__ __half g_wP_l[D * D];
__device__ __half g_wF1_h[D * D4];
__device__ __half g_wF1_l[D * D4];
__device__ __half g_wF2_h[D4 * D];
__device__ __half g_wF2_l[D4 * D];
// pre-split q/k/v for attention (bf16 3-pass path), layout [b, h, t, d]
__device__ __nv_bfloat16 g_qh[NTOK * D];
__device__ __nv_bfloat16 g_ql[NTOK * D];
__device__ __nv_bfloat16 g_kh[NTOK * D];
__device__ __nv_bfloat16 g_kl[NTOK * D];
__device__ __nv_bfloat16 g_vh[NTOK * D];
__device__ __nv_bfloat16 g_vl[NTOK * D];

// ---------------------------------------------------------------------------
// Helpers
// ---------------------------------------------------------------------------
__device__ __forceinline__ uint32_t smem_to_u32(const void* p) {
    uint32_t a;
    asm("{ .reg .u64 t; cvta.to.shared.u64 t, %1; cvt.u32.u64 %0, t; }" : "=r"(a) : "l"(p));
    return a;
}

#define SWZ(off) ((uint32_t)(off) ^ ((((uint32_t)(off) >> 7) & 7) << 4))

__device__ __forceinline__ void ldsm_x4(uint32_t* r, uint32_t addr) {
    asm volatile("ldmatrix.sync.aligned.m8n8.x4.shared.b16 {%0,%1,%2,%3}, [%4];"
                 : "=r"(r[0]), "=r"(r[1]), "=r"(r[2]), "=r"(r[3]) : "r"(addr));
}
__device__ __forceinline__ void ldsm_x2(uint32_t* r, uint32_t addr) {
    asm volatile("ldmatrix.sync.aligned.m8n8.x2.shared.b16 {%0,%1}, [%2];"
                 : "=r"(r[0]), "=r"(r[1]) : "r"(addr));
}
__device__ __forceinline__ void ldsm_x2_trans(uint32_t* r, uint32_t addr) {
    asm volatile("ldmatrix.sync.aligned.m8n8.x2.trans.shared.b16 {%0,%1}, [%2];"
                 : "=r"(r[0]), "=r"(r[1]) : "r"(addr));
}
// bf16 mma (attention path)
__device__ __forceinline__ void mma_bf16_g(float* d, const uint32_t* a, const uint32_t* b) {
    asm volatile(
        "mma.sync.aligned.m16n8k16.row.col.f32.bf16.bf16.f32 "
        "{%0,%1,%2,%3}, {%4,%5,%6,%7}, {%8,%9}, {%0,%1,%2,%3};"
        : "+f"(d[0]), "+f"(d[1]), "+f"(d[2]), "+f"(d[3])
        : "r"(a[0]), "r"(a[1]), "r"(a[2]), "r"(a[3]), "r"(b[0]), "r"(b[1]));
}
// fp16 mma (GEMM path)
__device__ __forceinline__ void mma_f16_g(float* d, const uint32_t* a, const uint32_t* b) {
    asm volatile(
        "mma.sync.aligned.m16n8k16.row.col.f32.f16.f16.f32 "
        "{%0,%1,%2,%3}, {%4,%5,%6,%7}, {%8,%9}, {%0,%1,%2,%3};"
        : "+f"(d[0]), "+f"(d[1]), "+f"(d[2]), "+f"(d[3])
        : "r"(a[0]), "r"(a[1]), "r"(a[2]), "r"(a[3]), "r"(b[0]), "r"(b[1]));
}

__device__ __forceinline__ void split2(float v, __nv_bfloat16& h, __nv_bfloat16& l) {
    h = __float2bfloat16(v);
    l = __float2bfloat16(v - __bfloat162float(h));
}
__device__ __forceinline__ void split2h(float v, __half& h, __half& l) {
    h = __float2half_rn(v);
    l = __float2half_rn(v - __half2float(h));
}
__device__ __forceinline__ uint32_t pack_bf16x2(float a, float b) {
    uint32_t r;
    asm("cvt.rn.bf16x2.f32 %0, %1, %2;" : "=r"(r) : "f"(b), "f"(a));
    return r;
}
__device__ __forceinline__ uint32_t pack_hi16(float a, float b) {
    uint32_t r;
    asm("prmt.b32 %0, %1, %2, 0x7632;" : "=r"(r) : "r"(__float_as_uint(a)), "r"(__float_as_uint(b)));
    return r;
}
__device__ __forceinline__ float trunc_bf16f(float v) {
    return __uint_as_float(__float_as_uint(v) & 0xFFFF0000u);
}

// ---------------------------------------------------------------------------
// Fused prep kernel: rmsnorm(x,g1) (fp16 single out) + 4 weight transposes
// (fp16 hi/lo out), one launch.
// ---------------------------------------------------------------------------
__device__ __forceinline__ void do_transpose(const float* __restrict__ W, int K, int N,
                                             __half* __restrict__ Th,
                                             __half* __restrict__ Tl,
                                             int tile, float* tbuf /* [32][33] */) {
    int tiles_n = N >> 5;
    int k0 = (tile / tiles_n) << 5;
    int n0 = (tile % tiles_n) << 5;
    int x = threadIdx.x & 31, y = threadIdx.x >> 5;   // 32 x 8
    #pragma unroll
    for (int i = y; i < 32; i += 8)
        tbuf[i * 33 + x] = W[(size_t)(k0 + i) * N + n0 + x];
    __syncthreads();
    #pragma unroll
    for (int b = y; b < 32; b += 8) {
        float v = tbuf[x * 33 + b];
        __half h, l;
        split2h(v, h, l);
        size_t o = (size_t)(n0 + b) * K + k0 + x;
        Th[o] = h;
        Tl[o] = l;
    }
}

__global__ void prep_kernel(const float* __restrict__ x, const float* __restrict__ g1,
                            __half* __restrict__ oa,
                            const float* __restrict__ wA, const float* __restrict__ wP,
                            const float* __restrict__ wF1, const float* __restrict__ wF2,
                            __half* wAh, __half* wAl,
                            __half* wPh, __half* wPl,
                            __half* wF1h, __half* wF1l,
                            __half* wF2h, __half* wF2l) {
    __shared__ float tbuf[32 * 33];
    int bid = blockIdx.x;
    if (bid < NTOK) {
        int row = bid;
        const float4* xr = reinterpret_cast<const float4*>(x + (size_t)row * D);
        float4 v = xr[threadIdx.x];
        float s = v.x * v.x + v.y * v.y + v.z * v.z + v.w * v.w;
        #pragma unroll
        for (int o = 16; o > 0; o >>= 1) s += __shfl_xor_sync(0xffffffffu, s, o);
        __shared__ float ws[8];
        if ((threadIdx.x & 31) == 0) ws[threadIdx.x >> 5] = s;
        __syncthreads();
        float tot = ws[0] + ws[1] + ws[2] + ws[3] + ws[4] + ws[5] + ws[6] + ws[7];
        float inv = rsqrtf(tot * (1.0f / (float)D) + EPS);
        float4 gv = reinterpret_cast<const float4*>(g1)[threadIdx.x];
        size_t off = (size_t)row * D + threadIdx.x * 4;
        *reinterpret_cast<__half2*>(&oa[off])     = __floats2half2_rn(v.x * inv * gv.x, v.y * inv * gv.y);
        *reinterpret_cast<__half2*>(&oa[off + 2]) = __floats2half2_rn(v.z * inv * gv.z, v.w * inv * gv.w);
    } else if (bid < NTOK + 3072) {
        do_transpose(wA, D, D3, wAh, wAl, bid - NTOK, tbuf);
    } else if (bid < NTOK + 3072 + 1024) {
        do_transpose(wP, D, D, wPh, wPl, bid - NTOK - 3072, tbuf);
    } else if (bid < NTOK + 3072 + 1024 + 4096) {
        do_transpose(wF1, D, D4, wF1h, wF1l, bid - NTOK - 3072 - 1024, tbuf);
    } else {
        do_transpose(wF2, D4, D, wF2h, wF2l, bid - NTOK - 3072 - 1024 - 4096, tbuf);
    }
}

// ---------------------------------------------------------------------------
// rmsnorm (standalone, for norm2) -> fp16 single
// ---------------------------------------------------------------------------
__global__ void rmsnorm_h_kernel(const float* __restrict__ x,
                                 const float* __restrict__ g,
                                 __half* __restrict__ oa) {
    int row = blockIdx.x;
    const float4* xr = reinterpret_cast<const float4*>(x + (size_t)row * D);
    float4 v = xr[threadIdx.x];
    float s = v.x * v.x + v.y * v.y + v.z * v.z + v.w * v.w;
    #pragma unroll
    for (int o = 16; o > 0; o >>= 1) s += __shfl_xor_sync(0xffffffffu, s, o);
    __shared__ float ws[8];
    if ((threadIdx.x & 31) == 0) ws[threadIdx.x >> 5] = s;
    __syncthreads();
    float tot = ws[0] + ws[1] + ws[2] + ws[3] + ws[4] + ws[5] + ws[6] + ws[7];
    float inv = rsqrtf(tot * (1.0f / (float)D) + EPS);
    float4 gv = reinterpret_cast<const float4*>(g)[threadIdx.x];
    size_t off = (size_t)row * D + threadIdx.x * 4;
    *reinterpret_cast<__half2*>(&oa[off])     = __floats2half2_rn(v.x * inv * gv.x, v.y * inv * gv.y);
    *reinterpret_cast<__half2*>(&oa[off + 2]) = __floats2half2_rn(v.z * inv * gv.z, v.w * inv * gv.w);
}

// ---------------------------------------------------------------------------
// fp16 2-pass GEMM: C = A @ (Bh+Bl)^T + bias (+ epilogue)
// A: [M,K] fp16 single. B: [N,K] fp16 hi/lo. 128x128, BK=64, 3-stage,
// single-barrier pipeline (wait -> barrier -> issue load(c+2) -> compute).
// ---------------------------------------------------------------------------
#define EPI_BIAS 0
#define EPI_GELU 1
#define EPI_RES  2
#define EPI_QKV  3

#define STAGE_BYTES 49152     // A 16K | Bh 16K | Bl 16K
#define TCG_SMEM (3 * STAGE_BYTES)

template <int EPI>
__global__ __launch_bounds__(256, 1)
void tcgemm_kernel(const __half* __restrict__ A,
                   const __half* __restrict__ Bh, const __half* __restrict__ Bl,
                   const float* __restrict__ bias, const float* __restrict__ R,
                   float* __restrict__ C,
                   __half* __restrict__ Oa,
                   __nv_bfloat16* __restrict__ Qh, __nv_bfloat16* __restrict__ Ql,
                   __nv_bfloat16* __restrict__ Kh, __nv_bfloat16* __restrict__ Kl,
                   __nv_bfloat16* __restrict__ Vh, __nv_bfloat16* __restrict__ Vl,
                   int M, int N, int K) {
    extern __shared__ __align__(1024) char smem[];
    uint32_t sbase = smem_to_u32(smem);
    const int tid = threadIdx.x;
    const int wid = tid >> 5, lid = tid & 31;
    const int wm = wid >> 2, wn = wid & 3;
    const int bm = blockIdx.y * 128, bn = blockIdx.x * 128;

    const __half* srcs[3] = {A, Bh, Bl};

    auto load_chunk = [&](int c, int s) {
        uint32_t tb = sbase + s * STAGE_BYTES;
        #pragma unroll
        for (int t3 = 0; t3 < 3; t3++) {
            const __half* src = srcs[t3];
            int rbase = (t3 == 0) ? bm : bn;
            uint32_t dst0 = tb + t3 * 16384;
            #pragma unroll
            for (int i = 0; i < 4; i++) {
                int u = tid + i * 256;
                int r = u >> 3, j = u & 7;
                uint32_t d = dst0 + SWZ(r * 128 + j * 16);
                const void* g = src + (size_t)(rbase + r) * K + c * 64 + j * 8;
                asm volatile("cp.async.cg.shared.global [%0], [%1], 16;"
                             :: "r"(d), "l"(g) : "memory");
            }
        }
        asm volatile("cp.async.commit_group;" ::: "memory");
    };

    float acc[4][4][4];
    #pragma unroll
    for (int im = 0; im < 4; im++)
        #pragma unroll
        for (int in = 0; in < 4; in++)
            #pragma unroll
            for (int q = 0; q < 4; q++) acc[im][in][q] = 0.0f;

    const int nchunks = K >> 6;
    load_chunk(0, 0);
    load_chunk(1, 1);

    const int arow = wm * 64 + (lid & 15);
    const int acol = (lid >> 4) * 16;
    const int brow = wn * 32 + (lid & 7);
    const int bcol = ((lid >> 3) & 1) * 16;

    for (int c = 0; c < nchunks; c++) {
        if (c + 1 < nchunks) {
            asm volatile("cp.async.wait_group 1;" ::: "memory");
        } else {
            asm volatile("cp.async.wait_group 0;" ::: "memory");
        }
        __syncthreads();
        if (c + 2 < nchunks)
            load_chunk(c + 2, (c + 2) % 3);

        int s = c % 3;
        uint32_t tb = sbase + s * STAGE_BYTES;
        uint32_t tA = tb, tBh = tb + 16384, tBl = tb + 32768;

        #pragma unroll
        for (int ks = 0; ks < 4; ks++) {
            uint32_t a4[4][4], bh[4][2], bl[4][2];
            #pragma unroll
            for (int im = 0; im < 4; im++) {
                uint32_t off = SWZ((arow + im * 16) * 128 + ks * 32 + acol);
                ldsm_x4(a4[im], tA + off);
            }
            #pragma unroll
            for (int in = 0; in < 4; in++) {
                uint32_t off = SWZ((brow + in * 8) * 128 + ks * 32 + bcol);
                ldsm_x2(bh[in], tBh + off);
            }
            #pragma unroll
            for (int im = 0; im < 4; im++)
                #pragma unroll
                for (int in = 0; in < 4; in++)
                    mma_f16_g(acc[im][in], a4[im], bh[in]);
            #pragma unroll
            for (int in = 0; in < 4; in++) {
                uint32_t off = SWZ((brow + in * 8) * 128 + ks * 32 + bcol);
                ldsm_x2(bl[in], tBl + off);
            }
            #pragma unroll
            for (int im = 0; im < 4; im++)
                #pragma unroll
                for (int in = 0; in < 4; in++)
                    mma_f16_g(acc[im][in], a4[im], bl[in]);
        }
    }

    #pragma unroll
    for (int im = 0; im < 4; im++) {
        #pragma unroll
        for (int in = 0; in < 4; in++) {
            int m0 = bm + wm * 64 + im * 16 + (lid >> 2);
            int n0 = bn + wn * 32 + in * 8 + (lid & 3) * 2;
            float b0 = bias[n0], b1 = bias[n0 + 1];
            #pragma unroll
            for (int half = 0; half < 2; half++) {
                int m = m0 + half * 8;
                float v0 = acc[im][in][half * 2]     + b0;
                float v1 = acc[im][in][half * 2 + 1] + b1;
                if (EPI == EPI_QKV) {
                    int part = n0 >> 10;
                    int head = (n0 >> 6) & 15;
                    int d = n0 & 63;
                    int bb = m >> 11, t = m & 2047;
                    size_t dst = ((size_t)(bb * NH + head) * TSEQ + t) * HD + d;
                    __nv_bfloat16 h0, l0, h1, l1;
                    split2(v0, h0, l0);
                    split2(v1, h1, l1);
                    __nv_bfloat16* dh = (part == 0) ? Qh : (part == 1) ? Kh : Vh;
                    __nv_bfloat16* dl = (part == 0) ? Ql : (part == 1) ? Kl : Vl;
                    *reinterpret_cast<__nv_bfloat162*>(&dh[dst]) = __halves2bfloat162(h0, h1);
                    *reinterpret_cast<__nv_bfloat162*>(&dl[dst]) = __halves2bfloat162(l0, l1);
                } else if (EPI == EPI_GELU) {
                    size_t off = (size_t)m * N + n0;
                    float g0 = 0.5f * v0 * (1.0f + erff(v0 * 0.70710678118654752f));
                    float g1 = 0.5f * v1 * (1.0f + erff(v1 * 0.70710678118654752f));
                    *reinterpret_cast<__half2*>(&Oa[off]) = __floats2half2_rn(g0, g1);
                } else {
                    size_t off = (size_t)m * N + n0;
                    if (EPI == EPI_RES) {
                        float2 rr = *reinterpret_cast<const float2*>(&R[off]);
                        v0 += rr.x; v1 += rr.y;
                    }
                    float2 o2 = make_float2(v0, v1);
                    *reinterpret_cast<float2*>(&C[off]) = o2;
                }
            }
        }
    }
}

// ---------------------------------------------------------------------------
// Tensor-core flash attention (bf16 3-pass, heavy-first).
// Output written as fp16 single into the GEMM-A buffer.
// ---------------------------------------------------------------------------
#define ATTN_SMEM 98304

__global__ __launch_bounds__(256, 1)
void attn_mma_kernel(const __nv_bfloat16* __restrict__ Qh, const __nv_bfloat16* __restrict__ Ql,
                     const __nv_bfloat16* __restrict__ Kh, const __nv_bfloat16* __restrict__ Kl,
                     const __nv_bfloat16* __restrict__ Vh, const __nv_bfloat16* __restrict__ Vl,
                     __half* __restrict__ oa) {
    extern __shared__ __align__(1024) char smem_raw[];
    uint32_t sb = smem_to_u32(smem_raw);
    const uint32_t sQh = 0, sQl = 16384;

    const int tid = threadIdx.x;
    const int wid = tid >> 5, lid = tid & 31;
    const int qb = gridDim.x - 1 - blockIdx.x;
    const int h = blockIdx.y, b = blockIdx.z;
    const int qbase = qb * 128;
    const size_t hdbase = (size_t)(b * NH + h) * TSEQ * HD;

    const __nv_bfloat16* kvsrc[4] = {Kh + hdbase, Kl + hdbase, Vh + hdbase, Vl + hdbase};

    auto load_kv = [&](int c, int s) {
        uint32_t slot = sb + 32768 + s * 32768;
        int rowbase = c * 64;
        #pragma unroll
        for (int i = 0; i < 8; i++) {
            int u = tid + i * 256;
            int t4 = u >> 9;
            int c2 = u & 511;
            int r = c2 >> 3, j = c2 & 7;
            uint32_t d = slot + t4 * 8192 + SWZ(r * 128 + j * 16);
            const void* g = kvsrc[t4] + (size_t)(rowbase + r) * HD + j * 8;
            asm volatile("cp.async.cg.shared.global [%0], [%1], 16;"
                         :: "r"(d), "l"(g) : "memory");
        }
    };

    {
        const __nv_bfloat16* qhp = Qh + hdbase + (size_t)qbase * HD;
        const __nv_bfloat16* qlp = Ql + hdbase + (size_t)qbase * HD;
        #pragma unroll
        for (int i = 0; i < 4; i++) {
            int u = tid + i * 256;
            int r = u >> 3, j = u & 7;
            uint32_t o = SWZ(r * 128 + j * 16);
            asm volatile("cp.async.cg.shared.global [%0], [%1], 16;"
                         :: "r"(sb + sQh + o), "l"((const void*)(qhp + (size_t)r * HD + j * 8)) : "memory");
            asm volatile("cp.async.cg.shared.global [%0], [%1], 16;"
                         :: "r"(sb + sQl + o), "l"((const void*)(qlp + (size_t)r * HD + j * 8)) : "memory");
        }
        load_kv(0, 0);
        asm volatile("cp.async.commit_group;" ::: "memory");
    }

    float mrow[2] = {-1e30f, -1e30f};
    float lrow[2] = {0.0f, 0.0f};
    float oacc[8][4];
    #pragma unroll
    for (int t = 0; t < 8; t++)
        #pragma unroll
        for (int c = 0; c < 4; c++) oacc[t][c] = 0.0f;

    const int nchunks = 2 * qb + 2;
    const int wrow_hi = qbase + 16 * wid + 15;

    for (int kc = 0; kc < nchunks; kc++) {
        const int kbase = kc * 64;
        const int s = kc & 1;
        if (kc + 1 < nchunks) {
            load_kv(kc + 1, s ^ 1);
            asm volatile("cp.async.commit_group;" ::: "memory");
            asm volatile("cp.async.wait_group 1;" ::: "memory");
        } else {
            asm volatile("cp.async.wait_group 0;" ::: "memory");
        }
        __syncthreads();

        if (wrow_hi >= kbase) {
            const uint32_t slot = sb + 32768 + s * 32768;
            const uint32_t tKh = slot, tKl = slot + 8192, tVh = slot + 16384, tVl = slot + 24576;

            uint32_t qh[4][4], ql[4][4];
            {
                int qr = 16 * wid + (lid & 15);
                int qc = (lid >> 4) * 16;
                #pragma unroll
                for (int ks = 0; ks < 4; ks++) {
                    uint32_t off = SWZ(qr * 128 + ks * 32 + qc);
                    ldsm_x4(qh[ks], sb + sQh + off);
                    ldsm_x4(ql[ks], sb + sQl + off);
                }
            }
            float sacc[8][4];
            #pragma unroll
            for (int t = 0; t < 8; t++)
                #pragma unroll
                for (int c = 0; c < 4; c++) sacc[t][c] = 0.0f;

            {
                int kr = lid & 7;
                int kcb = ((lid >> 3) & 1) * 16;
                #pragma unroll
                for (int t = 0; t < 8; t++) {
                    #pragma unroll
                    for (int ks = 0; ks < 4; ks++) {
                        uint32_t off = SWZ((t * 8 + kr) * 128 + ks * 32 + kcb);
                        uint32_t bh2[2], bl2[2];
                        ldsm_x2(bh2, tKh + off);
                        ldsm_x2(bl2, tKl + off);
                        mma_bf16_g(sacc[t], qh[ks], bh2);
                        mma_bf16_g(sacc[t], ql[ks], bh2);
                        mma_bf16_g(sacc[t], qh[ks], bl2);
                    }
                }
            }

            if (kc >= 2 * qb) {
                int row0 = qbase + 16 * wid + (lid >> 2);
                #pragma unroll
                for (int t = 0; t < 8; t++) {
                    int col = kbase + t * 8 + 2 * (lid & 3);
                    if (col > row0)     sacc[t][0] = -1e30f;
                    if (col + 1 > row0) sacc[t][1] = -1e30f;
                    if (col > row0 + 8)     sacc[t][2] = -1e30f;
                    if (col + 1 > row0 + 8) sacc[t][3] = -1e30f;
                }
            }

            #pragma unroll
            for (int rr = 0; rr < 2; rr++) {
                float mx = -1e30f;
                #pragma unroll
                for (int t = 0; t < 8; t++)
                    mx = fmaxf(mx, fmaxf(sacc[t][2 * rr], sacc[t][2 * rr + 1]));
                mx = fmaxf(mx, __shfl_xor_sync(0xffffffffu, mx, 1));
                mx = fmaxf(mx, __shfl_xor_sync(0xffffffffu, mx, 2));
                float mn = fmaxf(mrow[rr], mx);
                float sc = __expf(mrow[rr] - mn);
                mrow[rr] = mn;
                float rs = 0.0f;
                #pragma unroll
                for (int t = 0; t < 8; t++) {
                    float p0 = __expf(sacc[t][2 * rr] - mn);
                    float p1 = __expf(sacc[t][2 * rr + 1] - mn);
                    sacc[t][2 * rr] = p0; sacc[t][2 * rr + 1] = p1;
                    rs += p0 + p1;
                }
                lrow[rr] = lrow[rr] * sc + rs;
                #pragma unroll
                for (int t = 0; t < 8; t++) {
                    oacc[t][2 * rr]     *= sc;
                    oacc[t][2 * rr + 1] *= sc;
                }
            }

            {
                int vr = (lid & 7) + ((lid >> 3) & 1) * 8;
                #pragma unroll
                for (int j = 0; j < 4; j++) {
                    uint32_t ph[4], pl[4];
                    #pragma unroll
                    for (int half = 0; half < 2; half++) {
                        float a0 = sacc[2 * j + half][0], a1 = sacc[2 * j + half][1];
                        float a2 = sacc[2 * j + half][2], a3 = sacc[2 * j + half][3];
                        ph[0 + 2 * half] = pack_hi16(a0, a1);
                        ph[1 + 2 * half] = pack_hi16(a2, a3);
                        pl[0 + 2 * half] = pack_bf16x2(a0 - trunc_bf16f(a0), a1 - trunc_bf16f(a1));
                        pl[1 + 2 * half] = pack_bf16x2(a2 - trunc_bf16f(a2), a3 - trunc_bf16f(a3));
                    }
                    #pragma unroll
                    for (int t = 0; t < 8; t++) {
                        uint32_t voff = SWZ((j * 16 + vr) * 128 + t * 16);
                        uint32_t vh2[2], vl2[2];
                        ldsm_x2_trans(vh2, tVh + voff);
                        ldsm_x2_trans(vl2, tVl + voff);
                        mma_bf16_g(oacc[t], ph, vh2);
                        mma_bf16_g(oacc[t], pl, vh2);
                        mma_bf16_g(oacc[t], ph, vl2);
                    }
                }
            }
        }
        __syncthreads();
    }

    lrow[0] += __shfl_xor_sync(0xffffffffu, lrow[0], 1);
    lrow[0] += __shfl_xor_sync(0xffffffffu, lrow[0], 2);
    lrow[1] += __shfl_xor_sync(0xffffffffu, lrow[1], 1);
    lrow[1] += __shfl_xor_sync(0xffffffffu, lrow[1], 2);
    float inv0 = 0.03125f / lrow[0];
    float inv1 = 0.03125f / lrow[1];

    const size_t tok0 = (size_t)b * TSEQ;
    #pragma unroll
    for (int rr = 0; rr < 2; rr++) {
        float inv = rr ? inv1 : inv0;
        int row = qbase + 16 * wid + (lid >> 2) + rr * 8;
        size_t base = (tok0 + row) * (size_t)D + h * HD + 2 * (lid & 3);
        #pragma unroll
        for (int t = 0; t < 8; t++) {
            float v0 = oacc[t][2 * rr] * inv;
            float v1 = oacc[t][2 * rr + 1] * inv;
            *reinterpret_cast<__half2*>(&oa[base + t * 8]) = __floats2half2_rn(v0, v1);
        }
    }
}

// ---------------------------------------------------------------------------
// Launch
// ---------------------------------------------------------------------------
extern "C" void kernel_launch(void* const* d_in, const int* in_sizes, int n_in,
                              void* d_out, int out_size) {
    const float* x      = (const float*)d_in[0];
    const float* w_attn = (const float*)d_in[1];
    const float* b_attn = (const float*)d_in[2];
    const float* w_proj = (const float*)d_in[3];
    const float* b_proj = (const float*)d_in[4];
    const float* w_fc1  = (const float*)d_in[5];
    const float* b_fc1  = (const float*)d_in[6];
    const float* w_fc2  = (const float*)d_in[7];
    const float* b_fc2  = (const float*)d_in[8];
    const float* g1     = (const float*)d_in[9];
    const float* g2     = (const float*)d_in[10];
    float* out = (float*)d_out;

    __half *a, *act;
    __half *wAh, *wAl, *wPh, *wPl, *wF1h, *wF1l, *wF2h, *wF2l;
    __nv_bfloat16 *qh, *ql, *kh, *kl, *vh, *vl;
    cudaGetSymbolAddress((void**)&a,    g_a);
    cudaGetSymbolAddress((void**)&act,  g_act);
    cudaGetSymbolAddress((void**)&wAh,  g_wA_h);
    cudaGetSymbolAddress((void**)&wAl,  g_wA_l);
    cudaGetSymbolAddress((void**)&wPh,  g_wP_h);
    cudaGetSymbolAddress((void**)&wPl,  g_wP_l);
    cudaGetSymbolAddress((void**)&wF1h, g_wF1_h);
    cudaGetSymbolAddress((void**)&wF1l, g_wF1_l);
    cudaGetSymbolAddress((void**)&wF2h, g_wF2_h);
    cudaGetSymbolAddress((void**)&wF2l, g_wF2_l);
    cudaGetSymbolAddress((void**)&qh,   g_qh);
    cudaGetSymbolAddress((void**)&ql,   g_ql);
    cudaGetSymbolAddress((void**)&kh,   g_kh);
    cudaGetSymbolAddress((void**)&kl,   g_kl);
    cudaGetSymbolAddress((void**)&vh,   g_vh);
    cudaGetSymbolAddress((void**)&vl,   g_vl);

    cudaFuncSetAttribute(attn_mma_kernel, cudaFuncAttributeMaxDynamicSharedMemorySize, ATTN_SMEM);
    cudaFuncSetAttribute(tcgemm_kernel<EPI_BIAS>, cudaFuncAttributeMaxDynamicSharedMemorySize, TCG_SMEM);
    cudaFuncSetAttribute(tcgemm_kernel<EPI_GELU>, cudaFuncAttributeMaxDynamicSharedMemorySize, TCG_SMEM);
    cudaFuncSetAttribute(tcgemm_kernel<EPI_RES>,  cudaFuncAttributeMaxDynamicSharedMemorySize, TCG_SMEM);
    cudaFuncSetAttribute(tcgemm_kernel<EPI_QKV>,  cudaFuncAttributeMaxDynamicSharedMemorySize, TCG_SMEM);

    // 1. fused prep: rmsnorm1 (fp16) + 4 weight transposes (fp16 hi/lo)
    prep_kernel<<<16384, 256>>>(x, g1, a, w_attn, w_proj, w_fc1, w_fc2,
                                wAh, wAl, wPh, wPl, wF1h, wF1l, wF2h, wF2l);
    // 2. qkv gemm -> bf16-split q/k/v per head
    tcgemm_kernel<EPI_QKV><<<dim3(D3 / 128, NTOK / 128), 256, TCG_SMEM>>>(
        a, wAh, wAl, b_attn, nullptr, nullptr, nullptr,
        qh, ql, kh, kl, vh, vl, NTOK, D3, D);
    // 3. attention -> fp16 single into a
    attn_mma_kernel<<<dim3(TSEQ / 128, NH, NBATCH), 256, ATTN_SMEM>>>(
        qh, ql, kh, kl, vh, vl, a);
    // 4. out = x + o @ w_proj + b_proj
    tcgemm_kernel<EPI_RES><<<dim3(D / 128, NTOK / 128), 256, TCG_SMEM>>>(
        a, wPh, wPl, b_proj, x, out, nullptr,
        nullptr, nullptr, nullptr, nullptr, nullptr, nullptr, NTOK, D, D);
    // 5. rmsnorm2 -> fp16 single
    rmsnorm_h_kernel<<<NTOK, 256>>>(out, g2, a);
    // 6. act = gelu(h @ w_fc1 + b_fc1) -> fp16 single
    tcgemm_kernel<EPI_GELU><<<dim3(D4 / 128, NTOK / 128), 256, TCG_SMEM>>>(
        a, wF1h, wF1l, b_fc1, nullptr, nullptr, act,
        nullptr, nullptr, nullptr, nullptr, nullptr, nullptr, NTOK, D4, D);
    // 7. out = out + act @ w_fc2 + b_fc2
    tcgemm_kernel<EPI_RES><<<dim3(D / 128, NTOK / 128), 256, TCG_SMEM>>>(
        act, wF2h, wF2l, b_fc2, out, out, nullptr,
        nullptr, nullptr, nullptr, nullptr, nullptr, nullptr, NTOK, D, D4);
}

// round 13
// speedup vs baseline: 2.1750x; 1.6003x over previous
#include <cuda_runtime.h>
#include <cuda_bf16.h>
#include <cuda_fp16.h>
#include <math.h>
#include <cstdint>

#define D      1024
#define D3     3072
#define D4     4096
#define TSEQ   2048
#define NBATCH 2
#define NTOK   4096
#define NH     16
#define HD     64
#define EPS    1.1920929e-07f

// ---------------------------------------------------------------------------
// Scratch (device globals; no allocations allowed)
// ---------------------------------------------------------------------------
__device__ __half g_a[NTOK * D];        // activations fp16 (GEMM A side)
__device__ __half g_act[NTOK * D4];     // fc1 output fp16
// transposed weights, single fp16 [N,K]
__device__ __half g_wA[D * D3];
__device__ __half g_wP[D * D];
__device__ __half g_wF1[D * D4];
__device__ __half g_wF2[D4 * D];
// q/k/v single fp16, layout [b, h, t, d]
__device__ __half g_q[NTOK * D];
__device__ __half g_k[NTOK * D];
__device__ __half g_v[NTOK * D];

// ---------------------------------------------------------------------------
// Helpers
// ---------------------------------------------------------------------------
__device__ __forceinline__ uint32_t smem_to_u32(const void* p) {
    uint32_t a;
    asm("{ .reg .u64 t; cvta.to.shared.u64 t, %1; cvt.u32.u64 %0, t; }" : "=r"(a) : "l"(p));
    return a;
}

#define SWZ(off) ((uint32_t)(off) ^ ((((uint32_t)(off) >> 7) & 7) << 4))

__device__ __forceinline__ void ldsm_x4(uint32_t* r, uint32_t addr) {
    asm volatile("ldmatrix.sync.aligned.m8n8.x4.shared.b16 {%0,%1,%2,%3}, [%4];"
                 : "=r"(r[0]), "=r"(r[1]), "=r"(r[2]), "=r"(r[3]) : "r"(addr));
}
__device__ __forceinline__ void ldsm_x2(uint32_t* r, uint32_t addr) {
    asm volatile("ldmatrix.sync.aligned.m8n8.x2.shared.b16 {%0,%1}, [%2];"
                 : "=r"(r[0]), "=r"(r[1]) : "r"(addr));
}
__device__ __forceinline__ void ldsm_x2_trans(uint32_t* r, uint32_t addr) {
    asm volatile("ldmatrix.sync.aligned.m8n8.x2.trans.shared.b16 {%0,%1}, [%2];"
                 : "=r"(r[0]), "=r"(r[1]) : "r"(addr));
}
__device__ __forceinline__ void mma_f16_g(float* d, const uint32_t* a, const uint32_t* b) {
    asm volatile(
        "mma.sync.aligned.m16n8k16.row.col.f32.f16.f16.f32 "
        "{%0,%1,%2,%3}, {%4,%5,%6,%7}, {%8,%9}, {%0,%1,%2,%3};"
        : "+f"(d[0]), "+f"(d[1]), "+f"(d[2]), "+f"(d[3])
        : "r"(a[0]), "r"(a[1]), "r"(a[2]), "r"(a[3]), "r"(b[0]), "r"(b[1]));
}

// pack two fp32 -> fp16x2 (lo = a, hi = b)
__device__ __forceinline__ uint32_t pack_f16x2(float a, float b) {
    uint32_t r;
    asm("cvt.rn.f16x2.f32 %0, %1, %2;" : "=r"(r) : "f"(b), "f"(a));
    return r;
}

// ---------------------------------------------------------------------------
// Fused prep kernel: rmsnorm(x,g1) -> fp16 + 4 weight transposes -> fp16.
// Block ranges: [0,4096) rmsnorm | [4096,7168) wA | [7168,8192) wP
//               [8192,12288) wF1 | [12288,16384) wF2
// ---------------------------------------------------------------------------
__device__ __forceinline__ void do_transpose(const float* __restrict__ W, int K, int N,
                                             __half* __restrict__ T,
                                             int tile, float* tbuf /* [32][33] */) {
    int tiles_n = N >> 5;
    int k0 = (tile / tiles_n) << 5;
    int n0 = (tile % tiles_n) << 5;
    int x = threadIdx.x & 31, y = threadIdx.x >> 5;   // 32 x 8
    #pragma unroll
    for (int i = y; i < 32; i += 8)
        tbuf[i * 33 + x] = W[(size_t)(k0 + i) * N + n0 + x];
    __syncthreads();
    #pragma unroll
    for (int b = y; b < 32; b += 8) {
        T[(size_t)(n0 + b) * K + k0 + x] = __float2half_rn(tbuf[x * 33 + b]);
    }
}

__global__ void prep_kernel(const float* __restrict__ x, const float* __restrict__ g1,
                            __half* __restrict__ oa,
                            const float* __restrict__ wA, const float* __restrict__ wP,
                            const float* __restrict__ wF1, const float* __restrict__ wF2,
                            __half* tA, __half* tP, __half* tF1, __half* tF2) {
    __shared__ float tbuf[32 * 33];
    int bid = blockIdx.x;
    if (bid < NTOK) {
        int row = bid;
        const float4* xr = reinterpret_cast<const float4*>(x + (size_t)row * D);
        float4 v = xr[threadIdx.x];
        float s = v.x * v.x + v.y * v.y + v.z * v.z + v.w * v.w;
        #pragma unroll
        for (int o = 16; o > 0; o >>= 1) s += __shfl_xor_sync(0xffffffffu, s, o);
        __shared__ float ws[8];
        if ((threadIdx.x & 31) == 0) ws[threadIdx.x >> 5] = s;
        __syncthreads();
        float tot = ws[0] + ws[1] + ws[2] + ws[3] + ws[4] + ws[5] + ws[6] + ws[7];
        float inv = rsqrtf(tot * (1.0f / (float)D) + EPS);
        float4 gv = reinterpret_cast<const float4*>(g1)[threadIdx.x];
        size_t off = (size_t)row * D + threadIdx.x * 4;
        *reinterpret_cast<__half2*>(&oa[off])     = __floats2half2_rn(v.x * inv * gv.x, v.y * inv * gv.y);
        *reinterpret_cast<__half2*>(&oa[off + 2]) = __floats2half2_rn(v.z * inv * gv.z, v.w * inv * gv.w);
    } else if (bid < NTOK + 3072) {
        do_transpose(wA, D, D3, tA, bid - NTOK, tbuf);
    } else if (bid < NTOK + 3072 + 1024) {
        do_transpose(wP, D, D, tP, bid - NTOK - 3072, tbuf);
    } else if (bid < NTOK + 3072 + 1024 + 4096) {
        do_transpose(wF1, D, D4, tF1, bid - NTOK - 3072 - 1024, tbuf);
    } else {
        do_transpose(wF2, D4, D, tF2, bid - NTOK - 3072 - 1024 - 4096, tbuf);
    }
}

// ---------------------------------------------------------------------------
// rmsnorm (standalone, for norm2) -> fp16
// ---------------------------------------------------------------------------
__global__ void rmsnorm_h_kernel(const float* __restrict__ x,
                                 const float* __restrict__ g,
                                 __half* __restrict__ oa) {
    int row = blockIdx.x;
    const float4* xr = reinterpret_cast<const float4*>(x + (size_t)row * D);
    float4 v = xr[threadIdx.x];
    float s = v.x * v.x + v.y * v.y + v.z * v.z + v.w * v.w;
    #pragma unroll
    for (int o = 16; o > 0; o >>= 1) s += __shfl_xor_sync(0xffffffffu, s, o);
    __shared__ float ws[8];
    if ((threadIdx.x & 31) == 0) ws[threadIdx.x >> 5] = s;
    __syncthreads();
    float tot = ws[0] + ws[1] + ws[2] + ws[3] + ws[4] + ws[5] + ws[6] + ws[7];
    float inv = rsqrtf(tot * (1.0f / (float)D) + EPS);
    float4 gv = reinterpret_cast<const float4*>(g)[threadIdx.x];
    size_t off = (size_t)row * D + threadIdx.x * 4;
    *reinterpret_cast<__half2*>(&oa[off])     = __floats2half2_rn(v.x * inv * gv.x, v.y * inv * gv.y);
    *reinterpret_cast<__half2*>(&oa[off + 2]) = __floats2half2_rn(v.z * inv * gv.z, v.w * inv * gv.w);
}

// ---------------------------------------------------------------------------
// Single-fp16 1-pass GEMM: C = A @ B^T + bias (+ epilogue)
// A: [M,K] fp16. B: [N,K] fp16. 128x128, BK=64, 3-stage single-barrier.
// ---------------------------------------------------------------------------
#define EPI_BIAS 0
#define EPI_GELU 1
#define EPI_RES  2
#define EPI_QKV  3

#define STAGE_BYTES 32768     // A 16K | B 16K
#define TCG_SMEM (3 * STAGE_BYTES)

template <int EPI>
__global__ __launch_bounds__(256, 1)
void tcgemm_kernel(const __half* __restrict__ A, const __half* __restrict__ B,
                   const float* __restrict__ bias, const float* __restrict__ R,
                   float* __restrict__ C,
                   __half* __restrict__ Oa,
                   __half* __restrict__ Qp, __half* __restrict__ Kp, __half* __restrict__ Vp,
                   int M, int N, int K) {
    extern __shared__ __align__(1024) char smem[];
    uint32_t sbase = smem_to_u32(smem);
    const int tid = threadIdx.x;
    const int wid = tid >> 5, lid = tid & 31;
    const int wm = wid >> 2, wn = wid & 3;
    const int bm = blockIdx.y * 128, bn = blockIdx.x * 128;

    auto load_chunk = [&](int c, int s) {
        uint32_t tb = sbase + s * STAGE_BYTES;
        #pragma unroll
        for (int t2 = 0; t2 < 2; t2++) {
            const __half* src = t2 ? B : A;
            int rbase = t2 ? bn : bm;
            uint32_t dst0 = tb + t2 * 16384;
            #pragma unroll
            for (int i = 0; i < 4; i++) {
                int u = tid + i * 256;
                int r = u >> 3, j = u & 7;
                uint32_t d = dst0 + SWZ(r * 128 + j * 16);
                const void* g = src + (size_t)(rbase + r) * K + c * 64 + j * 8;
                asm volatile("cp.async.cg.shared.global [%0], [%1], 16;"
                             :: "r"(d), "l"(g) : "memory");
            }
        }
        asm volatile("cp.async.commit_group;" ::: "memory");
    };

    float acc[4][4][4];
    #pragma unroll
    for (int im = 0; im < 4; im++)
        #pragma unroll
        for (int in = 0; in < 4; in++)
            #pragma unroll
            for (int q = 0; q < 4; q++) acc[im][in][q] = 0.0f;

    const int nchunks = K >> 6;
    load_chunk(0, 0);
    load_chunk(1, 1);

    const int arow = wm * 64 + (lid & 15);
    const int acol = (lid >> 4) * 16;
    const int brow = wn * 32 + (lid & 7);
    const int bcol = ((lid >> 3) & 1) * 16;

    for (int c = 0; c < nchunks; c++) {
        if (c + 1 < nchunks) {
            asm volatile("cp.async.wait_group 1;" ::: "memory");
        } else {
            asm volatile("cp.async.wait_group 0;" ::: "memory");
        }
        __syncthreads();
        if (c + 2 < nchunks)
            load_chunk(c + 2, (c + 2) % 3);

        int s = c % 3;
        uint32_t tb = sbase + s * STAGE_BYTES;
        uint32_t tA = tb, tB = tb + 16384;

        #pragma unroll
        for (int ks = 0; ks < 4; ks++) {
            uint32_t a4[4][4], b2[4][2];
            #pragma unroll
            for (int im = 0; im < 4; im++) {
                uint32_t off = SWZ((arow + im * 16) * 128 + ks * 32 + acol);
                ldsm_x4(a4[im], tA + off);
            }
            #pragma unroll
            for (int in = 0; in < 4; in++) {
                uint32_t off = SWZ((brow + in * 8) * 128 + ks * 32 + bcol);
                ldsm_x2(b2[in], tB + off);
            }
            #pragma unroll
            for (int im = 0; im < 4; im++)
                #pragma unroll
                for (int in = 0; in < 4; in++)
                    mma_f16_g(acc[im][in], a4[im], b2[in]);
        }
    }

    #pragma unroll
    for (int im = 0; im < 4; im++) {
        #pragma unroll
        for (int in = 0; in < 4; in++) {
            int m0 = bm + wm * 64 + im * 16 + (lid >> 2);
            int n0 = bn + wn * 32 + in * 8 + (lid & 3) * 2;
            float b0 = bias[n0], b1 = bias[n0 + 1];
            #pragma unroll
            for (int half = 0; half < 2; half++) {
                int m = m0 + half * 8;
                float v0 = acc[im][in][half * 2]     + b0;
                float v1 = acc[im][in][half * 2 + 1] + b1;
                if (EPI == EPI_QKV) {
                    int part = n0 >> 10;
                    int head = (n0 >> 6) & 15;
                    int d = n0 & 63;
                    int bb = m >> 11, t = m & 2047;
                    size_t dst = ((size_t)(bb * NH + head) * TSEQ + t) * HD + d;
                    __half* dp = (part == 0) ? Qp : (part == 1) ? Kp : Vp;
                    *reinterpret_cast<__half2*>(&dp[dst]) = __floats2half2_rn(v0, v1);
                } else if (EPI == EPI_GELU) {
                    size_t off = (size_t)m * N + n0;
                    float g0 = 0.5f * v0 * (1.0f + erff(v0 * 0.70710678118654752f));
                    float g1 = 0.5f * v1 * (1.0f + erff(v1 * 0.70710678118654752f));
                    *reinterpret_cast<__half2*>(&Oa[off]) = __floats2half2_rn(g0, g1);
                } else {
                    size_t off = (size_t)m * N + n0;
                    if (EPI == EPI_RES) {
                        float2 rr = *reinterpret_cast<const float2*>(&R[off]);
                        v0 += rr.x; v1 += rr.y;
                    }
                    float2 o2 = make_float2(v0, v1);
                    *reinterpret_cast<float2*>(&C[off]) = o2;
                }
            }
        }
    }
}

// ---------------------------------------------------------------------------
// Single-fp16 flash attention: 1-pass QK^T, 1-pass PV. Heavy-first.
// smem: Q 16K | slot0 {K 8K, V 8K} | slot1 {K,V} = 48K
// ---------------------------------------------------------------------------
#define ATTN_SMEM 49152

__global__ __launch_bounds__(256, 1)
void attn_mma_kernel(const __half* __restrict__ Qp, const __half* __restrict__ Kp,
                     const __half* __restrict__ Vp, __half* __restrict__ oa) {
    extern __shared__ __align__(1024) char smem_raw[];
    uint32_t sb = smem_to_u32(smem_raw);
    const uint32_t sQ = 0;

    const int tid = threadIdx.x;
    const int wid = tid >> 5, lid = tid & 31;
    const int qb = gridDim.x - 1 - blockIdx.x;   // heavy CTAs first
    const int h = blockIdx.y, b = blockIdx.z;
    const int qbase = qb * 128;
    const size_t hdbase = (size_t)(b * NH + h) * TSEQ * HD;

    const __half* kvsrc[2] = {Kp + hdbase, Vp + hdbase};

    auto load_kv = [&](int c, int s) {
        uint32_t slot = sb + 16384 + s * 16384;
        int rowbase = c * 64;
        #pragma unroll
        for (int i = 0; i < 4; i++) {
            int u = tid + i * 256;              // 0..1023
            int t2 = u >> 9;
            int c2 = u & 511;
            int r = c2 >> 3, j = c2 & 7;
            uint32_t d = slot + t2 * 8192 + SWZ(r * 128 + j * 16);
            const void* g = kvsrc[t2] + (size_t)(rowbase + r) * HD + j * 8;
            asm volatile("cp.async.cg.shared.global [%0], [%1], 16;"
                         :: "r"(d), "l"(g) : "memory");
        }
    };

    {
        const __half* qp = Qp + hdbase + (size_t)qbase * HD;
        #pragma unroll
        for (int i = 0; i < 4; i++) {
            int u = tid + i * 256;              // 0..1023 (128 rows x 8 chunks)
            int r = u >> 3, j = u & 7;
            uint32_t o = SWZ(r * 128 + j * 16);
            asm volatile("cp.async.cg.shared.global [%0], [%1], 16;"
                         :: "r"(sb + sQ + o), "l"((const void*)(qp + (size_t)r * HD + j * 8)) : "memory");
        }
        load_kv(0, 0);
        asm volatile("cp.async.commit_group;" ::: "memory");
    }

    float mrow[2] = {-1e30f, -1e30f};
    float lrow[2] = {0.0f, 0.0f};
    float oacc[8][4];
    #pragma unroll
    for (int t = 0; t < 8; t++)
        #pragma unroll
        for (int c = 0; c < 4; c++) oacc[t][c] = 0.0f;

    const int nchunks = 2 * qb + 2;
    const int wrow_hi = qbase + 16 * wid + 15;

    for (int kc = 0; kc < nchunks; kc++) {
        const int kbase = kc * 64;
        const int s = kc & 1;
        if (kc + 1 < nchunks) {
            load_kv(kc + 1, s ^ 1);
            asm volatile("cp.async.commit_group;" ::: "memory");
            asm volatile("cp.async.wait_group 1;" ::: "memory");
        } else {
            asm volatile("cp.async.wait_group 0;" ::: "memory");
        }
        __syncthreads();

        if (wrow_hi >= kbase) {
            const uint32_t slot = sb + 16384 + s * 16384;
            const uint32_t tK = slot, tV = slot + 8192;

            // ---- S = Q K^T (1 pass) ----
            uint32_t qf[4][4];
            {
                int qr = 16 * wid + (lid & 15);
                int qc = (lid >> 4) * 16;
                #pragma unroll
                for (int ks = 0; ks < 4; ks++) {
                    uint32_t off = SWZ(qr * 128 + ks * 32 + qc);
                    ldsm_x4(qf[ks], sb + sQ + off);
                }
            }
            float sacc[8][4];
            #pragma unroll
            for (int t = 0; t < 8; t++)
                #pragma unroll
                for (int c = 0; c < 4; c++) sacc[t][c] = 0.0f;

            {
                int kr = lid & 7;
                int kcb = ((lid >> 3) & 1) * 16;
                #pragma unroll
                for (int t = 0; t < 8; t++) {
                    #pragma unroll
                    for (int ks = 0; ks < 4; ks++) {
                        uint32_t off = SWZ((t * 8 + kr) * 128 + ks * 32 + kcb);
                        uint32_t kf[2];
                        ldsm_x2(kf, tK + off);
                        mma_f16_g(sacc[t], qf[ks], kf);
                    }
                }
            }

            // ---- causal mask (diagonal chunks only) ----
            if (kc >= 2 * qb) {
                int row0 = qbase + 16 * wid + (lid >> 2);
                #pragma unroll
                for (int t = 0; t < 8; t++) {
                    int col = kbase + t * 8 + 2 * (lid & 3);
                    if (col > row0)     sacc[t][0] = -1e30f;
                    if (col + 1 > row0) sacc[t][1] = -1e30f;
                    if (col > row0 + 8)     sacc[t][2] = -1e30f;
                    if (col + 1 > row0 + 8) sacc[t][3] = -1e30f;
                }
            }

            // ---- online softmax ----
            #pragma unroll
            for (int rr = 0; rr < 2; rr++) {
                float mx = -1e30f;
                #pragma unroll
                for (int t = 0; t < 8; t++)
                    mx = fmaxf(mx, fmaxf(sacc[t][2 * rr], sacc[t][2 * rr + 1]));
                mx = fmaxf(mx, __shfl_xor_sync(0xffffffffu, mx, 1));
                mx = fmaxf(mx, __shfl_xor_sync(0xffffffffu, mx, 2));
                float mn = fmaxf(mrow[rr], mx);
                float sc = __expf(mrow[rr] - mn);
                mrow[rr] = mn;
                float rs = 0.0f;
                #pragma unroll
                for (int t = 0; t < 8; t++) {
                    float p0 = __expf(sacc[t][2 * rr] - mn);
                    float p1 = __expf(sacc[t][2 * rr + 1] - mn);
                    sacc[t][2 * rr] = p0; sacc[t][2 * rr + 1] = p1;
                    rs += p0 + p1;
                }
                lrow[rr] = lrow[rr] * sc + rs;
                #pragma unroll
                for (int t = 0; t < 8; t++) {
                    oacc[t][2 * rr]     *= sc;
                    oacc[t][2 * rr + 1] *= sc;
                }
            }

            // ---- O += P V (1 pass; P packed fp16) ----
            {
                int vr = (lid & 7) + ((lid >> 3) & 1) * 8;
                #pragma unroll
                for (int j = 0; j < 4; j++) {
                    uint32_t pf[4];
                    #pragma unroll
                    for (int half = 0; half < 2; half++) {
                        float a0 = sacc[2 * j + half][0], a1 = sacc[2 * j + half][1];
                        float a2 = sacc[2 * j + half][2], a3 = sacc[2 * j + half][3];
                        pf[0 + 2 * half] = pack_f16x2(a0, a1);
                        pf[1 + 2 * half] = pack_f16x2(a2, a3);
                    }
                    #pragma unroll
                    for (int t = 0; t < 8; t++) {
                        uint32_t voff = SWZ((j * 16 + vr) * 128 + t * 16);
                        uint32_t vf[2];
                        ldsm_x2_trans(vf, tV + voff);
                        mma_f16_g(oacc[t], pf, vf);
                    }
                }
            }
        }
        __syncthreads();
    }

    lrow[0] += __shfl_xor_sync(0xffffffffu, lrow[0], 1);
    lrow[0] += __shfl_xor_sync(0xffffffffu, lrow[0], 2);
    lrow[1] += __shfl_xor_sync(0xffffffffu, lrow[1], 1);
    lrow[1] += __shfl_xor_sync(0xffffffffu, lrow[1], 2);
    float inv0 = 0.03125f / lrow[0];
    float inv1 = 0.03125f / lrow[1];

    const size_t tok0 = (size_t)b * TSEQ;
    #pragma unroll
    for (int rr = 0; rr < 2; rr++) {
        float inv = rr ? inv1 : inv0;
        int row = qbase + 16 * wid + (lid >> 2) + rr * 8;
        size_t base = (tok0 + row) * (size_t)D + h * HD + 2 * (lid & 3);
        #pragma unroll
        for (int t = 0; t < 8; t++) {
            float v0 = oacc[t][2 * rr] * inv;
            float v1 = oacc[t][2 * rr + 1] * inv;
            *reinterpret_cast<__half2*>(&oa[base + t * 8]) = __floats2half2_rn(v0, v1);
        }
    }
}

// ---------------------------------------------------------------------------
// Launch
// ---------------------------------------------------------------------------
extern "C" void kernel_launch(void* const* d_in, const int* in_sizes, int n_in,
                              void* d_out, int out_size) {
    const float* x      = (const float*)d_in[0];
    const float* w_attn = (const float*)d_in[1];
    const float* b_attn = (const float*)d_in[2];
    const float* w_proj = (const float*)d_in[3];
    const float* b_proj = (const float*)d_in[4];
    const float* w_fc1  = (const float*)d_in[5];
    const float* b_fc1  = (const float*)d_in[6];
    const float* w_fc2  = (const float*)d_in[7];
    const float* b_fc2  = (const float*)d_in[8];
    const float* g1     = (const float*)d_in[9];
    const float* g2     = (const float*)d_in[10];
    float* out = (float*)d_out;

    __half *a, *act, *tA, *tP, *tF1, *tF2, *qp, *kp, *vp;
    cudaGetSymbolAddress((void**)&a,   g_a);
    cudaGetSymbolAddress((void**)&act, g_act);
    cudaGetSymbolAddress((void**)&tA,  g_wA);
    cudaGetSymbolAddress((void**)&tP,  g_wP);
    cudaGetSymbolAddress((void**)&tF1, g_wF1);
    cudaGetSymbolAddress((void**)&tF2, g_wF2);
    cudaGetSymbolAddress((void**)&qp,  g_q);
    cudaGetSymbolAddress((void**)&kp,  g_k);
    cudaGetSymbolAddress((void**)&vp,  g_v);

    cudaFuncSetAttribute(attn_mma_kernel, cudaFuncAttributeMaxDynamicSharedMemorySize, ATTN_SMEM);
    cudaFuncSetAttribute(tcgemm_kernel<EPI_BIAS>, cudaFuncAttributeMaxDynamicSharedMemorySize, TCG_SMEM);
    cudaFuncSetAttribute(tcgemm_kernel<EPI_GELU>, cudaFuncAttributeMaxDynamicSharedMemorySize, TCG_SMEM);
    cudaFuncSetAttribute(tcgemm_kernel<EPI_RES>,  cudaFuncAttributeMaxDynamicSharedMemorySize, TCG_SMEM);
    cudaFuncSetAttribute(tcgemm_kernel<EPI_QKV>,  cudaFuncAttributeMaxDynamicSharedMemorySize, TCG_SMEM);

    // 1. fused prep: rmsnorm1 + 4 weight transposes (all fp16)
    prep_kernel<<<16384, 256>>>(x, g1, a, w_attn, w_proj, w_fc1, w_fc2,
                                tA, tP, tF1, tF2);
    // 2. qkv gemm -> fp16 q/k/v per head
    tcgemm_kernel<EPI_QKV><<<dim3(D3 / 128, NTOK / 128), 256, TCG_SMEM>>>(
        a, tA, b_attn, nullptr, nullptr, nullptr, qp, kp, vp, NTOK, D3, D);
    // 3. attention -> fp16 into a
    attn_mma_kernel<<<dim3(TSEQ / 128, NH, NBATCH), 256, ATTN_SMEM>>>(qp, kp, vp, a);
    // 4. out = x + o @ w_proj + b_proj
    tcgemm_kernel<EPI_RES><<<dim3(D / 128, NTOK / 128), 256, TCG_SMEM>>>(
        a, tP, b_proj, x, out, nullptr, nullptr, nullptr, nullptr, NTOK, D, D);
    // 5. rmsnorm2 -> fp16
    rmsnorm_h_kernel<<<NTOK, 256>>>(out, g2, a);
    // 6. act = gelu(h @ w_fc1 + b_fc1) -> fp16
    tcgemm_kernel<EPI_GELU><<<dim3(D4 / 128, NTOK / 128), 256, TCG_SMEM>>>(
        a, tF1, b_fc1, nullptr, nullptr, act, nullptr, nullptr, nullptr, NTOK, D4, D);
    // 7. out = out + act @ w_fc2 + b_fc2
    tcgemm_kernel<EPI_RES><<<dim3(D / 128, NTOK / 128), 256, TCG_SMEM>>>(
        act, tF2, b_fc2, out, out, nullptr, nullptr, nullptr, nullptr, NTOK, D, D4);
}

// round 14
// speedup vs baseline: 2.2417x; 1.0307x over previous
#include <cuda_runtime.h>
#include <cuda_fp16.h>
#include <math.h>
#include <cstdint>

#define D      1024
#define D3     3072
#define D4     4096
#define TSEQ   2048
#define NBATCH 2
#define NTOK   4096
#define NH     16
#define HD     64
#define EPS    1.1920929e-07f

// ---------------------------------------------------------------------------
// Scratch (device globals; no allocations allowed)
// ---------------------------------------------------------------------------
__device__ __half g_a[NTOK * D];        // activations fp16 (GEMM A side)
__device__ __half g_act[NTOK * D4];     // fc1 output fp16
__device__ __half g_qkv[NTOK * D3];     // qkv contiguous fp16 [t, 3d]
// transposed weights fp16 [N,K]
__device__ __half g_wA[D * D3];
__device__ __half g_wP[D * D];
__device__ __half g_wF1[D * D4];
__device__ __half g_wF2[D4 * D];

// ---------------------------------------------------------------------------
// Helpers
// ---------------------------------------------------------------------------
__device__ __forceinline__ uint32_t smem_to_u32(const void* p) {
    uint32_t a;
    asm("{ .reg .u64 t; cvta.to.shared.u64 t, %1; cvt.u32.u64 %0, t; }" : "=r"(a) : "l"(p));
    return a;
}

#define SWZ(off) ((uint32_t)(off) ^ ((((uint32_t)(off) >> 7) & 7) << 4))

__device__ __forceinline__ void ldsm_x4(uint32_t* r, uint32_t addr) {
    asm volatile("ldmatrix.sync.aligned.m8n8.x4.shared.b16 {%0,%1,%2,%3}, [%4];"
                 : "=r"(r[0]), "=r"(r[1]), "=r"(r[2]), "=r"(r[3]) : "r"(addr));
}
__device__ __forceinline__ void ldsm_x2(uint32_t* r, uint32_t addr) {
    asm volatile("ldmatrix.sync.aligned.m8n8.x2.shared.b16 {%0,%1}, [%2];"
                 : "=r"(r[0]), "=r"(r[1]) : "r"(addr));
}
__device__ __forceinline__ void ldsm_x2_trans(uint32_t* r, uint32_t addr) {
    asm volatile("ldmatrix.sync.aligned.m8n8.x2.trans.shared.b16 {%0,%1}, [%2];"
                 : "=r"(r[0]), "=r"(r[1]) : "r"(addr));
}
__device__ __forceinline__ void mma_f16_g(float* d, const uint32_t* a, const uint32_t* b) {
    asm volatile(
        "mma.sync.aligned.m16n8k16.row.col.f32.f16.f16.f32 "
        "{%0,%1,%2,%3}, {%4,%5,%6,%7}, {%8,%9}, {%0,%1,%2,%3};"
        : "+f"(d[0]), "+f"(d[1]), "+f"(d[2]), "+f"(d[3])
        : "r"(a[0]), "r"(a[1]), "r"(a[2]), "r"(a[3]), "r"(b[0]), "r"(b[1]));
}
__device__ __forceinline__ uint32_t pack_f16x2(float a, float b) {
    uint32_t r;
    asm("cvt.rn.f16x2.f32 %0, %1, %2;" : "=r"(r) : "f"(b), "f"(a));
    return r;
}

// ---------------------------------------------------------------------------
// Fused prep kernel: rmsnorm(x,g1) -> fp16 + 4 weight transposes -> fp16.
// ---------------------------------------------------------------------------
__device__ __forceinline__ void do_transpose(const float* __restrict__ W, int K, int N,
                                             __half* __restrict__ T,
                                             int tile, float* tbuf /* [32][33] */) {
    int tiles_n = N >> 5;
    int k0 = (tile / tiles_n) << 5;
    int n0 = (tile % tiles_n) << 5;
    int x = threadIdx.x & 31, y = threadIdx.x >> 5;
    #pragma unroll
    for (int i = y; i < 32; i += 8)
        tbuf[i * 33 + x] = W[(size_t)(k0 + i) * N + n0 + x];
    __syncthreads();
    #pragma unroll
    for (int b = y; b < 32; b += 8)
        T[(size_t)(n0 + b) * K + k0 + x] = __float2half_rn(tbuf[x * 33 + b]);
}

__global__ void prep_kernel(const float* __restrict__ x, const float* __restrict__ g1,
                            __half* __restrict__ oa,
                            const float* __restrict__ wA, const float* __restrict__ wP,
                            const float* __restrict__ wF1, const float* __restrict__ wF2,
                            __half* tA, __half* tP, __half* tF1, __half* tF2) {
    __shared__ float tbuf[32 * 33];
    int bid = blockIdx.x;
    if (bid < NTOK) {
        int row = bid;
        const float4* xr = reinterpret_cast<const float4*>(x + (size_t)row * D);
        float4 v = xr[threadIdx.x];
        float s = v.x * v.x + v.y * v.y + v.z * v.z + v.w * v.w;
        #pragma unroll
        for (int o = 16; o > 0; o >>= 1) s += __shfl_xor_sync(0xffffffffu, s, o);
        __shared__ float ws[8];
        if ((threadIdx.x & 31) == 0) ws[threadIdx.x >> 5] = s;
        __syncthreads();
        float tot = ws[0] + ws[1] + ws[2] + ws[3] + ws[4] + ws[5] + ws[6] + ws[7];
        float inv = rsqrtf(tot * (1.0f / (float)D) + EPS);
        float4 gv = reinterpret_cast<const float4*>(g1)[threadIdx.x];
        size_t off = (size_t)row * D + threadIdx.x * 4;
        *reinterpret_cast<__half2*>(&oa[off])     = __floats2half2_rn(v.x * inv * gv.x, v.y * inv * gv.y);
        *reinterpret_cast<__half2*>(&oa[off + 2]) = __floats2half2_rn(v.z * inv * gv.z, v.w * inv * gv.w);
    } else if (bid < NTOK + 3072) {
        do_transpose(wA, D, D3, tA, bid - NTOK, tbuf);
    } else if (bid < NTOK + 3072 + 1024) {
        do_transpose(wP, D, D, tP, bid - NTOK - 3072, tbuf);
    } else if (bid < NTOK + 3072 + 1024 + 4096) {
        do_transpose(wF1, D, D4, tF1, bid - NTOK - 3072 - 1024, tbuf);
    } else {
        do_transpose(wF2, D4, D, tF2, bid - NTOK - 3072 - 1024 - 4096, tbuf);
    }
}

// ---------------------------------------------------------------------------
// rmsnorm (standalone, for norm2) -> fp16
// ---------------------------------------------------------------------------
__global__ void rmsnorm_h_kernel(const float* __restrict__ x,
                                 const float* __restrict__ g,
                                 __half* __restrict__ oa) {
    int row = blockIdx.x;
    const float4* xr = reinterpret_cast<const float4*>(x + (size_t)row * D);
    float4 v = xr[threadIdx.x];
    float s = v.x * v.x + v.y * v.y + v.z * v.z + v.w * v.w;
    #pragma unroll
    for (int o = 16; o > 0; o >>= 1) s += __shfl_xor_sync(0xffffffffu, s, o);
    __shared__ float ws[8];
    if ((threadIdx.x & 31) == 0) ws[threadIdx.x >> 5] = s;
    __syncthreads();
    float tot = ws[0] + ws[1] + ws[2] + ws[3] + ws[4] + ws[5] + ws[6] + ws[7];
    float inv = rsqrtf(tot * (1.0f / (float)D) + EPS);
    float4 gv = reinterpret_cast<const float4*>(g)[threadIdx.x];
    size_t off = (size_t)row * D + threadIdx.x * 4;
    *reinterpret_cast<__half2*>(&oa[off])     = __floats2half2_rn(v.x * inv * gv.x, v.y * inv * gv.y);
    *reinterpret_cast<__half2*>(&oa[off + 2]) = __floats2half2_rn(v.z * inv * gv.z, v.w * inv * gv.w);
}

// ---------------------------------------------------------------------------
// Single-fp16 1-pass GEMM: C = A @ B^T + bias (+ epilogue)
// 128x128, BK=64, 4-stage single-barrier pipeline.
// EPI_HBIAS: fp16 out with bias (qkv path, coalesced).
// ---------------------------------------------------------------------------
#define EPI_HBIAS 0
#define EPI_GELU  1
#define EPI_RES   2

#define STAGE_BYTES 32768     // A 16K | B 16K
#define TCG_SMEM (4 * STAGE_BYTES)

template <int EPI>
__global__ __launch_bounds__(256, 1)
void tcgemm_kernel(const __half* __restrict__ A, const __half* __restrict__ B,
                   const float* __restrict__ bias, const float* __restrict__ R,
                   float* __restrict__ C, __half* __restrict__ Oa,
                   int M, int N, int K) {
    extern __shared__ __align__(1024) char smem[];
    uint32_t sbase = smem_to_u32(smem);
    const int tid = threadIdx.x;
    const int wid = tid >> 5, lid = tid & 31;
    const int wm = wid >> 2, wn = wid & 3;
    const int bm = blockIdx.y * 128, bn = blockIdx.x * 128;

    auto load_chunk = [&](int c, int s) {
        uint32_t tb = sbase + s * STAGE_BYTES;
        #pragma unroll
        for (int t2 = 0; t2 < 2; t2++) {
            const __half* src = t2 ? B : A;
            int rbase = t2 ? bn : bm;
            uint32_t dst0 = tb + t2 * 16384;
            #pragma unroll
            for (int i = 0; i < 4; i++) {
                int u = tid + i * 256;
                int r = u >> 3, j = u & 7;
                uint32_t d = dst0 + SWZ(r * 128 + j * 16);
                const void* g = src + (size_t)(rbase + r) * K + c * 64 + j * 8;
                asm volatile("cp.async.cg.shared.global [%0], [%1], 16;"
                             :: "r"(d), "l"(g) : "memory");
            }
        }
        asm volatile("cp.async.commit_group;" ::: "memory");
    };

    float acc[4][4][4];
    #pragma unroll
    for (int im = 0; im < 4; im++)
        #pragma unroll
        for (int in = 0; in < 4; in++)
            #pragma unroll
            for (int q = 0; q < 4; q++) acc[im][in][q] = 0.0f;

    const int nchunks = K >> 6;
    load_chunk(0, 0);
    load_chunk(1, 1);
    if (nchunks > 2) load_chunk(2, 2);

    const int arow = wm * 64 + (lid & 15);
    const int acol = (lid >> 4) * 16;
    const int brow = wn * 32 + (lid & 7);
    const int bcol = ((lid >> 3) & 1) * 16;

    for (int c = 0; c < nchunks; c++) {
        // chunks loaded so far: up to min(c+2, nchunks-1). wait until chunk c done.
        int pend = nchunks - 1 - c;
        if (pend >= 2)      { asm volatile("cp.async.wait_group 2;" ::: "memory"); }
        else if (pend == 1) { asm volatile("cp.async.wait_group 1;" ::: "memory"); }
        else                { asm volatile("cp.async.wait_group 0;" ::: "memory"); }
        __syncthreads();           // all warps done with compute c-1
        if (c + 3 < nchunks)
            load_chunk(c + 3, (c + 3) & 3);   // reuses slot (c-1)&3 — safe now

        int s = c & 3;
        uint32_t tb = sbase + s * STAGE_BYTES;
        uint32_t tA = tb, tB = tb + 16384;

        #pragma unroll
        for (int ks = 0; ks < 4; ks++) {
            uint32_t a4[4][4], b2[4][2];
            #pragma unroll
            for (int im = 0; im < 4; im++) {
                uint32_t off = SWZ((arow + im * 16) * 128 + ks * 32 + acol);
                ldsm_x4(a4[im], tA + off);
            }
            #pragma unroll
            for (int in = 0; in < 4; in++) {
                uint32_t off = SWZ((brow + in * 8) * 128 + ks * 32 + bcol);
                ldsm_x2(b2[in], tB + off);
            }
            #pragma unroll
            for (int im = 0; im < 4; im++)
                #pragma unroll
                for (int in = 0; in < 4; in++)
                    mma_f16_g(acc[im][in], a4[im], b2[in]);
        }
    }

    #pragma unroll
    for (int im = 0; im < 4; im++) {
        #pragma unroll
        for (int in = 0; in < 4; in++) {
            int m0 = bm + wm * 64 + im * 16 + (lid >> 2);
            int n0 = bn + wn * 32 + in * 8 + (lid & 3) * 2;
            float b0 = bias[n0], b1 = bias[n0 + 1];
            #pragma unroll
            for (int half = 0; half < 2; half++) {
                int m = m0 + half * 8;
                float v0 = acc[im][in][half * 2]     + b0;
                float v1 = acc[im][in][half * 2 + 1] + b1;
                size_t off = (size_t)m * N + n0;
                if (EPI == EPI_HBIAS) {
                    *reinterpret_cast<__half2*>(&Oa[off]) = __floats2half2_rn(v0, v1);
                } else if (EPI == EPI_GELU) {
                    float g0 = 0.5f * v0 * (1.0f + erff(v0 * 0.70710678118654752f));
                    float g1 = 0.5f * v1 * (1.0f + erff(v1 * 0.70710678118654752f));
                    *reinterpret_cast<__half2*>(&Oa[off]) = __floats2half2_rn(g0, g1);
                } else {
                    float2 rr = *reinterpret_cast<const float2*>(&R[off]);
                    v0 += rr.x; v1 += rr.y;
                    float2 o2 = make_float2(v0, v1);
                    *reinterpret_cast<float2*>(&C[off]) = o2;
                }
            }
        }
    }
}

// ---------------------------------------------------------------------------
// Single-fp16 flash attention, K/V chunks of 128 rows, heavy-first.
// qkv input is contiguous [t, 3d] fp16: q at h*64, k at D+h*64, v at 2D+h*64.
// smem: Q 16K | slot0 {K 16K, V 16K} | slot1 = 80KB
// ---------------------------------------------------------------------------
#define ATTN_SMEM (16384 + 2 * 32768)

__global__ __launch_bounds__(256, 1)
void attn_mma_kernel(const __half* __restrict__ qkv, __half* __restrict__ oa) {
    extern __shared__ __align__(1024) char smem_raw[];
    uint32_t sb = smem_to_u32(smem_raw);
    const uint32_t sQ = 0;

    const int tid = threadIdx.x;
    const int wid = tid >> 5, lid = tid & 31;
    const int qb = gridDim.x - 1 - blockIdx.x;   // heavy CTAs first
    const int h = blockIdx.y, b = blockIdx.z;
    const int qbase = qb * 128;
    const size_t tok0 = (size_t)b * TSEQ;

    // K/V loader: chunk c = token rows [c*128, (c+1)*128)
    auto load_kv = [&](int c, int s) {
        uint32_t slot = sb + 16384 + s * 32768;
        int rowbase = c * 128;
        #pragma unroll
        for (int i = 0; i < 8; i++) {
            int u = tid + i * 256;              // 0..2047
            int t2 = u >> 10;                   // 0=K 1=V
            int c2 = u & 1023;
            int r = c2 >> 3, j = c2 & 7;
            uint32_t d = slot + t2 * 16384 + SWZ(r * 128 + j * 16);
            const void* g = qkv + (tok0 + rowbase + r) * D3 + (t2 + 1) * D + h * HD + j * 8;
            asm volatile("cp.async.cg.shared.global [%0], [%1], 16;"
                         :: "r"(d), "l"(g) : "memory");
        }
    };

    {
        #pragma unroll
        for (int i = 0; i < 4; i++) {
            int u = tid + i * 256;              // 0..1023: 128 rows x 8 chunks
            int r = u >> 3, j = u & 7;
            uint32_t o = SWZ(r * 128 + j * 16);
            const void* g = qkv + (tok0 + qbase + r) * D3 + h * HD + j * 8;
            asm volatile("cp.async.cg.shared.global [%0], [%1], 16;"
                         :: "r"(sb + sQ + o), "l"(g) : "memory");
        }
        load_kv(0, 0);
        asm volatile("cp.async.commit_group;" ::: "memory");
    }

    float mrow[2] = {-1e30f, -1e30f};
    float lrow[2] = {0.0f, 0.0f};
    float oacc[8][4];
    #pragma unroll
    for (int t = 0; t < 8; t++)
        #pragma unroll
        for (int c = 0; c < 4; c++) oacc[t][c] = 0.0f;

    const int nchunks = qb + 1;

    for (int kc = 0; kc < nchunks; kc++) {
        const int kbase = kc * 128;
        const int s = kc & 1;
        if (kc + 1 < nchunks) {
            load_kv(kc + 1, s ^ 1);
            asm volatile("cp.async.commit_group;" ::: "memory");
            asm volatile("cp.async.wait_group 1;" ::: "memory");
        } else {
            asm volatile("cp.async.wait_group 0;" ::: "memory");
        }
        __syncthreads();

        const uint32_t slot = sb + 16384 + s * 32768;
        const uint32_t tK = slot, tV = slot + 16384;

        // ---- S = Q K^T (16 n-tiles of 8) ----
        uint32_t qf[4][4];
        {
            int qr = 16 * wid + (lid & 15);
            int qc = (lid >> 4) * 16;
            #pragma unroll
            for (int ks = 0; ks < 4; ks++) {
                uint32_t off = SWZ(qr * 128 + ks * 32 + qc);
                ldsm_x4(qf[ks], sb + sQ + off);
            }
        }
        float sacc[16][4];
        #pragma unroll
        for (int t = 0; t < 16; t++)
            #pragma unroll
            for (int c = 0; c < 4; c++) sacc[t][c] = 0.0f;

        {
            int kr = lid & 7;
            int kcb = ((lid >> 3) & 1) * 16;
            #pragma unroll
            for (int t = 0; t < 16; t++) {
                #pragma unroll
                for (int ks = 0; ks < 4; ks++) {
                    uint32_t off = SWZ((t * 8 + kr) * 128 + ks * 32 + kcb);
                    uint32_t kf[2];
                    ldsm_x2(kf, tK + off);
                    mma_f16_g(sacc[t], qf[ks], kf);
                }
            }
        }

        // ---- causal mask (last chunk only) ----
        if (kc == qb) {
            int row0 = qbase + 16 * wid + (lid >> 2);
            #pragma unroll
            for (int t = 0; t < 16; t++) {
                int col = kbase + t * 8 + 2 * (lid & 3);
                if (col > row0)     sacc[t][0] = -1e30f;
                if (col + 1 > row0) sacc[t][1] = -1e30f;
                if (col > row0 + 8)     sacc[t][2] = -1e30f;
                if (col + 1 > row0 + 8) sacc[t][3] = -1e30f;
            }
        }

        // ---- online softmax ----
        #pragma unroll
        for (int rr = 0; rr < 2; rr++) {
            float mx = -1e30f;
            #pragma unroll
            for (int t = 0; t < 16; t++)
                mx = fmaxf(mx, fmaxf(sacc[t][2 * rr], sacc[t][2 * rr + 1]));
            mx = fmaxf(mx, __shfl_xor_sync(0xffffffffu, mx, 1));
            mx = fmaxf(mx, __shfl_xor_sync(0xffffffffu, mx, 2));
            float mn = fmaxf(mrow[rr], mx);
            float sc = __expf(mrow[rr] - mn);
            mrow[rr] = mn;
            float rs = 0.0f;
            #pragma unroll
            for (int t = 0; t < 16; t++) {
                float p0 = __expf(sacc[t][2 * rr] - mn);
                float p1 = __expf(sacc[t][2 * rr + 1] - mn);
                sacc[t][2 * rr] = p0; sacc[t][2 * rr + 1] = p1;
                rs += p0 + p1;
            }
            lrow[rr] = lrow[rr] * sc + rs;
            #pragma unroll
            for (int t = 0; t < 8; t++) {
                oacc[t][2 * rr]     *= sc;
                oacc[t][2 * rr + 1] *= sc;
            }
        }

        // ---- O += P V (8 k-groups of 16) ----
        {
            int vr = (lid & 7) + ((lid >> 3) & 1) * 8;
            #pragma unroll
            for (int j = 0; j < 8; j++) {
                uint32_t pf[4];
                #pragma unroll
                for (int half = 0; half < 2; half++) {
                    float a0 = sacc[2 * j + half][0], a1 = sacc[2 * j + half][1];
                    float a2 = sacc[2 * j + half][2], a3 = sacc[2 * j + half][3];
                    pf[0 + 2 * half] = pack_f16x2(a0, a1);
                    pf[1 + 2 * half] = pack_f16x2(a2, a3);
                }
                #pragma unroll
                for (int t = 0; t < 8; t++) {
                    uint32_t voff = SWZ((j * 16 + vr) * 128 + t * 16);
                    uint32_t vf[2];
                    ldsm_x2_trans(vf, tV + voff);
                    mma_f16_g(oacc[t], pf, vf);
                }
            }
        }
        __syncthreads();
    }

    lrow[0] += __shfl_xor_sync(0xffffffffu, lrow[0], 1);
    lrow[0] += __shfl_xor_sync(0xffffffffu, lrow[0], 2);
    lrow[1] += __shfl_xor_sync(0xffffffffu, lrow[1], 1);
    lrow[1] += __shfl_xor_sync(0xffffffffu, lrow[1], 2);
    float inv0 = 0.03125f / lrow[0];
    float inv1 = 0.03125f / lrow[1];

    #pragma unroll
    for (int rr = 0; rr < 2; rr++) {
        float inv = rr ? inv1 : inv0;
        int row = qbase + 16 * wid + (lid >> 2) + rr * 8;
        size_t base = (tok0 + row) * (size_t)D + h * HD + 2 * (lid & 3);
        #pragma unroll
        for (int t = 0; t < 8; t++) {
            float v0 = oacc[t][2 * rr] * inv;
            float v1 = oacc[t][2 * rr + 1] * inv;
            *reinterpret_cast<__half2*>(&oa[base + t * 8]) = __floats2half2_rn(v0, v1);
        }
    }
}

// ---------------------------------------------------------------------------
// Launch
// ---------------------------------------------------------------------------
extern "C" void kernel_launch(void* const* d_in, const int* in_sizes, int n_in,
                              void* d_out, int out_size) {
    const float* x      = (const float*)d_in[0];
    const float* w_attn = (const float*)d_in[1];
    const float* b_attn = (const float*)d_in[2];
    const float* w_proj = (const float*)d_in[3];
    const float* b_proj = (const float*)d_in[4];
    const float* w_fc1  = (const float*)d_in[5];
    const float* b_fc1  = (const float*)d_in[6];
    const float* w_fc2  = (const float*)d_in[7];
    const float* b_fc2  = (const float*)d_in[8];
    const float* g1     = (const float*)d_in[9];
    const float* g2     = (const float*)d_in[10];
    float* out = (float*)d_out;

    __half *a, *act, *qkv, *tA, *tP, *tF1, *tF2;
    cudaGetSymbolAddress((void**)&a,   g_a);
    cudaGetSymbolAddress((void**)&act, g_act);
    cudaGetSymbolAddress((void**)&qkv, g_qkv);
    cudaGetSymbolAddress((void**)&tA,  g_wA);
    cudaGetSymbolAddress((void**)&tP,  g_wP);
    cudaGetSymbolAddress((void**)&tF1, g_wF1);
    cudaGetSymbolAddress((void**)&tF2, g_wF2);

    cudaFuncSetAttribute(attn_mma_kernel, cudaFuncAttributeMaxDynamicSharedMemorySize, ATTN_SMEM);
    cudaFuncSetAttribute(tcgemm_kernel<EPI_HBIAS>, cudaFuncAttributeMaxDynamicSharedMemorySize, TCG_SMEM);
    cudaFuncSetAttribute(tcgemm_kernel<EPI_GELU>,  cudaFuncAttributeMaxDynamicSharedMemorySize, TCG_SMEM);
    cudaFuncSetAttribute(tcgemm_kernel<EPI_RES>,   cudaFuncAttributeMaxDynamicSharedMemorySize, TCG_SMEM);

    // 1. fused prep: rmsnorm1 + 4 weight transposes (all fp16)
    prep_kernel<<<16384, 256>>>(x, g1, a, w_attn, w_proj, w_fc1, w_fc2,
                                tA, tP, tF1, tF2);
    // 2. qkv = h @ w_attn + b_attn -> contiguous fp16 [t, 3d]
    tcgemm_kernel<EPI_HBIAS><<<dim3(D3 / 128, NTOK / 128), 256, TCG_SMEM>>>(
        a, tA, b_attn, nullptr, nullptr, qkv, NTOK, D3, D);
    // 3. attention -> fp16 into a
    attn_mma_kernel<<<dim3(TSEQ / 128, NH, NBATCH), 256, ATTN_SMEM>>>(qkv, a);
    // 4. out = x + o @ w_proj + b_proj
    tcgemm_kernel<EPI_RES><<<dim3(D / 128, NTOK / 128), 256, TCG_SMEM>>>(
        a, tP, b_proj, x, out, nullptr, NTOK, D, D);
    // 5. rmsnorm2 -> fp16
    rmsnorm_h_kernel<<<NTOK, 256>>>(out, g2, a);
    // 6. act = gelu(h @ w_fc1 + b_fc1) -> fp16
    tcgemm_kernel<EPI_GELU><<<dim3(D4 / 128, NTOK / 128), 256, TCG_SMEM>>>(
        a, tF1, b_fc1, nullptr, nullptr, act, NTOK, D4, D);
    // 7. out = out + act @ w_fc2 + b_fc2
    tcgemm_kernel<EPI_RES><<<dim3(D / 128, NTOK / 128), 256, TCG_SMEM>>>(
        act, tF2, b_fc2, out, out, nullptr, NTOK, D, D4);
}

// round 15
// speedup vs baseline: 2.3910x; 1.0666x over previous
#include <cuda_runtime.h>
#include <cuda_fp16.h>
#include <math.h>
#include <cstdint>

#define D      1024
#define D3     3072
#define D4     4096
#define TSEQ   2048
#define NBATCH 2
#define NTOK   4096
#define NH     16
#define HD     64
#define EPS    1.1920929e-07f

// ---------------------------------------------------------------------------
// Scratch (device globals; no allocations allowed)
// ---------------------------------------------------------------------------
__device__ __half g_a[NTOK * D];        // activations fp16 (GEMM A side)
__device__ __half g_act[NTOK * D4];     // fc1 output fp16
__device__ __half g_qkv[NTOK * D3];     // qkv contiguous fp16 [t, 3d]
// transposed weights fp16 [N,K]
__device__ __half g_wA[D * D3];
__device__ __half g_wP[D * D];
__device__ __half g_wF1[D * D4];
__device__ __half g_wF2[D4 * D];

// ---------------------------------------------------------------------------
// Helpers
// ---------------------------------------------------------------------------
__device__ __forceinline__ uint32_t smem_to_u32(const void* p) {
    uint32_t a;
    asm("{ .reg .u64 t; cvta.to.shared.u64 t, %1; cvt.u32.u64 %0, t; }" : "=r"(a) : "l"(p));
    return a;
}

#define SWZ(off) ((uint32_t)(off) ^ ((((uint32_t)(off) >> 7) & 7) << 4))

__device__ __forceinline__ void ldsm_x4(uint32_t* r, uint32_t addr) {
    asm volatile("ldmatrix.sync.aligned.m8n8.x4.shared.b16 {%0,%1,%2,%3}, [%4];"
                 : "=r"(r[0]), "=r"(r[1]), "=r"(r[2]), "=r"(r[3]) : "r"(addr));
}
__device__ __forceinline__ void ldsm_x2(uint32_t* r, uint32_t addr) {
    asm volatile("ldmatrix.sync.aligned.m8n8.x2.shared.b16 {%0,%1}, [%2];"
                 : "=r"(r[0]), "=r"(r[1]) : "r"(addr));
}
__device__ __forceinline__ void ldsm_x2_trans(uint32_t* r, uint32_t addr) {
    asm volatile("ldmatrix.sync.aligned.m8n8.x2.trans.shared.b16 {%0,%1}, [%2];"
                 : "=r"(r[0]), "=r"(r[1]) : "r"(addr));
}
__device__ __forceinline__ void mma_f16_g(float* d, const uint32_t* a, const uint32_t* b) {
    asm volatile(
        "mma.sync.aligned.m16n8k16.row.col.f32.f16.f16.f32 "
        "{%0,%1,%2,%3}, {%4,%5,%6,%7}, {%8,%9}, {%0,%1,%2,%3};"
        : "+f"(d[0]), "+f"(d[1]), "+f"(d[2]), "+f"(d[3])
        : "r"(a[0]), "r"(a[1]), "r"(a[2]), "r"(a[3]), "r"(b[0]), "r"(b[1]));
}
__device__ __forceinline__ uint32_t pack_f16x2(float a, float b) {
    uint32_t r;
    asm("cvt.rn.f16x2.f32 %0, %1, %2;" : "=r"(r) : "f"(b), "f"(a));
    return r;
}

// ---------------------------------------------------------------------------
// Fused prep kernel: rmsnorm(x,g1) -> fp16 + 4 weight transposes -> fp16.
// ---------------------------------------------------------------------------
__device__ __forceinline__ void do_transpose(const float* __restrict__ W, int K, int N,
                                             __half* __restrict__ T,
                                             int tile, float* tbuf /* [32][33] */) {
    int tiles_n = N >> 5;
    int k0 = (tile / tiles_n) << 5;
    int n0 = (tile % tiles_n) << 5;
    int x = threadIdx.x & 31, y = threadIdx.x >> 5;
    #pragma unroll
    for (int i = y; i < 32; i += 8)
        tbuf[i * 33 + x] = W[(size_t)(k0 + i) * N + n0 + x];
    __syncthreads();
    #pragma unroll
    for (int b = y; b < 32; b += 8)
        T[(size_t)(n0 + b) * K + k0 + x] = __float2half_rn(tbuf[x * 33 + b]);
}

__global__ void prep_kernel(const float* __restrict__ x, const float* __restrict__ g1,
                            __half* __restrict__ oa,
                            const float* __restrict__ wA, const float* __restrict__ wP,
                            const float* __restrict__ wF1, const float* __restrict__ wF2,
                            __half* tA, __half* tP, __half* tF1, __half* tF2) {
    __shared__ float tbuf[32 * 33];
    int bid = blockIdx.x;
    if (bid < NTOK) {
        int row = bid;
        const float4* xr = reinterpret_cast<const float4*>(x + (size_t)row * D);
        float4 v = xr[threadIdx.x];
        float s = v.x * v.x + v.y * v.y + v.z * v.z + v.w * v.w;
        #pragma unroll
        for (int o = 16; o > 0; o >>= 1) s += __shfl_xor_sync(0xffffffffu, s, o);
        __shared__ float ws[8];
        if ((threadIdx.x & 31) == 0) ws[threadIdx.x >> 5] = s;
        __syncthreads();
        float tot = ws[0] + ws[1] + ws[2] + ws[3] + ws[4] + ws[5] + ws[6] + ws[7];
        float inv = rsqrtf(tot * (1.0f / (float)D) + EPS);
        float4 gv = reinterpret_cast<const float4*>(g1)[threadIdx.x];
        size_t off = (size_t)row * D + threadIdx.x * 4;
        *reinterpret_cast<__half2*>(&oa[off])     = __floats2half2_rn(v.x * inv * gv.x, v.y * inv * gv.y);
        *reinterpret_cast<__half2*>(&oa[off + 2]) = __floats2half2_rn(v.z * inv * gv.z, v.w * inv * gv.w);
    } else if (bid < NTOK + 3072) {
        do_transpose(wA, D, D3, tA, bid - NTOK, tbuf);
    } else if (bid < NTOK + 3072 + 1024) {
        do_transpose(wP, D, D, tP, bid - NTOK - 3072, tbuf);
    } else if (bid < NTOK + 3072 + 1024 + 4096) {
        do_transpose(wF1, D, D4, tF1, bid - NTOK - 3072 - 1024, tbuf);
    } else {
        do_transpose(wF2, D4, D, tF2, bid - NTOK - 3072 - 1024 - 4096, tbuf);
    }
}

// ---------------------------------------------------------------------------
// rmsnorm (standalone, for norm2) -> fp16
// ---------------------------------------------------------------------------
__global__ void rmsnorm_h_kernel(const float* __restrict__ x,
                                 const float* __restrict__ g,
                                 __half* __restrict__ oa) {
    int row = blockIdx.x;
    const float4* xr = reinterpret_cast<const float4*>(x + (size_t)row * D);
    float4 v = xr[threadIdx.x];
    float s = v.x * v.x + v.y * v.y + v.z * v.z + v.w * v.w;
    #pragma unroll
    for (int o = 16; o > 0; o >>= 1) s += __shfl_xor_sync(0xffffffffu, s, o);
    __shared__ float ws[8];
    if ((threadIdx.x & 31) == 0) ws[threadIdx.x >> 5] = s;
    __syncthreads();
    float tot = ws[0] + ws[1] + ws[2] + ws[3] + ws[4] + ws[5] + ws[6] + ws[7];
    float inv = rsqrtf(tot * (1.0f / (float)D) + EPS);
    float4 gv = reinterpret_cast<const float4*>(g)[threadIdx.x];
    size_t off = (size_t)row * D + threadIdx.x * 4;
    *reinterpret_cast<__half2*>(&oa[off])     = __floats2half2_rn(v.x * inv * gv.x, v.y * inv * gv.y);
    *reinterpret_cast<__half2*>(&oa[off + 2]) = __floats2half2_rn(v.z * inv * gv.z, v.w * inv * gv.w);
}

// ---------------------------------------------------------------------------
// Single-fp16 1-pass GEMM: C = A @ B^T + bias (+ epilogue)
// 128x128, BK=64, 3-stage single-barrier pipeline, 2 CTAs/SM.
// ---------------------------------------------------------------------------
#define EPI_HBIAS 0
#define EPI_GELU  1
#define EPI_RES   2

#define STAGE_BYTES 32768     // A 16K | B 16K
#define TCG_SMEM (3 * STAGE_BYTES)

template <int EPI>
__global__ __launch_bounds__(256, 2)
void tcgemm_kernel(const __half* __restrict__ A, const __half* __restrict__ B,
                   const float* __restrict__ bias, const float* __restrict__ R,
                   float* __restrict__ C, __half* __restrict__ Oa,
                   int M, int N, int K) {
    extern __shared__ __align__(1024) char smem[];
    uint32_t sbase = smem_to_u32(smem);
    const int tid = threadIdx.x;
    const int wid = tid >> 5, lid = tid & 31;
    const int wm = wid >> 2, wn = wid & 3;
    const int bm = blockIdx.y * 128, bn = blockIdx.x * 128;

    auto load_chunk = [&](int c, int s) {
        uint32_t tb = sbase + s * STAGE_BYTES;
        #pragma unroll
        for (int t2 = 0; t2 < 2; t2++) {
            const __half* src = t2 ? B : A;
            int rbase = t2 ? bn : bm;
            uint32_t dst0 = tb + t2 * 16384;
            #pragma unroll
            for (int i = 0; i < 4; i++) {
                int u = tid + i * 256;
                int r = u >> 3, j = u & 7;
                uint32_t d = dst0 + SWZ(r * 128 + j * 16);
                const void* g = src + (size_t)(rbase + r) * K + c * 64 + j * 8;
                asm volatile("cp.async.cg.shared.global [%0], [%1], 16;"
                             :: "r"(d), "l"(g) : "memory");
            }
        }
        asm volatile("cp.async.commit_group;" ::: "memory");
    };

    float acc[4][4][4];
    #pragma unroll
    for (int im = 0; im < 4; im++)
        #pragma unroll
        for (int in = 0; in < 4; in++)
            #pragma unroll
            for (int q = 0; q < 4; q++) acc[im][in][q] = 0.0f;

    const int nchunks = K >> 6;
    load_chunk(0, 0);
    load_chunk(1, 1);

    const int arow = wm * 64 + (lid & 15);
    const int acol = (lid >> 4) * 16;
    const int brow = wn * 32 + (lid & 7);
    const int bcol = ((lid >> 3) & 1) * 16;

    for (int c = 0; c < nchunks; c++) {
        if (c + 1 < nchunks) {
            asm volatile("cp.async.wait_group 1;" ::: "memory");
        } else {
            asm volatile("cp.async.wait_group 0;" ::: "memory");
        }
        __syncthreads();           // all warps done with compute c-1
        if (c + 2 < nchunks)
            load_chunk(c + 2, (c + 2) % 3);   // reuses slot (c-1)%3 — safe now

        int s = c % 3;
        uint32_t tb = sbase + s * STAGE_BYTES;
        uint32_t tA = tb, tB = tb + 16384;

        #pragma unroll
        for (int ks = 0; ks < 4; ks++) {
            uint32_t a4[4][4], b2[4][2];
            #pragma unroll
            for (int im = 0; im < 4; im++) {
                uint32_t off = SWZ((arow + im * 16) * 128 + ks * 32 + acol);
                ldsm_x4(a4[im], tA + off);
            }
            #pragma unroll
            for (int in = 0; in < 4; in++) {
                uint32_t off = SWZ((brow + in * 8) * 128 + ks * 32 + bcol);
                ldsm_x2(b2[in], tB + off);
            }
            #pragma unroll
            for (int im = 0; im < 4; im++)
                #pragma unroll
                for (int in = 0; in < 4; in++)
                    mma_f16_g(acc[im][in], a4[im], b2[in]);
        }
    }

    #pragma unroll
    for (int im = 0; im < 4; im++) {
        #pragma unroll
        for (int in = 0; in < 4; in++) {
            int m0 = bm + wm * 64 + im * 16 + (lid >> 2);
            int n0 = bn + wn * 32 + in * 8 + (lid & 3) * 2;
            float b0 = bias[n0], b1 = bias[n0 + 1];
            #pragma unroll
            for (int half = 0; half < 2; half++) {
                int m = m0 + half * 8;
                float v0 = acc[im][in][half * 2]     + b0;
                float v1 = acc[im][in][half * 2 + 1] + b1;
                size_t off = (size_t)m * N + n0;
                if (EPI == EPI_HBIAS) {
                    *reinterpret_cast<__half2*>(&Oa[off]) = __floats2half2_rn(v0, v1);
                } else if (EPI == EPI_GELU) {
                    float g0 = 0.5f * v0 * (1.0f + erff(v0 * 0.70710678118654752f));
                    float g1 = 0.5f * v1 * (1.0f + erff(v1 * 0.70710678118654752f));
                    *reinterpret_cast<__half2*>(&Oa[off]) = __floats2half2_rn(g0, g1);
                } else {
                    float2 rr = *reinterpret_cast<const float2*>(&R[off]);
                    v0 += rr.x; v1 += rr.y;
                    float2 o2 = make_float2(v0, v1);
                    *reinterpret_cast<float2*>(&C[off]) = o2;
                }
            }
        }
    }
}

// ---------------------------------------------------------------------------
// Single-fp16 flash attention, K/V chunks of 128 rows, heavy-first.
// qkv input is contiguous [t, 3d] fp16.
// smem: Q 16K | slot0 {K 16K, V 16K} | slot1 = 80KB
// ---------------------------------------------------------------------------
#define ATTN_SMEM (16384 + 2 * 32768)

__global__ __launch_bounds__(256, 1)
void attn_mma_kernel(const __half* __restrict__ qkv, __half* __restrict__ oa) {
    extern __shared__ __align__(1024) char smem_raw[];
    uint32_t sb = smem_to_u32(smem_raw);
    const uint32_t sQ = 0;

    const int tid = threadIdx.x;
    const int wid = tid >> 5, lid = tid & 31;
    const int qb = gridDim.x - 1 - blockIdx.x;   // heavy CTAs first
    const int h = blockIdx.y, b = blockIdx.z;
    const int qbase = qb * 128;
    const size_t tok0 = (size_t)b * TSEQ;

    auto load_kv = [&](int c, int s) {
        uint32_t slot = sb + 16384 + s * 32768;
        int rowbase = c * 128;
        #pragma unroll
        for (int i = 0; i < 8; i++) {
            int u = tid + i * 256;
            int t2 = u >> 10;
            int c2 = u & 1023;
            int r = c2 >> 3, j = c2 & 7;
            uint32_t d = slot + t2 * 16384 + SWZ(r * 128 + j * 16);
            const void* g = qkv + (tok0 + rowbase + r) * D3 + (t2 + 1) * D + h * HD + j * 8;
            asm volatile("cp.async.cg.shared.global [%0], [%1], 16;"
                         :: "r"(d), "l"(g) : "memory");
        }
    };

    {
        #pragma unroll
        for (int i = 0; i < 4; i++) {
            int u = tid + i * 256;
            int r = u >> 3, j = u & 7;
            uint32_t o = SWZ(r * 128 + j * 16);
            const void* g = qkv + (tok0 + qbase + r) * D3 + h * HD + j * 8;
            asm volatile("cp.async.cg.shared.global [%0], [%1], 16;"
                         :: "r"(sb + sQ + o), "l"(g) : "memory");
        }
        load_kv(0, 0);
        asm volatile("cp.async.commit_group;" ::: "memory");
    }

    float mrow[2] = {-1e30f, -1e30f};
    float lrow[2] = {0.0f, 0.0f};
    float oacc[8][4];
    #pragma unroll
    for (int t = 0; t < 8; t++)
        #pragma unroll
        for (int c = 0; c < 4; c++) oacc[t][c] = 0.0f;

    const int nchunks = qb + 1;

    for (int kc = 0; kc < nchunks; kc++) {
        const int kbase = kc * 128;
        const int s = kc & 1;
        if (kc + 1 < nchunks) {
            load_kv(kc + 1, s ^ 1);
            asm volatile("cp.async.commit_group;" ::: "memory");
            asm volatile("cp.async.wait_group 1;" ::: "memory");
        } else {
            asm volatile("cp.async.wait_group 0;" ::: "memory");
        }
        __syncthreads();

        const uint32_t slot = sb + 16384 + s * 32768;
        const uint32_t tK = slot, tV = slot + 16384;

        uint32_t qf[4][4];
        {
            int qr = 16 * wid + (lid & 15);
            int qc = (lid >> 4) * 16;
            #pragma unroll
            for (int ks = 0; ks < 4; ks++) {
                uint32_t off = SWZ(qr * 128 + ks * 32 + qc);
                ldsm_x4(qf[ks], sb + sQ + off);
            }
        }
        float sacc[16][4];
        #pragma unroll
        for (int t = 0; t < 16; t++)
            #pragma unroll
            for (int c = 0; c < 4; c++) sacc[t][c] = 0.0f;

        {
            int kr = lid & 7;
            int kcb = ((lid >> 3) & 1) * 16;
            #pragma unroll
            for (int t = 0; t < 16; t++) {
                #pragma unroll
                for (int ks = 0; ks < 4; ks++) {
                    uint32_t off = SWZ((t * 8 + kr) * 128 + ks * 32 + kcb);
                    uint32_t kf[2];
                    ldsm_x2(kf, tK + off);
                    mma_f16_g(sacc[t], qf[ks], kf);
                }
            }
        }

        if (kc == qb) {
            int row0 = qbase + 16 * wid + (lid >> 2);
            #pragma unroll
            for (int t = 0; t < 16; t++) {
                int col = kbase + t * 8 + 2 * (lid & 3);
                if (col > row0)     sacc[t][0] = -1e30f;
                if (col + 1 > row0) sacc[t][1] = -1e30f;
                if (col > row0 + 8)     sacc[t][2] = -1e30f;
                if (col + 1 > row0 + 8) sacc[t][3] = -1e30f;
            }
        }

        #pragma unroll
        for (int rr = 0; rr < 2; rr++) {
            float mx = -1e30f;
            #pragma unroll
            for (int t = 0; t < 16; t++)
                mx = fmaxf(mx, fmaxf(sacc[t][2 * rr], sacc[t][2 * rr + 1]));
            mx = fmaxf(mx, __shfl_xor_sync(0xffffffffu, mx, 1));
            mx = fmaxf(mx, __shfl_xor_sync(0xffffffffu, mx, 2));
            float mn = fmaxf(mrow[rr], mx);
            float sc = __expf(mrow[rr] - mn);
            mrow[rr] = mn;
            float rs = 0.0f;
            #pragma unroll
            for (int t = 0; t < 16; t++) {
                float p0 = __expf(sacc[t][2 * rr] - mn);
                float p1 = __expf(sacc[t][2 * rr + 1] - mn);
                sacc[t][2 * rr] = p0; sacc[t][2 * rr + 1] = p1;
                rs += p0 + p1;
            }
            lrow[rr] = lrow[rr] * sc + rs;
            #pragma unroll
            for (int t = 0; t < 8; t++) {
                oacc[t][2 * rr]     *= sc;
                oacc[t][2 * rr + 1] *= sc;
            }
        }

        {
            int vr = (lid & 7) + ((lid >> 3) & 1) * 8;
            #pragma unroll
            for (int j = 0; j < 8; j++) {
                uint32_t pf[4];
                #pragma unroll
                for (int half = 0; half < 2; half++) {
                    float a0 = sacc[2 * j + half][0], a1 = sacc[2 * j + half][1];
                    float a2 = sacc[2 * j + half][2], a3 = sacc[2 * j + half][3];
                    pf[0 + 2 * half] = pack_f16x2(a0, a1);
                    pf[1 + 2 * half] = pack_f16x2(a2, a3);
                }
                #pragma unroll
                for (int t = 0; t < 8; t++) {
                    uint32_t voff = SWZ((j * 16 + vr) * 128 + t * 16);
                    uint32_t vf[2];
                    ldsm_x2_trans(vf, tV + voff);
                    mma_f16_g(oacc[t], pf, vf);
                }
            }
        }
        __syncthreads();
    }

    lrow[0] += __shfl_xor_sync(0xffffffffu, lrow[0], 1);
    lrow[0] += __shfl_xor_sync(0xffffffffu, lrow[0], 2);
    lrow[1] += __shfl_xor_sync(0xffffffffu, lrow[1], 1);
    lrow[1] += __shfl_xor_sync(0xffffffffu, lrow[1], 2);
    float inv0 = 0.03125f / lrow[0];
    float inv1 = 0.03125f / lrow[1];

    #pragma unroll
    for (int rr = 0; rr < 2; rr++) {
        float inv = rr ? inv1 : inv0;
        int row = qbase + 16 * wid + (lid >> 2) + rr * 8;
        size_t base = (tok0 + row) * (size_t)D + h * HD + 2 * (lid & 3);
        #pragma unroll
        for (int t = 0; t < 8; t++) {
            float v0 = oacc[t][2 * rr] * inv;
            float v1 = oacc[t][2 * rr + 1] * inv;
            *reinterpret_cast<__half2*>(&oa[base + t * 8]) = __floats2half2_rn(v0, v1);
        }
    }
}

// ---------------------------------------------------------------------------
// Launch
// ---------------------------------------------------------------------------
extern "C" void kernel_launch(void* const* d_in, const int* in_sizes, int n_in,
                              void* d_out, int out_size) {
    const float* x      = (const float*)d_in[0];
    const float* w_attn = (const float*)d_in[1];
    const float* b_attn = (const float*)d_in[2];
    const float* w_proj = (const float*)d_in[3];
    const float* b_proj = (const float*)d_in[4];
    const float* w_fc1  = (const float*)d_in[5];
    const float* b_fc1  = (const float*)d_in[6];
    const float* w_fc2  = (const float*)d_in[7];
    const float* b_fc2  = (const float*)d_in[8];
    const float* g1     = (const float*)d_in[9];
    const float* g2     = (const float*)d_in[10];
    float* out = (float*)d_out;

    __half *a, *act, *qkv, *tA, *tP, *tF1, *tF2;
    cudaGetSymbolAddress((void**)&a,   g_a);
    cudaGetSymbolAddress((void**)&act, g_act);
    cudaGetSymbolAddress((void**)&qkv, g_qkv);
    cudaGetSymbolAddress((void**)&tA,  g_wA);
    cudaGetSymbolAddress((void**)&tP,  g_wP);
    cudaGetSymbolAddress((void**)&tF1, g_wF1);
    cudaGetSymbolAddress((void**)&tF2, g_wF2);

    cudaFuncSetAttribute(attn_mma_kernel, cudaFuncAttributeMaxDynamicSharedMemorySize, ATTN_SMEM);
    cudaFuncSetAttribute(tcgemm_kernel<EPI_HBIAS>, cudaFuncAttributeMaxDynamicSharedMemorySize, TCG_SMEM);
    cudaFuncSetAttribute(tcgemm_kernel<EPI_GELU>,  cudaFuncAttributeMaxDynamicSharedMemorySize, TCG_SMEM);
    cudaFuncSetAttribute(tcgemm_kernel<EPI_RES>,   cudaFuncAttributeMaxDynamicSharedMemorySize, TCG_SMEM);

    // 1. fused prep: rmsnorm1 + 4 weight transposes (all fp16)
    prep_kernel<<<16384, 256>>>(x, g1, a, w_attn, w_proj, w_fc1, w_fc2,
                                tA, tP, tF1, tF2);
    // 2. qkv = h @ w_attn + b_attn -> contiguous fp16 [t, 3d]
    tcgemm_kernel<EPI_HBIAS><<<dim3(D3 / 128, NTOK / 128), 256, TCG_SMEM>>>(
        a, tA, b_attn, nullptr, nullptr, qkv, NTOK, D3, D);
    // 3. attention -> fp16 into a
    attn_mma_kernel<<<dim3(TSEQ / 128, NH, NBATCH), 256, ATTN_SMEM>>>(qkv, a);
    // 4. out = x + o @ w_proj + b_proj
    tcgemm_kernel<EPI_RES><<<dim3(D / 128, NTOK / 128), 256, TCG_SMEM>>>(
        a, tP, b_proj, x, out, nullptr, NTOK, D, D);
    // 5. rmsnorm2 -> fp16
    rmsnorm_h_kernel<<<NTOK, 256>>>(out, g2, a);
    // 6. act = gelu(h @ w_fc1 + b_fc1) -> fp16
    tcgemm_kernel<EPI_GELU><<<dim3(D4 / 128, NTOK / 128), 256, TCG_SMEM>>>(
        a, tF1, b_fc1, nullptr, nullptr, act, NTOK, D4, D);
    // 7. out = out + act @ w_fc2 + b_fc2
    tcgemm_kernel<EPI_RES><<<dim3(D / 128, NTOK / 128), 256, TCG_SMEM>>>(
        act, tF2, b_fc2, out, out, nullptr, NTOK, D, D4);
}